// round 9
// baseline (speedup 1.0000x reference)
#include <cuda_runtime.h>
#include <cuda_bf16.h>
#include <math.h>
#include <stdint.h>

#define T_TOK 4096
#define H_DIM 1024
#define F_DIM 2816
#define N_EXP 8
#define EPS_V 1e-5f
#define MP_MAX 9216

// swizzled smem: 64B rows (32 bf16), seg' = seg ^ ((row>>1)&3)
#define TILE_B 8192                  // 128 rows * 64B
#define STG   (4 * TILE_B)           // Ah, Al, Bh, Bl per stage = 32768
#define SMEM_TOT (3 * STG)           // 98304 -> 2 CTAs/SM

// ---------------- PTX helpers (sm_80-family, valid on plain sm_103) ---------
__device__ __forceinline__ uint32_t s2u(const void* p) {
    uint32_t a;
    asm("{ .reg .u64 t; cvta.to.shared.u64 t, %1; cvt.u32.u64 %0, t; }" : "=r"(a) : "l"(p));
    return a;
}
__device__ __forceinline__ void ldsm4(uint32_t* r, uint32_t a) {
    asm volatile("ldmatrix.sync.aligned.m8n8.x4.shared.b16 {%0,%1,%2,%3}, [%4];"
        : "=r"(r[0]), "=r"(r[1]), "=r"(r[2]), "=r"(r[3]) : "r"(a));
}
__device__ __forceinline__ void mma16816(float* d, const uint32_t* a, uint32_t b0, uint32_t b1) {
    asm volatile("mma.sync.aligned.m16n8k16.row.col.f32.bf16.bf16.f32 "
        "{%0,%1,%2,%3}, {%4,%5,%6,%7}, {%8,%9}, {%0,%1,%2,%3};"
        : "+f"(d[0]), "+f"(d[1]), "+f"(d[2]), "+f"(d[3])
        : "r"(a[0]), "r"(a[1]), "r"(a[2]), "r"(a[3]), "r"(b0), "r"(b1));
}
__device__ __forceinline__ void cp16(uint32_t s, const void* g) {
    asm volatile("{ .reg .u64 gg; cvta.to.global.u64 gg, %1; "
                 "cp.async.cg.shared.global [%0], [gg], 16; }"
                 :: "r"(s), "l"(g) : "memory");
}
#define CP_COMMIT() asm volatile("cp.async.commit_group;" ::: "memory")
#define CP_WAIT1()  asm volatile("cp.async.wait_group 1;" ::: "memory")

// ---------------- scratch (device globals) ----------------
__device__ __nv_bfloat16 g_x_hi[T_TOK * H_DIM];
__device__ __nv_bfloat16 g_x_lo[T_TOK * H_DIM];
__device__ __nv_bfloat16 g_h_hi[(size_t)MP_MAX * F_DIM];
__device__ __nv_bfloat16 g_h_lo[(size_t)MP_MAX * F_DIM];
__device__ __nv_bfloat16 g_wg_hi[(size_t)N_EXP * F_DIM * H_DIM];
__device__ __nv_bfloat16 g_wg_lo[(size_t)N_EXP * F_DIM * H_DIM];
__device__ __nv_bfloat16 g_wu_hi[(size_t)N_EXP * F_DIM * H_DIM];
__device__ __nv_bfloat16 g_wu_lo[(size_t)N_EXP * F_DIM * H_DIM];
__device__ __nv_bfloat16 g_wd_hi[(size_t)N_EXP * H_DIM * F_DIM];
__device__ __nv_bfloat16 g_wd_lo[(size_t)N_EXP * H_DIM * F_DIM];
__device__ int   g_tok[MP_MAX];
__device__ float g_scale[MP_MAX];
__device__ int   g_te[T_TOK * 2];
__device__ float g_tp[T_TOK * 2];
__device__ int   g_cnt[N_EXP];
__device__ int   g_offp[N_EXP + 1];

// ---------------- kernel 1: rmsnorm + router + bf16 split ----------------
__global__ __launch_bounds__(256)
void k_rms_router(const float* __restrict__ hs,
                  const float* __restrict__ lnw,
                  const float* __restrict__ rw)
{
    int t = blockIdx.x;
    int tid = threadIdx.x;
    int lane = tid & 31, wid = tid >> 5;

    __shared__ float s_x[H_DIM];
    __shared__ float swr[8];
    __shared__ float s_inv;
    __shared__ float sl[8][N_EXP];

    const float4 v = ((const float4*)(hs + (size_t)t * H_DIM))[tid];
    float ss = v.x*v.x + v.y*v.y + v.z*v.z + v.w*v.w;
    #pragma unroll
    for (int o = 16; o; o >>= 1) ss += __shfl_xor_sync(0xffffffffu, ss, o);
    if (lane == 0) swr[wid] = ss;
    __syncthreads();
    if (tid == 0) {
        float s = 0.f;
        #pragma unroll
        for (int i = 0; i < 8; i++) s += swr[i];
        s_inv = rsqrtf(s / (float)H_DIM + EPS_V);
    }
    __syncthreads();
    float inv = s_inv;

    const float4 w = ((const float4*)lnw)[tid];
    float xv[4];
    xv[0] = v.x * inv * w.x;  xv[1] = v.y * inv * w.y;
    xv[2] = v.z * inv * w.z;  xv[3] = v.w * inv * w.w;

    __nv_bfloat16 hi[4], lo[4];
    #pragma unroll
    for (int j = 0; j < 4; j++) {
        s_x[tid * 4 + j] = xv[j];
        hi[j] = __float2bfloat16(xv[j]);
        lo[j] = __float2bfloat16(xv[j] - __bfloat162float(hi[j]));
    }
    ((uint2*)(g_x_hi + (size_t)t * H_DIM))[tid] = *(uint2*)hi;
    ((uint2*)(g_x_lo + (size_t)t * H_DIM))[tid] = *(uint2*)lo;
    __syncthreads();

    {
        const int c = lane & 3, r = lane >> 2;
        const float2* rw2 = (const float2*)rw;
        float2 p = make_float2(0.f, 0.f);
        int ibase = wid * 128 + r;
        #pragma unroll
        for (int k = 0; k < 16; k++) {
            int i = ibase + k * 8;
            float2 w2 = rw2[i * 4 + c];
            float xs = s_x[i];
            p.x += xs * w2.x;
            p.y += xs * w2.y;
        }
        #pragma unroll
        for (int o = 16; o >= 4; o >>= 1) {
            p.x += __shfl_xor_sync(0xffffffffu, p.x, o);
            p.y += __shfl_xor_sync(0xffffffffu, p.y, o);
        }
        if (lane < 4) {
            sl[wid][2 * c]     = p.x;
            sl[wid][2 * c + 1] = p.y;
        }
    }
    __syncthreads();

    if (tid == 0) {
        float l[N_EXP];
        #pragma unroll
        for (int e = 0; e < N_EXP; e++) {
            float s = 0.f;
            #pragma unroll
            for (int w2 = 0; w2 < 8; w2++) s += sl[w2][e];
            l[e] = s;
        }
        float m = l[0];
        #pragma unroll
        for (int e = 1; e < N_EXP; e++) m = fmaxf(m, l[e]);
        float den = 0.f, pr[N_EXP];
        #pragma unroll
        for (int e = 0; e < N_EXP; e++) { pr[e] = expf(l[e] - m); den += pr[e]; }
        float rden = 1.f / den;
        #pragma unroll
        for (int e = 0; e < N_EXP; e++) pr[e] *= rden;

        int i1 = 0;
        #pragma unroll
        for (int e = 1; e < N_EXP; e++) if (pr[e] > pr[i1]) i1 = e;
        int i2 = (i1 == 0) ? 1 : 0;
        #pragma unroll
        for (int e = 0; e < N_EXP; e++) if (e != i1 && pr[e] > pr[i2]) i2 = e;

        g_te[t * 2 + 0] = i1;  g_tp[t * 2 + 0] = pr[i1];
        g_te[t * 2 + 1] = i2;  g_tp[t * 2 + 1] = pr[i2];
        atomicAdd(&g_cnt[i1], 1);
        atomicAdd(&g_cnt[i2], 1);
    }
}

// ---------------- kernel 2: ALL weight transposes + bf16 splits --------------
__global__ __launch_bounds__(256)
void k_tsplit_all(const float* __restrict__ wg,
                  const float* __restrict__ wu,
                  const float* __restrict__ wd)
{
    int z = blockIdx.z;
    const float* src;
    __nv_bfloat16 *dhi, *dlo;
    int R, C, e;
    if (z < 8)       { src = wg; dhi = g_wg_hi; dlo = g_wg_lo; R = H_DIM; C = F_DIM; e = z; }
    else if (z < 16) { src = wu; dhi = g_wu_hi; dlo = g_wu_lo; R = H_DIM; C = F_DIM; e = z - 8; }
    else             { src = wd; dhi = g_wd_hi; dlo = g_wd_lo; R = F_DIM; C = H_DIM; e = z - 16; }

    int c0 = blockIdx.x * 32, r0 = blockIdx.y * 64;
    if (c0 >= C || r0 >= R) return;

    __shared__ float t[64][33];
    const float* s = src + (size_t)e * R * C;
    size_t dbase = (size_t)e * R * C;
    int tx = threadIdx.x, ty = threadIdx.y;
    #pragma unroll
    for (int i = 0; i < 8; i++) {
        int r = ty + i * 8;
        t[r][tx] = s[(size_t)(r0 + r) * C + c0 + tx];
    }
    __syncthreads();
    #pragma unroll
    for (int i = 0; i < 4; i++) {
        int c = ty + i * 8;
        float v0 = t[2 * tx][c];
        float v1 = t[2 * tx + 1][c];
        __nv_bfloat16 h0 = __float2bfloat16(v0);
        __nv_bfloat16 h1 = __float2bfloat16(v1);
        __nv_bfloat16 l0 = __float2bfloat16(v0 - __bfloat162float(h0));
        __nv_bfloat16 l1 = __float2bfloat16(v1 - __bfloat162float(h1));
        uint32_t uh = (uint32_t)__bfloat16_as_ushort(h0) | ((uint32_t)__bfloat16_as_ushort(h1) << 16);
        uint32_t ul = (uint32_t)__bfloat16_as_ushort(l0) | ((uint32_t)__bfloat16_as_ushort(l1) << 16);
        size_t o = dbase + (size_t)(c0 + c) * R + r0 + 2 * tx;
        *(uint32_t*)(dhi + o) = uh;
        *(uint32_t*)(dlo + o) = ul;
    }
}

// ---------------- kernel 3: offsets + scatter (single block) -----------------
__global__ __launch_bounds__(256)
void k_offscatter()
{
    __shared__ int s_fill[N_EXP];
    int tid = threadIdx.x;
    if (tid == 0) {
        int acc = 0;
        #pragma unroll
        for (int e = 0; e < N_EXP; e++) {
            g_offp[e]  = acc;
            s_fill[e]  = acc;
            acc += (g_cnt[e] + 127) & ~127;
        }
        g_offp[N_EXP] = acc;
    }
    __syncthreads();
    for (int t = tid; t < T_TOK; t += 256) {
        #pragma unroll
        for (int k = 0; k < 2; k++) {
            int e = g_te[t * 2 + k];
            int r = atomicAdd(&s_fill[e], 1);
            g_tok[r]   = t;
            g_scale[r] = g_tp[t * 2 + k];
        }
    }
}

// ======================= GEMM1: gate/up + SiLU (mma.sync) ====================
// Swizzled smem, 3-stage pipeline, rotated stage pointers, hoisted addresses.
__global__ __launch_bounds__(256, 2)
void k_gemm1_mma()
{
    extern __shared__ char smem[];
    const uint32_t sb = s2u(smem);
    const int tid = threadIdx.x, lane = tid & 31, wid = tid >> 5;

    const int Mp = g_offp[N_EXP];
    const int m0 = blockIdx.y * 128;
    if (m0 >= Mp) return;
    const int n0 = blockIdx.x * 64;
    int e = 0;
    #pragma unroll
    for (int i = 1; i < N_EXP; i++) if (m0 >= g_offp[i]) e = i;

    __shared__ int s_tok[128];
    if (tid < 128) {
        int tok = g_tok[m0 + tid];
        s_tok[tid] = (tok >= 0) ? tok : 0;
    }
    __syncthreads();

    // ---- hoisted loader addressing (rows lr and lr+64; identical swizzle) ----
    const int lr = tid >> 2;
    const int ls = tid & 3;
    const uint32_t so0 = (uint32_t)(lr * 64 + ((ls ^ ((lr >> 1) & 3)) << 4));
    const uint32_t so1 = (uint32_t)((lr + 64) * 64 + ((ls ^ (((lr + 64) >> 1) & 3)) << 4));
    const __nv_bfloat16* pAh0 = g_x_hi + (size_t)s_tok[lr] * H_DIM + ls * 8;
    const __nv_bfloat16* pAh1 = g_x_hi + (size_t)s_tok[lr + 64] * H_DIM + ls * 8;
    const __nv_bfloat16* pAl0 = g_x_lo + (size_t)s_tok[lr] * H_DIM + ls * 8;
    const __nv_bfloat16* pAl1 = g_x_lo + (size_t)s_tok[lr + 64] * H_DIM + ls * 8;
    const int col0 = n0 + (lr >> 1);
    const int col1 = n0 + ((lr + 64) >> 1);
    const __nv_bfloat16* Wh0 = ((lr & 1) ? g_wu_hi : g_wg_hi) + ((size_t)e * F_DIM + col0) * H_DIM + ls * 8;
    const __nv_bfloat16* Wl0 = ((lr & 1) ? g_wu_lo : g_wg_lo) + ((size_t)e * F_DIM + col0) * H_DIM + ls * 8;
    const __nv_bfloat16* Wh1 = (((lr + 64) & 1) ? g_wu_hi : g_wg_hi) + ((size_t)e * F_DIM + col1) * H_DIM + ls * 8;
    const __nv_bfloat16* Wl1 = (((lr + 64) & 1) ? g_wu_lo : g_wg_lo) + ((size_t)e * F_DIM + col1) * H_DIM + ls * 8;

    const int NC = H_DIM / 32;

    auto load_chunk = [&](int kc, uint32_t base) {
        cp16(base + so0, pAh0 + kc);
        cp16(base + so1, pAh1 + kc);
        cp16(base + TILE_B + so0, pAl0 + kc);
        cp16(base + TILE_B + so1, pAl1 + kc);
        cp16(base + 2 * TILE_B + so0, Wh0 + kc);
        cp16(base + 2 * TILE_B + so1, Wh1 + kc);
        cp16(base + 3 * TILE_B + so0, Wl0 + kc);
        cp16(base + 3 * TILE_B + so1, Wl1 + kc);
    };

    load_chunk(0, sb);          CP_COMMIT();
    load_chunk(32, sb + STG);   CP_COMMIT();

    const int warp_m = (wid & 1) * 64;
    const int warp_n = (wid >> 1) * 32;

    float acc[4][4][4];
    #pragma unroll
    for (int i = 0; i < 4; i++)
        #pragma unroll
        for (int j = 0; j < 4; j++)
            #pragma unroll
            for (int k = 0; k < 4; k++) acc[i][j][k] = 0.f;

    const int quad = lane >> 3, l7 = lane & 7;
    const int a_row = warp_m + (quad & 1) * 8 + l7;
    const int b_row = warp_n + (quad & 1) * 8 + l7;
    const int kq = quad >> 1;
    const uint32_t a_seg0 = (uint32_t)(((kq) ^ ((a_row >> 1) & 3)) << 4);
    const uint32_t a_seg1 = (uint32_t)(((2 + kq) ^ ((a_row >> 1) & 3)) << 4);
    const uint32_t b_seg0 = (uint32_t)(((kq) ^ ((b_row >> 1) & 3)) << 4);
    const uint32_t b_seg1 = (uint32_t)(((2 + kq) ^ ((b_row >> 1) & 3)) << 4);
    const uint32_t a_ro = (uint32_t)(a_row * 64);
    const uint32_t b_ro = (uint32_t)(b_row * 64);

    uint32_t base_c = sb;                 // stage of chunk c
    uint32_t base_l = sb + 2 * STG;       // stage for chunk c+2
    const uint32_t wrap = sb + 3 * STG;

    for (int c = 0; c < NC; c++) {
        CP_WAIT1();
        __syncthreads();
        if (c + 2 < NC) load_chunk((c + 2) * 32, base_l);
        CP_COMMIT();
        base_l += STG; if (base_l == wrap) base_l = sb;

        const uint32_t ah = base_c, al = base_c + TILE_B;
        const uint32_t bh = base_c + 2 * TILE_B, bl = base_c + 3 * TILE_B;
        #pragma unroll
        for (int ks = 0; ks < 2; ks++) {
            const uint32_t a_seg = ks ? a_seg1 : a_seg0;
            const uint32_t b_seg = ks ? b_seg1 : b_seg0;
            uint32_t aH[4][4], aL[4][4], bH[2][4], bL[2][4];
            #pragma unroll
            for (int bj = 0; bj < 2; bj++) {
                uint32_t ro = b_ro + bj * (16 * 64) + b_seg;
                ldsm4(bH[bj], bh + ro);
                ldsm4(bL[bj], bl + ro);
            }
            #pragma unroll
            for (int mi = 0; mi < 4; mi++) {
                uint32_t ro = a_ro + mi * (16 * 64) + a_seg;
                ldsm4(aH[mi], ah + ro);
                ldsm4(aL[mi], al + ro);
            }
            #pragma unroll
            for (int mi = 0; mi < 4; mi++)
                #pragma unroll
                for (int nj = 0; nj < 4; nj++) {
                    const uint32_t* fh = bH[nj >> 1];
                    const uint32_t* fl = bL[nj >> 1];
                    int s = nj & 1;
                    mma16816(acc[mi][nj], aH[mi], fh[s], fh[s + 2]);
                    mma16816(acc[mi][nj], aH[mi], fl[s], fl[s + 2]);
                    mma16816(acc[mi][nj], aL[mi], fh[s], fh[s + 2]);
                }
        }
        base_c += STG; if (base_c == wrap) base_c = sb;
    }

    // epilogue: h = silu(g)*u via fast intrinsics; split bf16
    const int rbase = m0 + warp_m + (lane >> 2);
    const int cbase = n0 + (warp_n >> 1) + (lane & 3);
    #pragma unroll
    for (int mi = 0; mi < 4; mi++) {
        size_t r0 = (size_t)(rbase + mi * 16) * F_DIM;
        size_t r1 = r0 + 8 * F_DIM;
        #pragma unroll
        for (int nj = 0; nj < 4; nj++) {
            int L = cbase + nj * 4;
            float g0 = acc[mi][nj][0], u0 = acc[mi][nj][1];
            float g1 = acc[mi][nj][2], u1 = acc[mi][nj][3];
            float h0 = __fdividef(g0, 1.f + __expf(-g0)) * u0;
            float h1 = __fdividef(g1, 1.f + __expf(-g1)) * u1;
            __nv_bfloat16 h0h = __float2bfloat16(h0);
            __nv_bfloat16 h1h = __float2bfloat16(h1);
            g_h_hi[r0 + L] = h0h;
            g_h_hi[r1 + L] = h1h;
            g_h_lo[r0 + L] = __float2bfloat16(h0 - __bfloat162float(h0h));
            g_h_lo[r1 + L] = __float2bfloat16(h1 - __bfloat162float(h1h));
        }
    }
}

// ======================= GEMM2: down proj + combine (mma.sync) ===============
__global__ __launch_bounds__(256, 2)
void k_gemm2_mma(float* __restrict__ out)
{
    extern __shared__ char smem[];
    const uint32_t sb = s2u(smem);
    const int tid = threadIdx.x, lane = tid & 31, wid = tid >> 5;

    const int Mp = g_offp[N_EXP];
    const int m0 = blockIdx.y * 128;
    if (m0 >= Mp) return;
    const int n0 = blockIdx.x * 128;
    int e = 0;
    #pragma unroll
    for (int i = 1; i < N_EXP; i++) if (m0 >= g_offp[i]) e = i;

    const int lr = tid >> 2;
    const int ls = tid & 3;
    const uint32_t so0 = (uint32_t)(lr * 64 + ((ls ^ ((lr >> 1) & 3)) << 4));
    const uint32_t so1 = (uint32_t)((lr + 64) * 64 + ((ls ^ (((lr + 64) >> 1) & 3)) << 4));
    const __nv_bfloat16* pAh0 = g_h_hi + (size_t)(m0 + lr) * F_DIM + ls * 8;
    const __nv_bfloat16* pAh1 = g_h_hi + (size_t)(m0 + lr + 64) * F_DIM + ls * 8;
    const __nv_bfloat16* pAl0 = g_h_lo + (size_t)(m0 + lr) * F_DIM + ls * 8;
    const __nv_bfloat16* pAl1 = g_h_lo + (size_t)(m0 + lr + 64) * F_DIM + ls * 8;
    const __nv_bfloat16* pBh0 = g_wd_hi + ((size_t)e * H_DIM + n0 + lr) * F_DIM + ls * 8;
    const __nv_bfloat16* pBh1 = g_wd_hi + ((size_t)e * H_DIM + n0 + lr + 64) * F_DIM + ls * 8;
    const __nv_bfloat16* pBl0 = g_wd_lo + ((size_t)e * H_DIM + n0 + lr) * F_DIM + ls * 8;
    const __nv_bfloat16* pBl1 = g_wd_lo + ((size_t)e * H_DIM + n0 + lr + 64) * F_DIM + ls * 8;

    const int NC = F_DIM / 32;

    auto load_chunk = [&](int kc, uint32_t base) {
        cp16(base + so0, pAh0 + kc);
        cp16(base + so1, pAh1 + kc);
        cp16(base + TILE_B + so0, pAl0 + kc);
        cp16(base + TILE_B + so1, pAl1 + kc);
        cp16(base + 2 * TILE_B + so0, pBh0 + kc);
        cp16(base + 2 * TILE_B + so1, pBh1 + kc);
        cp16(base + 3 * TILE_B + so0, pBl0 + kc);
        cp16(base + 3 * TILE_B + so1, pBl1 + kc);
    };

    load_chunk(0, sb);          CP_COMMIT();
    load_chunk(32, sb + STG);   CP_COMMIT();

    const int warp_m = (wid & 1) * 64;
    const int warp_n = (wid >> 1) * 32;

    float acc[4][4][4];
    #pragma unroll
    for (int i = 0; i < 4; i++)
        #pragma unroll
        for (int j = 0; j < 4; j++)
            #pragma unroll
            for (int k = 0; k < 4; k++) acc[i][j][k] = 0.f;

    const int quad = lane >> 3, l7 = lane & 7;
    const int a_row = warp_m + (quad & 1) * 8 + l7;
    const int b_row = warp_n + (quad & 1) * 8 + l7;
    const int kq = quad >> 1;
    const uint32_t a_seg0 = (uint32_t)(((kq) ^ ((a_row >> 1) & 3)) << 4);
    const uint32_t a_seg1 = (uint32_t)(((2 + kq) ^ ((a_row >> 1) & 3)) << 4);
    const uint32_t b_seg0 = (uint32_t)(((kq) ^ ((b_row >> 1) & 3)) << 4);
    const uint32_t b_seg1 = (uint32_t)(((2 + kq) ^ ((b_row >> 1) & 3)) << 4);
    const uint32_t a_ro = (uint32_t)(a_row * 64);
    const uint32_t b_ro = (uint32_t)(b_row * 64);

    uint32_t base_c = sb;
    uint32_t base_l = sb + 2 * STG;
    const uint32_t wrap = sb + 3 * STG;

    for (int c = 0; c < NC; c++) {
        CP_WAIT1();
        __syncthreads();
        if (c + 2 < NC) load_chunk((c + 2) * 32, base_l);
        CP_COMMIT();
        base_l += STG; if (base_l == wrap) base_l = sb;

        const uint32_t ah = base_c, al = base_c + TILE_B;
        const uint32_t bh = base_c + 2 * TILE_B, bl = base_c + 3 * TILE_B;
        #pragma unroll
        for (int ks = 0; ks < 2; ks++) {
            const uint32_t a_seg = ks ? a_seg1 : a_seg0;
            const uint32_t b_seg = ks ? b_seg1 : b_seg0;
            uint32_t aH[4][4], aL[4][4], bH[2][4], bL[2][4];
            #pragma unroll
            for (int bj = 0; bj < 2; bj++) {
                uint32_t ro = b_ro + bj * (16 * 64) + b_seg;
                ldsm4(bH[bj], bh + ro);
                ldsm4(bL[bj], bl + ro);
            }
            #pragma unroll
            for (int mi = 0; mi < 4; mi++) {
                uint32_t ro = a_ro + mi * (16 * 64) + a_seg;
                ldsm4(aH[mi], ah + ro);
                ldsm4(aL[mi], al + ro);
            }
            #pragma unroll
            for (int mi = 0; mi < 4; mi++)
                #pragma unroll
                for (int nj = 0; nj < 4; nj++) {
                    const uint32_t* fh = bH[nj >> 1];
                    const uint32_t* fl = bL[nj >> 1];
                    int s = nj & 1;
                    mma16816(acc[mi][nj], aH[mi], fh[s], fh[s + 2]);
                    mma16816(acc[mi][nj], aH[mi], fl[s], fl[s + 2]);
                    mma16816(acc[mi][nj], aL[mi], fh[s], fh[s + 2]);
                }
        }
        base_c += STG; if (base_c == wrap) base_c = sb;
    }

    const int rbase = m0 + warp_m + (lane >> 2);
    const int cbase = n0 + warp_n + (lane & 3) * 2;
    #pragma unroll
    for (int mi = 0; mi < 4; mi++) {
        int r0 = rbase + mi * 16;
        int r1 = r0 + 8;
        int tok0 = g_tok[r0], tok1 = g_tok[r1];
        float sc0 = (tok0 >= 0) ? g_scale[r0] : 0.f;
        float sc1 = (tok1 >= 0) ? g_scale[r1] : 0.f;
        #pragma unroll
        for (int nj = 0; nj < 4; nj++) {
            int col = cbase + nj * 8;
            if (tok0 >= 0) {
                float* p0 = out + (size_t)tok0 * H_DIM + col;
                atomicAdd(p0,     acc[mi][nj][0] * sc0);
                atomicAdd(p0 + 1, acc[mi][nj][1] * sc0);
            }
            if (tok1 >= 0) {
                float* p1 = out + (size_t)tok1 * H_DIM + col;
                atomicAdd(p1,     acc[mi][nj][2] * sc1);
                atomicAdd(p1 + 1, acc[mi][nj][3] * sc1);
            }
        }
    }
}

// ---------------- launch ----------------
extern "C" void kernel_launch(void* const* d_in, const int* in_sizes, int n_in,
                              void* d_out, int out_size)
{
    const float* hs  = (const float*)d_in[0];
    const float* lnw = (const float*)d_in[1];
    const float* rw  = (const float*)d_in[2];
    const float* wg  = (const float*)d_in[3];
    const float* wu  = (const float*)d_in[4];
    const float* wd  = (const float*)d_in[5];
    float* out = (float*)d_out;

    cudaFuncSetAttribute(k_gemm1_mma, cudaFuncAttributeMaxDynamicSharedMemorySize, SMEM_TOT);
    cudaFuncSetAttribute(k_gemm2_mma, cudaFuncAttributeMaxDynamicSharedMemorySize, SMEM_TOT);

    void *p_cnt = nullptr, *p_tok = nullptr;
    cudaGetSymbolAddress(&p_cnt, g_cnt);
    cudaGetSymbolAddress(&p_tok, g_tok);

    cudaMemsetAsync(p_cnt, 0, N_EXP * sizeof(int));
    cudaMemsetAsync(p_tok, 0xFF, MP_MAX * sizeof(int));
    cudaMemsetAsync(out, 0, (size_t)out_size * sizeof(float));

    k_rms_router<<<T_TOK, 256>>>(hs, lnw, rw);

    dim3 tb(32, 8);
    dim3 tg(F_DIM / 32, F_DIM / 64, 24);
    k_tsplit_all<<<tg, tb>>>(wg, wu, wd);

    k_offscatter<<<1, 256>>>();

    // launch 4 (ncu capture slot): GEMM1
    dim3 g1(F_DIM / 64, MP_MAX / 128);   // (44, 72)
    k_gemm1_mma<<<g1, 256, SMEM_TOT>>>();

    dim3 g2(H_DIM / 128, MP_MAX / 128);  // (8, 72)
    k_gemm2_mma<<<g2, 256, SMEM_TOT>>>(out);
}

// round 10
// speedup vs baseline: 1.0200x; 1.0200x over previous
#include <cuda_runtime.h>
#include <cuda_bf16.h>
#include <math.h>
#include <stdint.h>

#define T_TOK 4096
#define H_DIM 1024
#define F_DIM 2816
#define N_EXP 8
#define EPS_V 1e-5f
#define MP_MAX 9216

// swizzled smem: 64B rows (32 bf16), seg' = seg ^ ((row>>1)&3)
#define TILE_B 8192                  // 128 rows * 64B
#define STG   (4 * TILE_B)           // Ah, Al, Bh, Bl per stage = 32768
#define SMEM_TOT (3 * STG)           // 98304 -> 2 CTAs/SM

// ---------------- PTX helpers (sm_80-family, valid on plain sm_103) ---------
__device__ __forceinline__ uint32_t s2u(const void* p) {
    uint32_t a;
    asm("{ .reg .u64 t; cvta.to.shared.u64 t, %1; cvt.u32.u64 %0, t; }" : "=r"(a) : "l"(p));
    return a;
}
__device__ __forceinline__ void ldsm4(uint32_t* r, uint32_t a) {
    asm volatile("ldmatrix.sync.aligned.m8n8.x4.shared.b16 {%0,%1,%2,%3}, [%4];"
        : "=r"(r[0]), "=r"(r[1]), "=r"(r[2]), "=r"(r[3]) : "r"(a));
}
__device__ __forceinline__ void mma16816(float* d, const uint32_t* a, uint32_t b0, uint32_t b1) {
    asm volatile("mma.sync.aligned.m16n8k16.row.col.f32.bf16.bf16.f32 "
        "{%0,%1,%2,%3}, {%4,%5,%6,%7}, {%8,%9}, {%0,%1,%2,%3};"
        : "+f"(d[0]), "+f"(d[1]), "+f"(d[2]), "+f"(d[3])
        : "r"(a[0]), "r"(a[1]), "r"(a[2]), "r"(a[3]), "r"(b0), "r"(b1));
}
__device__ __forceinline__ void cp16(uint32_t s, const void* g) {
    asm volatile("{ .reg .u64 gg; cvta.to.global.u64 gg, %1; "
                 "cp.async.cg.shared.global [%0], [gg], 16; }"
                 :: "r"(s), "l"(g) : "memory");
}
#define CP_COMMIT() asm volatile("cp.async.commit_group;" ::: "memory")
#define CP_WAIT1()  asm volatile("cp.async.wait_group 1;" ::: "memory")
#define CP_WAIT0()  asm volatile("cp.async.wait_group 0;" ::: "memory")

// ---------------- scratch (device globals) ----------------
__device__ __nv_bfloat16 g_x_hi[T_TOK * H_DIM];
__device__ __nv_bfloat16 g_x_lo[T_TOK * H_DIM];
__device__ __nv_bfloat16 g_h_hi[(size_t)MP_MAX * F_DIM];
__device__ __nv_bfloat16 g_h_lo[(size_t)MP_MAX * F_DIM];
__device__ __nv_bfloat16 g_wg_hi[(size_t)N_EXP * F_DIM * H_DIM];
__device__ __nv_bfloat16 g_wg_lo[(size_t)N_EXP * F_DIM * H_DIM];
__device__ __nv_bfloat16 g_wu_hi[(size_t)N_EXP * F_DIM * H_DIM];
__device__ __nv_bfloat16 g_wu_lo[(size_t)N_EXP * F_DIM * H_DIM];
__device__ __nv_bfloat16 g_wd_hi[(size_t)N_EXP * H_DIM * F_DIM];
__device__ __nv_bfloat16 g_wd_lo[(size_t)N_EXP * H_DIM * F_DIM];
__device__ int   g_tok[MP_MAX];
__device__ float g_scale[MP_MAX];
__device__ int   g_te[T_TOK * 2];
__device__ float g_tp[T_TOK * 2];
__device__ int   g_cnt[N_EXP];
__device__ int   g_offp[N_EXP + 1];

// ---------------- kernel 1: rmsnorm + router + bf16 split ----------------
__global__ __launch_bounds__(256)
void k_rms_router(const float* __restrict__ hs,
                  const float* __restrict__ lnw,
                  const float* __restrict__ rw)
{
    int t = blockIdx.x;
    int tid = threadIdx.x;
    int lane = tid & 31, wid = tid >> 5;

    __shared__ float s_x[H_DIM];
    __shared__ float swr[8];
    __shared__ float s_inv;
    __shared__ float sl[8][N_EXP];

    const float4 v = ((const float4*)(hs + (size_t)t * H_DIM))[tid];
    float ss = v.x*v.x + v.y*v.y + v.z*v.z + v.w*v.w;
    #pragma unroll
    for (int o = 16; o; o >>= 1) ss += __shfl_xor_sync(0xffffffffu, ss, o);
    if (lane == 0) swr[wid] = ss;
    __syncthreads();
    if (tid == 0) {
        float s = 0.f;
        #pragma unroll
        for (int i = 0; i < 8; i++) s += swr[i];
        s_inv = rsqrtf(s / (float)H_DIM + EPS_V);
    }
    __syncthreads();
    float inv = s_inv;

    const float4 w = ((const float4*)lnw)[tid];
    float xv[4];
    xv[0] = v.x * inv * w.x;  xv[1] = v.y * inv * w.y;
    xv[2] = v.z * inv * w.z;  xv[3] = v.w * inv * w.w;

    __nv_bfloat16 hi[4], lo[4];
    #pragma unroll
    for (int j = 0; j < 4; j++) {
        s_x[tid * 4 + j] = xv[j];
        hi[j] = __float2bfloat16(xv[j]);
        lo[j] = __float2bfloat16(xv[j] - __bfloat162float(hi[j]));
    }
    ((uint2*)(g_x_hi + (size_t)t * H_DIM))[tid] = *(uint2*)hi;
    ((uint2*)(g_x_lo + (size_t)t * H_DIM))[tid] = *(uint2*)lo;
    __syncthreads();

    {
        const int c = lane & 3, r = lane >> 2;
        const float2* rw2 = (const float2*)rw;
        float2 p = make_float2(0.f, 0.f);
        int ibase = wid * 128 + r;
        #pragma unroll
        for (int k = 0; k < 16; k++) {
            int i = ibase + k * 8;
            float2 w2 = rw2[i * 4 + c];
            float xs = s_x[i];
            p.x += xs * w2.x;
            p.y += xs * w2.y;
        }
        #pragma unroll
        for (int o = 16; o >= 4; o >>= 1) {
            p.x += __shfl_xor_sync(0xffffffffu, p.x, o);
            p.y += __shfl_xor_sync(0xffffffffu, p.y, o);
        }
        if (lane < 4) {
            sl[wid][2 * c]     = p.x;
            sl[wid][2 * c + 1] = p.y;
        }
    }
    __syncthreads();

    if (tid == 0) {
        float l[N_EXP];
        #pragma unroll
        for (int e = 0; e < N_EXP; e++) {
            float s = 0.f;
            #pragma unroll
            for (int w2 = 0; w2 < 8; w2++) s += sl[w2][e];
            l[e] = s;
        }
        float m = l[0];
        #pragma unroll
        for (int e = 1; e < N_EXP; e++) m = fmaxf(m, l[e]);
        float den = 0.f, pr[N_EXP];
        #pragma unroll
        for (int e = 0; e < N_EXP; e++) { pr[e] = expf(l[e] - m); den += pr[e]; }
        float rden = 1.f / den;
        #pragma unroll
        for (int e = 0; e < N_EXP; e++) pr[e] *= rden;

        int i1 = 0;
        #pragma unroll
        for (int e = 1; e < N_EXP; e++) if (pr[e] > pr[i1]) i1 = e;
        int i2 = (i1 == 0) ? 1 : 0;
        #pragma unroll
        for (int e = 0; e < N_EXP; e++) if (e != i1 && pr[e] > pr[i2]) i2 = e;

        g_te[t * 2 + 0] = i1;  g_tp[t * 2 + 0] = pr[i1];
        g_te[t * 2 + 1] = i2;  g_tp[t * 2 + 1] = pr[i2];
        atomicAdd(&g_cnt[i1], 1);
        atomicAdd(&g_cnt[i2], 1);
    }
}

// ---------------- kernel 2: ALL weight transposes + bf16 splits --------------
__global__ __launch_bounds__(256)
void k_tsplit_all(const float* __restrict__ wg,
                  const float* __restrict__ wu,
                  const float* __restrict__ wd)
{
    int z = blockIdx.z;
    const float* src;
    __nv_bfloat16 *dhi, *dlo;
    int R, C, e;
    if (z < 8)       { src = wg; dhi = g_wg_hi; dlo = g_wg_lo; R = H_DIM; C = F_DIM; e = z; }
    else if (z < 16) { src = wu; dhi = g_wu_hi; dlo = g_wu_lo; R = H_DIM; C = F_DIM; e = z - 8; }
    else             { src = wd; dhi = g_wd_hi; dlo = g_wd_lo; R = F_DIM; C = H_DIM; e = z - 16; }

    int c0 = blockIdx.x * 32, r0 = blockIdx.y * 64;
    if (c0 >= C || r0 >= R) return;

    __shared__ float t[64][33];
    const float* s = src + (size_t)e * R * C;
    size_t dbase = (size_t)e * R * C;
    int tx = threadIdx.x, ty = threadIdx.y;
    #pragma unroll
    for (int i = 0; i < 8; i++) {
        int r = ty + i * 8;
        t[r][tx] = s[(size_t)(r0 + r) * C + c0 + tx];
    }
    __syncthreads();
    #pragma unroll
    for (int i = 0; i < 4; i++) {
        int c = ty + i * 8;
        float v0 = t[2 * tx][c];
        float v1 = t[2 * tx + 1][c];
        __nv_bfloat16 h0 = __float2bfloat16(v0);
        __nv_bfloat16 h1 = __float2bfloat16(v1);
        __nv_bfloat16 l0 = __float2bfloat16(v0 - __bfloat162float(h0));
        __nv_bfloat16 l1 = __float2bfloat16(v1 - __bfloat162float(h1));
        uint32_t uh = (uint32_t)__bfloat16_as_ushort(h0) | ((uint32_t)__bfloat16_as_ushort(h1) << 16);
        uint32_t ul = (uint32_t)__bfloat16_as_ushort(l0) | ((uint32_t)__bfloat16_as_ushort(l1) << 16);
        size_t o = dbase + (size_t)(c0 + c) * R + r0 + 2 * tx;
        *(uint32_t*)(dhi + o) = uh;
        *(uint32_t*)(dlo + o) = ul;
    }
}

// ---------------- kernel 3: offsets + scatter (single block) -----------------
__global__ __launch_bounds__(256)
void k_offscatter()
{
    __shared__ int s_fill[N_EXP];
    int tid = threadIdx.x;
    if (tid == 0) {
        int acc = 0;
        #pragma unroll
        for (int e = 0; e < N_EXP; e++) {
            g_offp[e]  = acc;
            s_fill[e]  = acc;
            acc += (g_cnt[e] + 127) & ~127;
        }
        g_offp[N_EXP] = acc;
    }
    __syncthreads();
    for (int t = tid; t < T_TOK; t += 256) {
        #pragma unroll
        for (int k = 0; k < 2; k++) {
            int e = g_te[t * 2 + k];
            int r = atomicAdd(&s_fill[e], 1);
            g_tok[r]   = t;
            g_scale[r] = g_tp[t * 2 + k];
        }
    }
}

// ======================= GEMM1: gate/up + SiLU (mma.sync) ====================
// R8 structure + term-outer MMA ordering (breaks 3-deep RAW chains on acc).
__global__ __launch_bounds__(256, 2)
void k_gemm1_mma()
{
    extern __shared__ char smem[];
    const uint32_t sb = s2u(smem);
    const int tid = threadIdx.x, lane = tid & 31, wid = tid >> 5;

    const int Mp = g_offp[N_EXP];
    const int m0 = blockIdx.y * 128;
    if (m0 >= Mp) return;
    const int n0 = blockIdx.x * 64;
    int e = 0;
    #pragma unroll
    for (int i = 1; i < N_EXP; i++) if (m0 >= g_offp[i]) e = i;

    __shared__ int s_tok[128];
    if (tid < 128) {
        int tok = g_tok[m0 + tid];
        s_tok[tid] = (tok >= 0) ? tok : 0;
    }
    __syncthreads();

    const int lr = tid >> 2;                  // smem row 0..63 (+64)
    const int ls = tid & 3;                   // 16B segment
    const int NC = H_DIM / 32;                // 32 chunks

    auto load_chunk = [&](int c, uint32_t base) {
        int kc = c * 32;
        uint32_t ah = base, al = base + TILE_B, bh = base + 2 * TILE_B, bl = base + 3 * TILE_B;
        #pragma unroll
        for (int i = 0; i < 2; i++) {
            int row = lr + 64 * i;
            uint32_t so = row * 64 + ((ls ^ ((row >> 1) & 3)) << 4);
            size_t go = (size_t)s_tok[row] * H_DIM + kc + ls * 8;
            cp16(ah + so, g_x_hi + go);
            cp16(al + so, g_x_lo + go);
        }
        #pragma unroll
        for (int i = 0; i < 2; i++) {
            int rn = lr + 64 * i;
            uint32_t so = rn * 64 + ((ls ^ ((rn >> 1) & 3)) << 4);
            int col = n0 + (rn >> 1);
            size_t go = ((size_t)e * F_DIM + col) * H_DIM + kc + ls * 8;
            const __nv_bfloat16* Wh = (rn & 1) ? g_wu_hi : g_wg_hi;
            const __nv_bfloat16* Wl = (rn & 1) ? g_wu_lo : g_wg_lo;
            cp16(bh + so, Wh + go);
            cp16(bl + so, Wl + go);
        }
    };

    load_chunk(0, sb);        CP_COMMIT();
    load_chunk(1, sb + STG);  CP_COMMIT();

    const int warp_m = (wid & 1) * 64;
    const int warp_n = (wid >> 1) * 32;

    float acc[4][4][4];
    #pragma unroll
    for (int i = 0; i < 4; i++)
        #pragma unroll
        for (int j = 0; j < 4; j++)
            #pragma unroll
            for (int k = 0; k < 4; k++) acc[i][j][k] = 0.f;

    const int quad = lane >> 3, l7 = lane & 7;
    const int a_row = warp_m + (quad & 1) * 8 + l7;
    const int b_row = warp_n + (quad & 1) * 8 + l7;
    const int kq = quad >> 1;
    const int a_swz = (a_row >> 1) & 3;
    const int b_swz = (b_row >> 1) & 3;

    uint32_t base_c = sb;                  // stage of chunk c
    uint32_t base_l = sb + 2 * STG;        // stage for chunk c+2
    const uint32_t wrap = sb + 3 * STG;

    for (int c = 0; c < NC; c++) {
        if (c + 1 < NC) { CP_WAIT1(); } else { CP_WAIT0(); }
        __syncthreads();
        if (c + 2 < NC) { load_chunk(c + 2, base_l); CP_COMMIT(); }
        base_l += STG; if (base_l == wrap) base_l = sb;

        const uint32_t ah = base_c, al = base_c + TILE_B;
        const uint32_t bh = base_c + 2 * TILE_B, bl = base_c + 3 * TILE_B;
        #pragma unroll
        for (int ks = 0; ks < 2; ks++) {
            const uint32_t a_seg = (uint32_t)(((ks * 2 + kq) ^ a_swz) << 4);
            const uint32_t b_seg = (uint32_t)(((ks * 2 + kq) ^ b_swz) << 4);
            uint32_t aH[4][4], aL[4][4], bH[2][4], bL[2][4];
            #pragma unroll
            for (int mi = 0; mi < 4; mi++) {
                uint32_t ro = (a_row + mi * 16) * 64 + a_seg;
                ldsm4(aH[mi], ah + ro);
                ldsm4(aL[mi], al + ro);
            }
            #pragma unroll
            for (int bj = 0; bj < 2; bj++) {
                uint32_t ro = (b_row + bj * 16) * 64 + b_seg;
                ldsm4(bH[bj], bh + ro);
                ldsm4(bL[bj], bl + ro);
            }
            // term 1: aH * bH  (16 independent MMAs)
            #pragma unroll
            for (int mi = 0; mi < 4; mi++)
                #pragma unroll
                for (int nj = 0; nj < 4; nj++) {
                    const uint32_t* f = bH[nj >> 1];
                    int s = nj & 1;
                    mma16816(acc[mi][nj], aH[mi], f[s], f[s + 2]);
                }
            // term 2: aH * bL
            #pragma unroll
            for (int mi = 0; mi < 4; mi++)
                #pragma unroll
                for (int nj = 0; nj < 4; nj++) {
                    const uint32_t* f = bL[nj >> 1];
                    int s = nj & 1;
                    mma16816(acc[mi][nj], aH[mi], f[s], f[s + 2]);
                }
            // term 3: aL * bH
            #pragma unroll
            for (int mi = 0; mi < 4; mi++)
                #pragma unroll
                for (int nj = 0; nj < 4; nj++) {
                    const uint32_t* f = bH[nj >> 1];
                    int s = nj & 1;
                    mma16816(acc[mi][nj], aL[mi], f[s], f[s + 2]);
                }
        }
        base_c += STG; if (base_c == wrap) base_c = sb;
    }

    // epilogue: h = silu(g)*u (fast intrinsics); split bf16
    const int rbase = m0 + warp_m + (lane >> 2);
    const int cbase = n0 + (warp_n >> 1) + (lane & 3);
    #pragma unroll
    for (int mi = 0; mi < 4; mi++) {
        size_t r0 = (size_t)(rbase + mi * 16) * F_DIM;
        size_t r1 = r0 + 8 * F_DIM;
        #pragma unroll
        for (int nj = 0; nj < 4; nj++) {
            int L = cbase + nj * 4;
            float g0 = acc[mi][nj][0], u0 = acc[mi][nj][1];
            float g1 = acc[mi][nj][2], u1 = acc[mi][nj][3];
            float h0 = __fdividef(g0, 1.f + __expf(-g0)) * u0;
            float h1 = __fdividef(g1, 1.f + __expf(-g1)) * u1;
            __nv_bfloat16 h0h = __float2bfloat16(h0);
            __nv_bfloat16 h1h = __float2bfloat16(h1);
            g_h_hi[r0 + L] = h0h;
            g_h_hi[r1 + L] = h1h;
            g_h_lo[r0 + L] = __float2bfloat16(h0 - __bfloat162float(h0h));
            g_h_lo[r1 + L] = __float2bfloat16(h1 - __bfloat162float(h1h));
        }
    }
}

// ======================= GEMM2: down proj + combine (mma.sync) ===============
__global__ __launch_bounds__(256, 2)
void k_gemm2_mma(float* __restrict__ out)
{
    extern __shared__ char smem[];
    const uint32_t sb = s2u(smem);
    const int tid = threadIdx.x, lane = tid & 31, wid = tid >> 5;

    const int Mp = g_offp[N_EXP];
    const int m0 = blockIdx.y * 128;
    if (m0 >= Mp) return;
    const int n0 = blockIdx.x * 128;
    int e = 0;
    #pragma unroll
    for (int i = 1; i < N_EXP; i++) if (m0 >= g_offp[i]) e = i;

    const int lr = tid >> 2;
    const int ls = tid & 3;
    const int NC = F_DIM / 32;                // 88 chunks

    auto load_chunk = [&](int c, uint32_t base) {
        int kc = c * 32;
        uint32_t ah = base, al = base + TILE_B, bh = base + 2 * TILE_B, bl = base + 3 * TILE_B;
        #pragma unroll
        for (int i = 0; i < 2; i++) {
            int row = lr + 64 * i;
            uint32_t so = row * 64 + ((ls ^ ((row >> 1) & 3)) << 4);
            size_t go = (size_t)(m0 + row) * F_DIM + kc + ls * 8;
            cp16(ah + so, g_h_hi + go);
            cp16(al + so, g_h_lo + go);
        }
        #pragma unroll
        for (int i = 0; i < 2; i++) {
            int rn = lr + 64 * i;
            uint32_t so = rn * 64 + ((ls ^ ((rn >> 1) & 3)) << 4);
            size_t go = ((size_t)e * H_DIM + n0 + rn) * F_DIM + kc + ls * 8;
            cp16(bh + so, g_wd_hi + go);
            cp16(bl + so, g_wd_lo + go);
        }
    };

    load_chunk(0, sb);        CP_COMMIT();
    load_chunk(1, sb + STG);  CP_COMMIT();

    const int warp_m = (wid & 1) * 64;
    const int warp_n = (wid >> 1) * 32;

    float acc[4][4][4];
    #pragma unroll
    for (int i = 0; i < 4; i++)
        #pragma unroll
        for (int j = 0; j < 4; j++)
            #pragma unroll
            for (int k = 0; k < 4; k++) acc[i][j][k] = 0.f;

    const int quad = lane >> 3, l7 = lane & 7;
    const int a_row = warp_m + (quad & 1) * 8 + l7;
    const int b_row = warp_n + (quad & 1) * 8 + l7;
    const int kq = quad >> 1;
    const int a_swz = (a_row >> 1) & 3;
    const int b_swz = (b_row >> 1) & 3;

    uint32_t base_c = sb;
    uint32_t base_l = sb + 2 * STG;
    const uint32_t wrap = sb + 3 * STG;

    for (int c = 0; c < NC; c++) {
        if (c + 1 < NC) { CP_WAIT1(); } else { CP_WAIT0(); }
        __syncthreads();
        if (c + 2 < NC) { load_chunk(c + 2, base_l); CP_COMMIT(); }
        base_l += STG; if (base_l == wrap) base_l = sb;

        const uint32_t ah = base_c, al = base_c + TILE_B;
        const uint32_t bh = base_c + 2 * TILE_B, bl = base_c + 3 * TILE_B;
        #pragma unroll
        for (int ks = 0; ks < 2; ks++) {
            const uint32_t a_seg = (uint32_t)(((ks * 2 + kq) ^ a_swz) << 4);
            const uint32_t b_seg = (uint32_t)(((ks * 2 + kq) ^ b_swz) << 4);
            uint32_t aH[4][4], aL[4][4], bH[2][4], bL[2][4];
            #pragma unroll
            for (int mi = 0; mi < 4; mi++) {
                uint32_t ro = (a_row + mi * 16) * 64 + a_seg;
                ldsm4(aH[mi], ah + ro);
                ldsm4(aL[mi], al + ro);
            }
            #pragma unroll
            for (int bj = 0; bj < 2; bj++) {
                uint32_t ro = (b_row + bj * 16) * 64 + b_seg;
                ldsm4(bH[bj], bh + ro);
                ldsm4(bL[bj], bl + ro);
            }
            // term-outer ordering
            #pragma unroll
            for (int mi = 0; mi < 4; mi++)
                #pragma unroll
                for (int nj = 0; nj < 4; nj++) {
                    const uint32_t* f = bH[nj >> 1];
                    int s = nj & 1;
                    mma16816(acc[mi][nj], aH[mi], f[s], f[s + 2]);
                }
            #pragma unroll
            for (int mi = 0; mi < 4; mi++)
                #pragma unroll
                for (int nj = 0; nj < 4; nj++) {
                    const uint32_t* f = bL[nj >> 1];
                    int s = nj & 1;
                    mma16816(acc[mi][nj], aH[mi], f[s], f[s + 2]);
                }
            #pragma unroll
            for (int mi = 0; mi < 4; mi++)
                #pragma unroll
                for (int nj = 0; nj < 4; nj++) {
                    const uint32_t* f = bH[nj >> 1];
                    int s = nj & 1;
                    mma16816(acc[mi][nj], aL[mi], f[s], f[s + 2]);
                }
        }
        base_c += STG; if (base_c == wrap) base_c = sb;
    }

    const int rbase = m0 + warp_m + (lane >> 2);
    const int cbase = n0 + warp_n + (lane & 3) * 2;
    #pragma unroll
    for (int mi = 0; mi < 4; mi++) {
        int r0 = rbase + mi * 16;
        int r1 = r0 + 8;
        int tok0 = g_tok[r0], tok1 = g_tok[r1];
        float sc0 = (tok0 >= 0) ? g_scale[r0] : 0.f;
        float sc1 = (tok1 >= 0) ? g_scale[r1] : 0.f;
        #pragma unroll
        for (int nj = 0; nj < 4; nj++) {
            int col = cbase + nj * 8;
            if (tok0 >= 0) {
                float* p0 = out + (size_t)tok0 * H_DIM + col;
                atomicAdd(p0,     acc[mi][nj][0] * sc0);
                atomicAdd(p0 + 1, acc[mi][nj][1] * sc0);
            }
            if (tok1 >= 0) {
                float* p1 = out + (size_t)tok1 * H_DIM + col;
                atomicAdd(p1,     acc[mi][nj][2] * sc1);
                atomicAdd(p1 + 1, acc[mi][nj][3] * sc1);
            }
        }
    }
}

// ---------------- launch ----------------
extern "C" void kernel_launch(void* const* d_in, const int* in_sizes, int n_in,
                              void* d_out, int out_size)
{
    const float* hs  = (const float*)d_in[0];
    const float* lnw = (const float*)d_in[1];
    const float* rw  = (const float*)d_in[2];
    const float* wg  = (const float*)d_in[3];
    const float* wu  = (const float*)d_in[4];
    const float* wd  = (const float*)d_in[5];
    float* out = (float*)d_out;

    cudaFuncSetAttribute(k_gemm1_mma, cudaFuncAttributeMaxDynamicSharedMemorySize, SMEM_TOT);
    cudaFuncSetAttribute(k_gemm2_mma, cudaFuncAttributeMaxDynamicSharedMemorySize, SMEM_TOT);

    void *p_cnt = nullptr, *p_tok = nullptr;
    cudaGetSymbolAddress(&p_cnt, g_cnt);
    cudaGetSymbolAddress(&p_tok, g_tok);

    cudaMemsetAsync(p_cnt, 0, N_EXP * sizeof(int));
    cudaMemsetAsync(p_tok, 0xFF, MP_MAX * sizeof(int));
    cudaMemsetAsync(out, 0, (size_t)out_size * sizeof(float));

    k_rms_router<<<T_TOK, 256>>>(hs, lnw, rw);

    dim3 tb(32, 8);
    dim3 tg(F_DIM / 32, F_DIM / 64, 24);
    k_tsplit_all<<<tg, tb>>>(wg, wu, wd);

    k_offscatter<<<1, 256>>>();

    // launch 4 (ncu capture slot): GEMM1
    dim3 g1(F_DIM / 64, MP_MAX / 128);   // (44, 72)
    k_gemm1_mma<<<g1, 256, SMEM_TOT>>>();

    dim3 g2(H_DIM / 128, MP_MAX / 128);  // (8, 72)
    k_gemm2_mma<<<g2, 256, SMEM_TOT>>>(out);
}

// round 11
// speedup vs baseline: 1.0423x; 1.0219x over previous
#include <cuda_runtime.h>
#include <cuda_bf16.h>
#include <math.h>
#include <stdint.h>

#define T_TOK 4096
#define H_DIM 1024
#define F_DIM 2816
#define N_EXP 8
#define EPS_V 1e-5f
#define MP_MAX 9216

// swizzled smem: 64B rows (32 bf16), seg' = seg ^ ((row>>1)&3)
#define TILE_B 8192                  // 128 rows * 64B
#define STG   (4 * TILE_B)           // Ah, Al, Bh, Bl per stage = 32768
#define SMEM_TOT (3 * STG)           // 98304 -> 2 CTAs/SM

// ---------------- PTX helpers (sm_80-family, valid on plain sm_103) ---------
__device__ __forceinline__ uint32_t s2u(const void* p) {
    uint32_t a;
    asm("{ .reg .u64 t; cvta.to.shared.u64 t, %1; cvt.u32.u64 %0, t; }" : "=r"(a) : "l"(p));
    return a;
}
__device__ __forceinline__ void ldsm4(uint32_t* r, uint32_t a) {
    asm volatile("ldmatrix.sync.aligned.m8n8.x4.shared.b16 {%0,%1,%2,%3}, [%4];"
        : "=r"(r[0]), "=r"(r[1]), "=r"(r[2]), "=r"(r[3]) : "r"(a));
}
__device__ __forceinline__ void mma16816(float* d, const uint32_t* a, uint32_t b0, uint32_t b1) {
    asm volatile("mma.sync.aligned.m16n8k16.row.col.f32.bf16.bf16.f32 "
        "{%0,%1,%2,%3}, {%4,%5,%6,%7}, {%8,%9}, {%0,%1,%2,%3};"
        : "+f"(d[0]), "+f"(d[1]), "+f"(d[2]), "+f"(d[3])
        : "r"(a[0]), "r"(a[1]), "r"(a[2]), "r"(a[3]), "r"(b0), "r"(b1));
}
__device__ __forceinline__ void cp16(uint32_t s, const void* g) {
    asm volatile("{ .reg .u64 gg; cvta.to.global.u64 gg, %1; "
                 "cp.async.cg.shared.global [%0], [gg], 16; }"
                 :: "r"(s), "l"(g) : "memory");
}
#define CP_COMMIT() asm volatile("cp.async.commit_group;" ::: "memory")
#define CP_WAIT1()  asm volatile("cp.async.wait_group 1;" ::: "memory")
#define CP_WAIT0()  asm volatile("cp.async.wait_group 0;" ::: "memory")

// ---------------- scratch (device globals) ----------------
__device__ __nv_bfloat16 g_x_hi[T_TOK * H_DIM];
__device__ __nv_bfloat16 g_x_lo[T_TOK * H_DIM];
__device__ __nv_bfloat16 g_h_hi[(size_t)MP_MAX * F_DIM];
__device__ __nv_bfloat16 g_h_lo[(size_t)MP_MAX * F_DIM];
__device__ __nv_bfloat16 g_wg_hi[(size_t)N_EXP * F_DIM * H_DIM];
__device__ __nv_bfloat16 g_wg_lo[(size_t)N_EXP * F_DIM * H_DIM];
__device__ __nv_bfloat16 g_wu_hi[(size_t)N_EXP * F_DIM * H_DIM];
__device__ __nv_bfloat16 g_wu_lo[(size_t)N_EXP * F_DIM * H_DIM];
__device__ __nv_bfloat16 g_wd_hi[(size_t)N_EXP * H_DIM * F_DIM];
__device__ __nv_bfloat16 g_wd_lo[(size_t)N_EXP * H_DIM * F_DIM];
__device__ float g_part[(size_t)MP_MAX * H_DIM];     // per-assignment scaled output
__device__ int   g_tok[MP_MAX];
__device__ float g_scale[MP_MAX];
__device__ int   g_rowof[T_TOK * 2];                 // token -> assignment rows
__device__ int   g_te[T_TOK * 2];
__device__ float g_tp[T_TOK * 2];
__device__ int   g_cnt[N_EXP];
__device__ int   g_offp[N_EXP + 1];

// ---------------- kernel 1: rmsnorm + router + bf16 split ----------------
__global__ __launch_bounds__(256)
void k_rms_router(const float* __restrict__ hs,
                  const float* __restrict__ lnw,
                  const float* __restrict__ rw)
{
    int t = blockIdx.x;
    int tid = threadIdx.x;
    int lane = tid & 31, wid = tid >> 5;

    __shared__ float s_x[H_DIM];
    __shared__ float swr[8];
    __shared__ float s_inv;
    __shared__ float sl[8][N_EXP];

    const float4 v = ((const float4*)(hs + (size_t)t * H_DIM))[tid];
    float ss = v.x*v.x + v.y*v.y + v.z*v.z + v.w*v.w;
    #pragma unroll
    for (int o = 16; o; o >>= 1) ss += __shfl_xor_sync(0xffffffffu, ss, o);
    if (lane == 0) swr[wid] = ss;
    __syncthreads();
    if (tid == 0) {
        float s = 0.f;
        #pragma unroll
        for (int i = 0; i < 8; i++) s += swr[i];
        s_inv = rsqrtf(s / (float)H_DIM + EPS_V);
    }
    __syncthreads();
    float inv = s_inv;

    const float4 w = ((const float4*)lnw)[tid];
    float xv[4];
    xv[0] = v.x * inv * w.x;  xv[1] = v.y * inv * w.y;
    xv[2] = v.z * inv * w.z;  xv[3] = v.w * inv * w.w;

    __nv_bfloat16 hi[4], lo[4];
    #pragma unroll
    for (int j = 0; j < 4; j++) {
        s_x[tid * 4 + j] = xv[j];
        hi[j] = __float2bfloat16(xv[j]);
        lo[j] = __float2bfloat16(xv[j] - __bfloat162float(hi[j]));
    }
    ((uint2*)(g_x_hi + (size_t)t * H_DIM))[tid] = *(uint2*)hi;
    ((uint2*)(g_x_lo + (size_t)t * H_DIM))[tid] = *(uint2*)lo;
    __syncthreads();

    {
        const int c = lane & 3, r = lane >> 2;
        const float2* rw2 = (const float2*)rw;
        float2 p = make_float2(0.f, 0.f);
        int ibase = wid * 128 + r;
        #pragma unroll
        for (int k = 0; k < 16; k++) {
            int i = ibase + k * 8;
            float2 w2 = rw2[i * 4 + c];
            float xs = s_x[i];
            p.x += xs * w2.x;
            p.y += xs * w2.y;
        }
        #pragma unroll
        for (int o = 16; o >= 4; o >>= 1) {
            p.x += __shfl_xor_sync(0xffffffffu, p.x, o);
            p.y += __shfl_xor_sync(0xffffffffu, p.y, o);
        }
        if (lane < 4) {
            sl[wid][2 * c]     = p.x;
            sl[wid][2 * c + 1] = p.y;
        }
    }
    __syncthreads();

    if (tid == 0) {
        float l[N_EXP];
        #pragma unroll
        for (int e = 0; e < N_EXP; e++) {
            float s = 0.f;
            #pragma unroll
            for (int w2 = 0; w2 < 8; w2++) s += sl[w2][e];
            l[e] = s;
        }
        float m = l[0];
        #pragma unroll
        for (int e = 1; e < N_EXP; e++) m = fmaxf(m, l[e]);
        float den = 0.f, pr[N_EXP];
        #pragma unroll
        for (int e = 0; e < N_EXP; e++) { pr[e] = expf(l[e] - m); den += pr[e]; }
        float rden = 1.f / den;
        #pragma unroll
        for (int e = 0; e < N_EXP; e++) pr[e] *= rden;

        int i1 = 0;
        #pragma unroll
        for (int e = 1; e < N_EXP; e++) if (pr[e] > pr[i1]) i1 = e;
        int i2 = (i1 == 0) ? 1 : 0;
        #pragma unroll
        for (int e = 0; e < N_EXP; e++) if (e != i1 && pr[e] > pr[i2]) i2 = e;

        g_te[t * 2 + 0] = i1;  g_tp[t * 2 + 0] = pr[i1];
        g_te[t * 2 + 1] = i2;  g_tp[t * 2 + 1] = pr[i2];
        atomicAdd(&g_cnt[i1], 1);
        atomicAdd(&g_cnt[i2], 1);
    }
}

// ---------------- kernel 2: ALL weight transposes + bf16 splits --------------
__global__ __launch_bounds__(256)
void k_tsplit_all(const float* __restrict__ wg,
                  const float* __restrict__ wu,
                  const float* __restrict__ wd)
{
    int z = blockIdx.z;
    const float* src;
    __nv_bfloat16 *dhi, *dlo;
    int R, C, e;
    if (z < 8)       { src = wg; dhi = g_wg_hi; dlo = g_wg_lo; R = H_DIM; C = F_DIM; e = z; }
    else if (z < 16) { src = wu; dhi = g_wu_hi; dlo = g_wu_lo; R = H_DIM; C = F_DIM; e = z - 8; }
    else             { src = wd; dhi = g_wd_hi; dlo = g_wd_lo; R = F_DIM; C = H_DIM; e = z - 16; }

    int c0 = blockIdx.x * 32, r0 = blockIdx.y * 64;
    if (c0 >= C || r0 >= R) return;

    __shared__ float t[64][33];
    const float* s = src + (size_t)e * R * C;
    size_t dbase = (size_t)e * R * C;
    int tx = threadIdx.x, ty = threadIdx.y;
    #pragma unroll
    for (int i = 0; i < 8; i++) {
        int r = ty + i * 8;
        t[r][tx] = s[(size_t)(r0 + r) * C + c0 + tx];
    }
    __syncthreads();
    #pragma unroll
    for (int i = 0; i < 4; i++) {
        int c = ty + i * 8;
        float v0 = t[2 * tx][c];
        float v1 = t[2 * tx + 1][c];
        __nv_bfloat16 h0 = __float2bfloat16(v0);
        __nv_bfloat16 h1 = __float2bfloat16(v1);
        __nv_bfloat16 l0 = __float2bfloat16(v0 - __bfloat162float(h0));
        __nv_bfloat16 l1 = __float2bfloat16(v1 - __bfloat162float(h1));
        uint32_t uh = (uint32_t)__bfloat16_as_ushort(h0) | ((uint32_t)__bfloat16_as_ushort(h1) << 16);
        uint32_t ul = (uint32_t)__bfloat16_as_ushort(l0) | ((uint32_t)__bfloat16_as_ushort(l1) << 16);
        size_t o = dbase + (size_t)(c0 + c) * R + r0 + 2 * tx;
        *(uint32_t*)(dhi + o) = uh;
        *(uint32_t*)(dlo + o) = ul;
    }
}

// ---------------- kernel 3: offsets + scatter (single block) -----------------
__global__ __launch_bounds__(256)
void k_offscatter()
{
    __shared__ int s_fill[N_EXP];
    int tid = threadIdx.x;
    if (tid == 0) {
        int acc = 0;
        #pragma unroll
        for (int e = 0; e < N_EXP; e++) {
            g_offp[e]  = acc;
            s_fill[e]  = acc;
            acc += (g_cnt[e] + 127) & ~127;
        }
        g_offp[N_EXP] = acc;
    }
    __syncthreads();
    for (int t = tid; t < T_TOK; t += 256) {
        #pragma unroll
        for (int k = 0; k < 2; k++) {
            int e = g_te[t * 2 + k];
            int r = atomicAdd(&s_fill[e], 1);
            g_tok[r]     = t;
            g_scale[r]   = g_tp[t * 2 + k];
            g_rowof[t * 2 + k] = r;
        }
    }
}

// ======================= GEMM1: gate/up + SiLU (mma.sync) ====================
// Exact R8 mainloop (proven 826us / tensor 59%).
__global__ __launch_bounds__(256, 2)
void k_gemm1_mma()
{
    extern __shared__ char smem[];
    const uint32_t sb = s2u(smem);
    const int tid = threadIdx.x, lane = tid & 31, wid = tid >> 5;

    const int Mp = g_offp[N_EXP];
    const int m0 = blockIdx.y * 128;
    if (m0 >= Mp) return;
    const int n0 = blockIdx.x * 64;
    int e = 0;
    #pragma unroll
    for (int i = 1; i < N_EXP; i++) if (m0 >= g_offp[i]) e = i;

    __shared__ int s_tok[128];
    if (tid < 128) {
        int tok = g_tok[m0 + tid];
        s_tok[tid] = (tok >= 0) ? tok : 0;
    }
    __syncthreads();

    const int lr = tid >> 2;
    const int ls = tid & 3;
    const int NC = H_DIM / 32;

    auto load_chunk = [&](int c, int stg) {
        int kc = c * 32;
        uint32_t base = sb + stg * STG;
        uint32_t ah = base, al = base + TILE_B, bh = base + 2 * TILE_B, bl = base + 3 * TILE_B;
        #pragma unroll
        for (int i = 0; i < 2; i++) {
            int row = lr + 64 * i;
            uint32_t so = row * 64 + ((ls ^ ((row >> 1) & 3)) << 4);
            size_t go = (size_t)s_tok[row] * H_DIM + kc + ls * 8;
            cp16(ah + so, g_x_hi + go);
            cp16(al + so, g_x_lo + go);
        }
        #pragma unroll
        for (int i = 0; i < 2; i++) {
            int rn = lr + 64 * i;
            uint32_t so = rn * 64 + ((ls ^ ((rn >> 1) & 3)) << 4);
            int col = n0 + (rn >> 1);
            size_t go = ((size_t)e * F_DIM + col) * H_DIM + kc + ls * 8;
            const __nv_bfloat16* Wh = (rn & 1) ? g_wu_hi : g_wg_hi;
            const __nv_bfloat16* Wl = (rn & 1) ? g_wu_lo : g_wg_lo;
            cp16(bh + so, Wh + go);
            cp16(bl + so, Wl + go);
        }
    };

    load_chunk(0, 0); CP_COMMIT();
    load_chunk(1, 1); CP_COMMIT();

    const int warp_m = (wid & 1) * 64;
    const int warp_n = (wid >> 1) * 32;

    float acc[4][4][4];
    #pragma unroll
    for (int i = 0; i < 4; i++)
        #pragma unroll
        for (int j = 0; j < 4; j++)
            #pragma unroll
            for (int k = 0; k < 4; k++) acc[i][j][k] = 0.f;

    const int quad = lane >> 3, l7 = lane & 7;
    const int a_row = warp_m + (quad & 1) * 8 + l7;
    const int b_row = warp_n + (quad & 1) * 8 + l7;
    const int kq = quad >> 1;
    const int a_swz = (a_row >> 1) & 3;
    const int b_swz = (b_row >> 1) & 3;

    for (int c = 0; c < NC; c++) {
        if (c + 1 < NC) { CP_WAIT1(); } else { CP_WAIT0(); }
        __syncthreads();
        if (c + 2 < NC) { load_chunk(c + 2, (c + 2) % 3); CP_COMMIT(); }

        uint32_t base = sb + (c % 3) * STG;
        uint32_t ah = base, al = base + TILE_B, bh = base + 2 * TILE_B, bl = base + 3 * TILE_B;
        #pragma unroll
        for (int ks = 0; ks < 2; ks++) {
            const uint32_t a_seg = (uint32_t)(((ks * 2 + kq) ^ a_swz) << 4);
            const uint32_t b_seg = (uint32_t)(((ks * 2 + kq) ^ b_swz) << 4);
            uint32_t aH[4][4], aL[4][4], bH[2][4], bL[2][4];
            #pragma unroll
            for (int mi = 0; mi < 4; mi++) {
                uint32_t ro = (a_row + mi * 16) * 64 + a_seg;
                ldsm4(aH[mi], ah + ro);
                ldsm4(aL[mi], al + ro);
            }
            #pragma unroll
            for (int bj = 0; bj < 2; bj++) {
                uint32_t ro = (b_row + bj * 16) * 64 + b_seg;
                ldsm4(bH[bj], bh + ro);
                ldsm4(bL[bj], bl + ro);
            }
            #pragma unroll
            for (int mi = 0; mi < 4; mi++)
                #pragma unroll
                for (int nj = 0; nj < 4; nj++) {
                    const uint32_t* fh = bH[nj >> 1];
                    const uint32_t* fl = bL[nj >> 1];
                    int s = nj & 1;
                    mma16816(acc[mi][nj], aH[mi], fh[s], fh[s + 2]);
                    mma16816(acc[mi][nj], aH[mi], fl[s], fl[s + 2]);
                    mma16816(acc[mi][nj], aL[mi], fh[s], fh[s + 2]);
                }
        }
    }

    const int rbase = m0 + warp_m + (lane >> 2);
    const int cbase = n0 + (warp_n >> 1) + (lane & 3);
    #pragma unroll
    for (int mi = 0; mi < 4; mi++) {
        size_t r0 = (size_t)(rbase + mi * 16) * F_DIM;
        size_t r1 = r0 + 8 * F_DIM;
        #pragma unroll
        for (int nj = 0; nj < 4; nj++) {
            int L = cbase + nj * 4;
            float g0 = acc[mi][nj][0], u0 = acc[mi][nj][1];
            float g1 = acc[mi][nj][2], u1 = acc[mi][nj][3];
            float h0 = (g0 / (1.f + expf(-g0))) * u0;
            float h1 = (g1 / (1.f + expf(-g1))) * u1;
            __nv_bfloat16 h0h = __float2bfloat16(h0);
            __nv_bfloat16 h1h = __float2bfloat16(h1);
            g_h_hi[r0 + L] = h0h;
            g_h_hi[r1 + L] = h1h;
            g_h_lo[r0 + L] = __float2bfloat16(h0 - __bfloat162float(h0h));
            g_h_lo[r1 + L] = __float2bfloat16(h1 - __bfloat162float(h1h));
        }
    }
}

// ======================= GEMM2: down proj -> g_part (STG, no atomics) ========
__global__ __launch_bounds__(256, 2)
void k_gemm2_mma()
{
    extern __shared__ char smem[];
    const uint32_t sb = s2u(smem);
    const int tid = threadIdx.x, lane = tid & 31, wid = tid >> 5;

    const int Mp = g_offp[N_EXP];
    const int m0 = blockIdx.y * 128;
    if (m0 >= Mp) return;
    const int n0 = blockIdx.x * 128;
    int e = 0;
    #pragma unroll
    for (int i = 1; i < N_EXP; i++) if (m0 >= g_offp[i]) e = i;

    const int lr = tid >> 2;
    const int ls = tid & 3;
    const int NC = F_DIM / 32;

    auto load_chunk = [&](int c, int stg) {
        int kc = c * 32;
        uint32_t base = sb + stg * STG;
        uint32_t ah = base, al = base + TILE_B, bh = base + 2 * TILE_B, bl = base + 3 * TILE_B;
        #pragma unroll
        for (int i = 0; i < 2; i++) {
            int row = lr + 64 * i;
            uint32_t so = row * 64 + ((ls ^ ((row >> 1) & 3)) << 4);
            size_t go = (size_t)(m0 + row) * F_DIM + kc + ls * 8;
            cp16(ah + so, g_h_hi + go);
            cp16(al + so, g_h_lo + go);
        }
        #pragma unroll
        for (int i = 0; i < 2; i++) {
            int rn = lr + 64 * i;
            uint32_t so = rn * 64 + ((ls ^ ((rn >> 1) & 3)) << 4);
            size_t go = ((size_t)e * H_DIM + n0 + rn) * F_DIM + kc + ls * 8;
            cp16(bh + so, g_wd_hi + go);
            cp16(bl + so, g_wd_lo + go);
        }
    };

    load_chunk(0, 0); CP_COMMIT();
    load_chunk(1, 1); CP_COMMIT();

    const int warp_m = (wid & 1) * 64;
    const int warp_n = (wid >> 1) * 32;

    float acc[4][4][4];
    #pragma unroll
    for (int i = 0; i < 4; i++)
        #pragma unroll
        for (int j = 0; j < 4; j++)
            #pragma unroll
            for (int k = 0; k < 4; k++) acc[i][j][k] = 0.f;

    const int quad = lane >> 3, l7 = lane & 7;
    const int a_row = warp_m + (quad & 1) * 8 + l7;
    const int b_row = warp_n + (quad & 1) * 8 + l7;
    const int kq = quad >> 1;
    const int a_swz = (a_row >> 1) & 3;
    const int b_swz = (b_row >> 1) & 3;

    for (int c = 0; c < NC; c++) {
        if (c + 1 < NC) { CP_WAIT1(); } else { CP_WAIT0(); }
        __syncthreads();
        if (c + 2 < NC) { load_chunk(c + 2, (c + 2) % 3); CP_COMMIT(); }

        uint32_t base = sb + (c % 3) * STG;
        uint32_t ah = base, al = base + TILE_B, bh = base + 2 * TILE_B, bl = base + 3 * TILE_B;
        #pragma unroll
        for (int ks = 0; ks < 2; ks++) {
            const uint32_t a_seg = (uint32_t)(((ks * 2 + kq) ^ a_swz) << 4);
            const uint32_t b_seg = (uint32_t)(((ks * 2 + kq) ^ b_swz) << 4);
            uint32_t aH[4][4], aL[4][4], bH[2][4], bL[2][4];
            #pragma unroll
            for (int mi = 0; mi < 4; mi++) {
                uint32_t ro = (a_row + mi * 16) * 64 + a_seg;
                ldsm4(aH[mi], ah + ro);
                ldsm4(aL[mi], al + ro);
            }
            #pragma unroll
            for (int bj = 0; bj < 2; bj++) {
                uint32_t ro = (b_row + bj * 16) * 64 + b_seg;
                ldsm4(bH[bj], bh + ro);
                ldsm4(bL[bj], bl + ro);
            }
            #pragma unroll
            for (int mi = 0; mi < 4; mi++)
                #pragma unroll
                for (int nj = 0; nj < 4; nj++) {
                    const uint32_t* fh = bH[nj >> 1];
                    const uint32_t* fl = bL[nj >> 1];
                    int s = nj & 1;
                    mma16816(acc[mi][nj], aH[mi], fh[s], fh[s + 2]);
                    mma16816(acc[mi][nj], aH[mi], fl[s], fl[s + 2]);
                    mma16816(acc[mi][nj], aL[mi], fh[s], fh[s + 2]);
                }
        }
    }

    // epilogue: scale and STORE to per-assignment buffer (exclusive rows)
    const int rbase = m0 + warp_m + (lane >> 2);
    const int cbase = n0 + warp_n + (lane & 3) * 2;
    #pragma unroll
    for (int mi = 0; mi < 4; mi++) {
        int r0 = rbase + mi * 16;
        int r1 = r0 + 8;
        float sc0 = g_scale[r0];
        float sc1 = g_scale[r1];
        float* p0 = g_part + (size_t)r0 * H_DIM;
        float* p1 = g_part + (size_t)r1 * H_DIM;
        #pragma unroll
        for (int nj = 0; nj < 4; nj++) {
            int col = cbase + nj * 8;
            float2 v0 = make_float2(acc[mi][nj][0] * sc0, acc[mi][nj][1] * sc0);
            float2 v1 = make_float2(acc[mi][nj][2] * sc1, acc[mi][nj][3] * sc1);
            *(float2*)(p0 + col) = v0;
            *(float2*)(p1 + col) = v1;
        }
    }
}

// ---------------- kernel 6: combine the two expert contributions -------------
__global__ __launch_bounds__(256)
void k_combine(float* __restrict__ out)
{
    int t = blockIdx.x;
    int tid = threadIdx.x;
    int r0 = g_rowof[t * 2 + 0];
    int r1 = g_rowof[t * 2 + 1];
    float4 a = ((const float4*)(g_part + (size_t)r0 * H_DIM))[tid];
    float4 b = ((const float4*)(g_part + (size_t)r1 * H_DIM))[tid];
    float4 o;
    o.x = a.x + b.x;  o.y = a.y + b.y;
    o.z = a.z + b.z;  o.w = a.w + b.w;
    ((float4*)(out + (size_t)t * H_DIM))[tid] = o;
}

// ---------------- launch ----------------
extern "C" void kernel_launch(void* const* d_in, const int* in_sizes, int n_in,
                              void* d_out, int out_size)
{
    const float* hs  = (const float*)d_in[0];
    const float* lnw = (const float*)d_in[1];
    const float* rw  = (const float*)d_in[2];
    const float* wg  = (const float*)d_in[3];
    const float* wu  = (const float*)d_in[4];
    const float* wd  = (const float*)d_in[5];
    float* out = (float*)d_out;

    cudaFuncSetAttribute(k_gemm1_mma, cudaFuncAttributeMaxDynamicSharedMemorySize, SMEM_TOT);
    cudaFuncSetAttribute(k_gemm2_mma, cudaFuncAttributeMaxDynamicSharedMemorySize, SMEM_TOT);

    void *p_cnt = nullptr, *p_tok = nullptr;
    cudaGetSymbolAddress(&p_cnt, g_cnt);
    cudaGetSymbolAddress(&p_tok, g_tok);

    cudaMemsetAsync(p_cnt, 0, N_EXP * sizeof(int));
    cudaMemsetAsync(p_tok, 0xFF, MP_MAX * sizeof(int));

    k_rms_router<<<T_TOK, 256>>>(hs, lnw, rw);

    dim3 tb(32, 8);
    dim3 tg(F_DIM / 32, F_DIM / 64, 24);
    k_tsplit_all<<<tg, tb>>>(wg, wu, wd);

    k_offscatter<<<1, 256>>>();

    // launch 4 (ncu capture slot): GEMM1
    dim3 g1(F_DIM / 64, MP_MAX / 128);   // (44, 72)
    k_gemm1_mma<<<g1, 256, SMEM_TOT>>>();

    dim3 g2(H_DIM / 128, MP_MAX / 128);  // (8, 72)
    k_gemm2_mma<<<g2, 256, SMEM_TOT>>>();

    k_combine<<<T_TOK, 256>>>(out);
}

// round 12
// speedup vs baseline: 1.0484x; 1.0059x over previous
#include <cuda_runtime.h>
#include <cuda_bf16.h>
#include <math.h>
#include <stdint.h>

#define T_TOK 4096
#define H_DIM 1024
#define F_DIM 2816
#define N_EXP 8
#define EPS_V 1e-5f
#define MP_MAX 9216

// swizzled smem: 64B rows (32 bf16), seg' = seg ^ ((row>>1)&3)
#define TILE_B 8192                  // 128 rows * 64B
#define STG   (4 * TILE_B)           // Ah, Al, Bh, Bl per stage = 32768
#define SMEM_TOT (3 * STG)           // 98304 -> 2 CTAs/SM

// ---------------- PTX helpers (sm_80-family, valid on plain sm_103) ---------
__device__ __forceinline__ uint32_t s2u(const void* p) {
    uint32_t a;
    asm("{ .reg .u64 t; cvta.to.shared.u64 t, %1; cvt.u32.u64 %0, t; }" : "=r"(a) : "l"(p));
    return a;
}
__device__ __forceinline__ void ldsm4(uint32_t* r, uint32_t a) {
    asm volatile("ldmatrix.sync.aligned.m8n8.x4.shared.b16 {%0,%1,%2,%3}, [%4];"
        : "=r"(r[0]), "=r"(r[1]), "=r"(r[2]), "=r"(r[3]) : "r"(a));
}
__device__ __forceinline__ void mma16816(float* d, const uint32_t* a, uint32_t b0, uint32_t b1) {
    asm volatile("mma.sync.aligned.m16n8k16.row.col.f32.bf16.bf16.f32 "
        "{%0,%1,%2,%3}, {%4,%5,%6,%7}, {%8,%9}, {%0,%1,%2,%3};"
        : "+f"(d[0]), "+f"(d[1]), "+f"(d[2]), "+f"(d[3])
        : "r"(a[0]), "r"(a[1]), "r"(a[2]), "r"(a[3]), "r"(b0), "r"(b1));
}
__device__ __forceinline__ void cp16(uint32_t s, const void* g) {
    asm volatile("{ .reg .u64 gg; cvta.to.global.u64 gg, %1; "
                 "cp.async.cg.shared.global [%0], [gg], 16; }"
                 :: "r"(s), "l"(g) : "memory");
}
#define CP_COMMIT() asm volatile("cp.async.commit_group;" ::: "memory")
#define CP_WAIT1()  asm volatile("cp.async.wait_group 1;" ::: "memory")
#define CP_WAIT0()  asm volatile("cp.async.wait_group 0;" ::: "memory")

// ---------------- scratch (device globals) ----------------
__device__ __nv_bfloat16 g_x_hi[T_TOK * H_DIM];
__device__ __nv_bfloat16 g_x_lo[T_TOK * H_DIM];
__device__ __nv_bfloat16 g_h_hi[(size_t)MP_MAX * F_DIM];
__device__ __nv_bfloat16 g_h_lo[(size_t)MP_MAX * F_DIM];
__device__ __nv_bfloat16 g_wg_hi[(size_t)N_EXP * F_DIM * H_DIM];
__device__ __nv_bfloat16 g_wg_lo[(size_t)N_EXP * F_DIM * H_DIM];
__device__ __nv_bfloat16 g_wu_hi[(size_t)N_EXP * F_DIM * H_DIM];
__device__ __nv_bfloat16 g_wu_lo[(size_t)N_EXP * F_DIM * H_DIM];
__device__ __nv_bfloat16 g_wd_hi[(size_t)N_EXP * H_DIM * F_DIM];
__device__ __nv_bfloat16 g_wd_lo[(size_t)N_EXP * H_DIM * F_DIM];
__device__ float g_part[(size_t)MP_MAX * H_DIM];     // per-assignment scaled output
__device__ int   g_tok[MP_MAX];
__device__ float g_scale[MP_MAX];
__device__ int   g_rowof[T_TOK * 2];                 // token -> assignment rows
__device__ int   g_te[T_TOK * 2];
__device__ float g_tp[T_TOK * 2];
__device__ int   g_cnt[N_EXP];
__device__ int   g_offp[N_EXP + 1];

// ---------------- kernel 1: rmsnorm + router + bf16 split ----------------
__global__ __launch_bounds__(256)
void k_rms_router(const float* __restrict__ hs,
                  const float* __restrict__ lnw,
                  const float* __restrict__ rw)
{
    int t = blockIdx.x;
    int tid = threadIdx.x;
    int lane = tid & 31, wid = tid >> 5;

    __shared__ float s_x[H_DIM];
    __shared__ float swr[8];
    __shared__ float s_inv;
    __shared__ float sl[8][N_EXP];

    const float4 v = ((const float4*)(hs + (size_t)t * H_DIM))[tid];
    float ss = v.x*v.x + v.y*v.y + v.z*v.z + v.w*v.w;
    #pragma unroll
    for (int o = 16; o; o >>= 1) ss += __shfl_xor_sync(0xffffffffu, ss, o);
    if (lane == 0) swr[wid] = ss;
    __syncthreads();
    if (tid == 0) {
        float s = 0.f;
        #pragma unroll
        for (int i = 0; i < 8; i++) s += swr[i];
        s_inv = rsqrtf(s / (float)H_DIM + EPS_V);
    }
    __syncthreads();
    float inv = s_inv;

    const float4 w = ((const float4*)lnw)[tid];
    float xv[4];
    xv[0] = v.x * inv * w.x;  xv[1] = v.y * inv * w.y;
    xv[2] = v.z * inv * w.z;  xv[3] = v.w * inv * w.w;

    __nv_bfloat16 hi[4], lo[4];
    #pragma unroll
    for (int j = 0; j < 4; j++) {
        s_x[tid * 4 + j] = xv[j];
        hi[j] = __float2bfloat16(xv[j]);
        lo[j] = __float2bfloat16(xv[j] - __bfloat162float(hi[j]));
    }
    ((uint2*)(g_x_hi + (size_t)t * H_DIM))[tid] = *(uint2*)hi;
    ((uint2*)(g_x_lo + (size_t)t * H_DIM))[tid] = *(uint2*)lo;
    __syncthreads();

    {
        const int c = lane & 3, r = lane >> 2;
        const float2* rw2 = (const float2*)rw;
        float2 p = make_float2(0.f, 0.f);
        int ibase = wid * 128 + r;
        #pragma unroll
        for (int k = 0; k < 16; k++) {
            int i = ibase + k * 8;
            float2 w2 = rw2[i * 4 + c];
            float xs = s_x[i];
            p.x += xs * w2.x;
            p.y += xs * w2.y;
        }
        #pragma unroll
        for (int o = 16; o >= 4; o >>= 1) {
            p.x += __shfl_xor_sync(0xffffffffu, p.x, o);
            p.y += __shfl_xor_sync(0xffffffffu, p.y, o);
        }
        if (lane < 4) {
            sl[wid][2 * c]     = p.x;
            sl[wid][2 * c + 1] = p.y;
        }
    }
    __syncthreads();

    if (tid == 0) {
        float l[N_EXP];
        #pragma unroll
        for (int e = 0; e < N_EXP; e++) {
            float s = 0.f;
            #pragma unroll
            for (int w2 = 0; w2 < 8; w2++) s += sl[w2][e];
            l[e] = s;
        }
        float m = l[0];
        #pragma unroll
        for (int e = 1; e < N_EXP; e++) m = fmaxf(m, l[e]);
        float den = 0.f, pr[N_EXP];
        #pragma unroll
        for (int e = 0; e < N_EXP; e++) { pr[e] = expf(l[e] - m); den += pr[e]; }
        float rden = 1.f / den;
        #pragma unroll
        for (int e = 0; e < N_EXP; e++) pr[e] *= rden;

        int i1 = 0;
        #pragma unroll
        for (int e = 1; e < N_EXP; e++) if (pr[e] > pr[i1]) i1 = e;
        int i2 = (i1 == 0) ? 1 : 0;
        #pragma unroll
        for (int e = 0; e < N_EXP; e++) if (e != i1 && pr[e] > pr[i2]) i2 = e;

        g_te[t * 2 + 0] = i1;  g_tp[t * 2 + 0] = pr[i1];
        g_te[t * 2 + 1] = i2;  g_tp[t * 2 + 1] = pr[i2];
        atomicAdd(&g_cnt[i1], 1);
        atomicAdd(&g_cnt[i2], 1);
    }
}

// ---------------- kernel 2: ALL weight transposes + bf16 splits --------------
__global__ __launch_bounds__(256)
void k_tsplit_all(const float* __restrict__ wg,
                  const float* __restrict__ wu,
                  const float* __restrict__ wd)
{
    int z = blockIdx.z;
    const float* src;
    __nv_bfloat16 *dhi, *dlo;
    int R, C, e;
    if (z < 8)       { src = wg; dhi = g_wg_hi; dlo = g_wg_lo; R = H_DIM; C = F_DIM; e = z; }
    else if (z < 16) { src = wu; dhi = g_wu_hi; dlo = g_wu_lo; R = H_DIM; C = F_DIM; e = z - 8; }
    else             { src = wd; dhi = g_wd_hi; dlo = g_wd_lo; R = F_DIM; C = H_DIM; e = z - 16; }

    int c0 = blockIdx.x * 32, r0 = blockIdx.y * 64;
    if (c0 >= C || r0 >= R) return;

    __shared__ float t[64][33];
    const float* s = src + (size_t)e * R * C;
    size_t dbase = (size_t)e * R * C;
    int tx = threadIdx.x, ty = threadIdx.y;
    #pragma unroll
    for (int i = 0; i < 8; i++) {
        int r = ty + i * 8;
        t[r][tx] = s[(size_t)(r0 + r) * C + c0 + tx];
    }
    __syncthreads();
    #pragma unroll
    for (int i = 0; i < 4; i++) {
        int c = ty + i * 8;
        float v0 = t[2 * tx][c];
        float v1 = t[2 * tx + 1][c];
        __nv_bfloat16 h0 = __float2bfloat16(v0);
        __nv_bfloat16 h1 = __float2bfloat16(v1);
        __nv_bfloat16 l0 = __float2bfloat16(v0 - __bfloat162float(h0));
        __nv_bfloat16 l1 = __float2bfloat16(v1 - __bfloat162float(h1));
        uint32_t uh = (uint32_t)__bfloat16_as_ushort(h0) | ((uint32_t)__bfloat16_as_ushort(h1) << 16);
        uint32_t ul = (uint32_t)__bfloat16_as_ushort(l0) | ((uint32_t)__bfloat16_as_ushort(l1) << 16);
        size_t o = dbase + (size_t)(c0 + c) * R + r0 + 2 * tx;
        *(uint32_t*)(dhi + o) = uh;
        *(uint32_t*)(dlo + o) = ul;
    }
}

// ---------------- kernel 3: offsets + scatter (single block) -----------------
__global__ __launch_bounds__(256)
void k_offscatter()
{
    __shared__ int s_fill[N_EXP];
    int tid = threadIdx.x;
    if (tid == 0) {
        int acc = 0;
        #pragma unroll
        for (int e = 0; e < N_EXP; e++) {
            g_offp[e]  = acc;
            s_fill[e]  = acc;
            acc += (g_cnt[e] + 127) & ~127;
        }
        g_offp[N_EXP] = acc;
    }
    __syncthreads();
    for (int t = tid; t < T_TOK; t += 256) {
        #pragma unroll
        for (int k = 0; k < 2; k++) {
            int e = g_te[t * 2 + k];
            int r = atomicAdd(&s_fill[e], 1);
            g_tok[r]     = t;
            g_scale[r]   = g_tp[t * 2 + k];
            g_rowof[t * 2 + k] = r;
        }
    }
}

// ======================= GEMM1: gate/up + SiLU (mma.sync) ====================
// Exact R8 mainloop (proven 824us / tensor 59%). FROZEN.
__global__ __launch_bounds__(256, 2)
void k_gemm1_mma()
{
    extern __shared__ char smem[];
    const uint32_t sb = s2u(smem);
    const int tid = threadIdx.x, lane = tid & 31, wid = tid >> 5;

    const int Mp = g_offp[N_EXP];
    const int m0 = blockIdx.y * 128;
    if (m0 >= Mp) return;
    const int n0 = blockIdx.x * 64;
    int e = 0;
    #pragma unroll
    for (int i = 1; i < N_EXP; i++) if (m0 >= g_offp[i]) e = i;

    __shared__ int s_tok[128];
    if (tid < 128) {
        int tok = g_tok[m0 + tid];
        s_tok[tid] = (tok >= 0) ? tok : 0;
    }
    __syncthreads();

    const int lr = tid >> 2;
    const int ls = tid & 3;
    const int NC = H_DIM / 32;

    auto load_chunk = [&](int c, int stg) {
        int kc = c * 32;
        uint32_t base = sb + stg * STG;
        uint32_t ah = base, al = base + TILE_B, bh = base + 2 * TILE_B, bl = base + 3 * TILE_B;
        #pragma unroll
        for (int i = 0; i < 2; i++) {
            int row = lr + 64 * i;
            uint32_t so = row * 64 + ((ls ^ ((row >> 1) & 3)) << 4);
            size_t go = (size_t)s_tok[row] * H_DIM + kc + ls * 8;
            cp16(ah + so, g_x_hi + go);
            cp16(al + so, g_x_lo + go);
        }
        #pragma unroll
        for (int i = 0; i < 2; i++) {
            int rn = lr + 64 * i;
            uint32_t so = rn * 64 + ((ls ^ ((rn >> 1) & 3)) << 4);
            int col = n0 + (rn >> 1);
            size_t go = ((size_t)e * F_DIM + col) * H_DIM + kc + ls * 8;
            const __nv_bfloat16* Wh = (rn & 1) ? g_wu_hi : g_wg_hi;
            const __nv_bfloat16* Wl = (rn & 1) ? g_wu_lo : g_wg_lo;
            cp16(bh + so, Wh + go);
            cp16(bl + so, Wl + go);
        }
    };

    load_chunk(0, 0); CP_COMMIT();
    load_chunk(1, 1); CP_COMMIT();

    const int warp_m = (wid & 1) * 64;
    const int warp_n = (wid >> 1) * 32;

    float acc[4][4][4];
    #pragma unroll
    for (int i = 0; i < 4; i++)
        #pragma unroll
        for (int j = 0; j < 4; j++)
            #pragma unroll
            for (int k = 0; k < 4; k++) acc[i][j][k] = 0.f;

    const int quad = lane >> 3, l7 = lane & 7;
    const int a_row = warp_m + (quad & 1) * 8 + l7;
    const int b_row = warp_n + (quad & 1) * 8 + l7;
    const int kq = quad >> 1;
    const int a_swz = (a_row >> 1) & 3;
    const int b_swz = (b_row >> 1) & 3;

    for (int c = 0; c < NC; c++) {
        if (c + 1 < NC) { CP_WAIT1(); } else { CP_WAIT0(); }
        __syncthreads();
        if (c + 2 < NC) { load_chunk(c + 2, (c + 2) % 3); CP_COMMIT(); }

        uint32_t base = sb + (c % 3) * STG;
        uint32_t ah = base, al = base + TILE_B, bh = base + 2 * TILE_B, bl = base + 3 * TILE_B;
        #pragma unroll
        for (int ks = 0; ks < 2; ks++) {
            const uint32_t a_seg = (uint32_t)(((ks * 2 + kq) ^ a_swz) << 4);
            const uint32_t b_seg = (uint32_t)(((ks * 2 + kq) ^ b_swz) << 4);
            uint32_t aH[4][4], aL[4][4], bH[2][4], bL[2][4];
            #pragma unroll
            for (int mi = 0; mi < 4; mi++) {
                uint32_t ro = (a_row + mi * 16) * 64 + a_seg;
                ldsm4(aH[mi], ah + ro);
                ldsm4(aL[mi], al + ro);
            }
            #pragma unroll
            for (int bj = 0; bj < 2; bj++) {
                uint32_t ro = (b_row + bj * 16) * 64 + b_seg;
                ldsm4(bH[bj], bh + ro);
                ldsm4(bL[bj], bl + ro);
            }
            #pragma unroll
            for (int mi = 0; mi < 4; mi++)
                #pragma unroll
                for (int nj = 0; nj < 4; nj++) {
                    const uint32_t* fh = bH[nj >> 1];
                    const uint32_t* fl = bL[nj >> 1];
                    int s = nj & 1;
                    mma16816(acc[mi][nj], aH[mi], fh[s], fh[s + 2]);
                    mma16816(acc[mi][nj], aH[mi], fl[s], fl[s + 2]);
                    mma16816(acc[mi][nj], aL[mi], fh[s], fh[s + 2]);
                }
        }
    }

    const int rbase = m0 + warp_m + (lane >> 2);
    const int cbase = n0 + (warp_n >> 1) + (lane & 3);
    #pragma unroll
    for (int mi = 0; mi < 4; mi++) {
        size_t r0 = (size_t)(rbase + mi * 16) * F_DIM;
        size_t r1 = r0 + 8 * F_DIM;
        #pragma unroll
        for (int nj = 0; nj < 4; nj++) {
            int L = cbase + nj * 4;
            float g0 = acc[mi][nj][0], u0 = acc[mi][nj][1];
            float g1 = acc[mi][nj][2], u1 = acc[mi][nj][3];
            float h0 = (g0 / (1.f + expf(-g0))) * u0;
            float h1 = (g1 / (1.f + expf(-g1))) * u1;
            __nv_bfloat16 h0h = __float2bfloat16(h0);
            __nv_bfloat16 h1h = __float2bfloat16(h1);
            g_h_hi[r0 + L] = h0h;
            g_h_hi[r1 + L] = h1h;
            g_h_lo[r0 + L] = __float2bfloat16(h0 - __bfloat162float(h0h));
            g_h_lo[r1 + L] = __float2bfloat16(h1 - __bfloat162float(h1h));
        }
    }
}

// ======================= GEMM2: down proj -> g_part (STG, no atomics) ========
__global__ __launch_bounds__(256, 2)
void k_gemm2_mma()
{
    extern __shared__ char smem[];
    const uint32_t sb = s2u(smem);
    const int tid = threadIdx.x, lane = tid & 31, wid = tid >> 5;

    const int Mp = g_offp[N_EXP];
    const int m0 = blockIdx.y * 128;
    if (m0 >= Mp) return;
    const int n0 = blockIdx.x * 128;
    int e = 0;
    #pragma unroll
    for (int i = 1; i < N_EXP; i++) if (m0 >= g_offp[i]) e = i;

    const int lr = tid >> 2;
    const int ls = tid & 3;
    const int NC = F_DIM / 32;

    auto load_chunk = [&](int c, int stg) {
        int kc = c * 32;
        uint32_t base = sb + stg * STG;
        uint32_t ah = base, al = base + TILE_B, bh = base + 2 * TILE_B, bl = base + 3 * TILE_B;
        #pragma unroll
        for (int i = 0; i < 2; i++) {
            int row = lr + 64 * i;
            uint32_t so = row * 64 + ((ls ^ ((row >> 1) & 3)) << 4);
            size_t go = (size_t)(m0 + row) * F_DIM + kc + ls * 8;
            cp16(ah + so, g_h_hi + go);
            cp16(al + so, g_h_lo + go);
        }
        #pragma unroll
        for (int i = 0; i < 2; i++) {
            int rn = lr + 64 * i;
            uint32_t so = rn * 64 + ((ls ^ ((rn >> 1) & 3)) << 4);
            size_t go = ((size_t)e * H_DIM + n0 + rn) * F_DIM + kc + ls * 8;
            cp16(bh + so, g_wd_hi + go);
            cp16(bl + so, g_wd_lo + go);
        }
    };

    load_chunk(0, 0); CP_COMMIT();
    load_chunk(1, 1); CP_COMMIT();

    const int warp_m = (wid & 1) * 64;
    const int warp_n = (wid >> 1) * 32;

    float acc[4][4][4];
    #pragma unroll
    for (int i = 0; i < 4; i++)
        #pragma unroll
        for (int j = 0; j < 4; j++)
            #pragma unroll
            for (int k = 0; k < 4; k++) acc[i][j][k] = 0.f;

    const int quad = lane >> 3, l7 = lane & 7;
    const int a_row = warp_m + (quad & 1) * 8 + l7;
    const int b_row = warp_n + (quad & 1) * 8 + l7;
    const int kq = quad >> 1;
    const int a_swz = (a_row >> 1) & 3;
    const int b_swz = (b_row >> 1) & 3;

    for (int c = 0; c < NC; c++) {
        if (c + 1 < NC) { CP_WAIT1(); } else { CP_WAIT0(); }
        __syncthreads();
        if (c + 2 < NC) { load_chunk(c + 2, (c + 2) % 3); CP_COMMIT(); }

        uint32_t base = sb + (c % 3) * STG;
        uint32_t ah = base, al = base + TILE_B, bh = base + 2 * TILE_B, bl = base + 3 * TILE_B;
        #pragma unroll
        for (int ks = 0; ks < 2; ks++) {
            const uint32_t a_seg = (uint32_t)(((ks * 2 + kq) ^ a_swz) << 4);
            const uint32_t b_seg = (uint32_t)(((ks * 2 + kq) ^ b_swz) << 4);
            uint32_t aH[4][4], aL[4][4], bH[2][4], bL[2][4];
            #pragma unroll
            for (int mi = 0; mi < 4; mi++) {
                uint32_t ro = (a_row + mi * 16) * 64 + a_seg;
                ldsm4(aH[mi], ah + ro);
                ldsm4(aL[mi], al + ro);
            }
            #pragma unroll
            for (int bj = 0; bj < 2; bj++) {
                uint32_t ro = (b_row + bj * 16) * 64 + b_seg;
                ldsm4(bH[bj], bh + ro);
                ldsm4(bL[bj], bl + ro);
            }
            #pragma unroll
            for (int mi = 0; mi < 4; mi++)
                #pragma unroll
                for (int nj = 0; nj < 4; nj++) {
                    const uint32_t* fh = bH[nj >> 1];
                    const uint32_t* fl = bL[nj >> 1];
                    int s = nj & 1;
                    mma16816(acc[mi][nj], aH[mi], fh[s], fh[s + 2]);
                    mma16816(acc[mi][nj], aH[mi], fl[s], fl[s + 2]);
                    mma16816(acc[mi][nj], aL[mi], fh[s], fh[s + 2]);
                }
        }
    }

    // epilogue: scale and STORE to per-assignment buffer (exclusive rows)
    const int rbase = m0 + warp_m + (lane >> 2);
    const int cbase = n0 + warp_n + (lane & 3) * 2;
    #pragma unroll
    for (int mi = 0; mi < 4; mi++) {
        int r0 = rbase + mi * 16;
        int r1 = r0 + 8;
        float sc0 = g_scale[r0];
        float sc1 = g_scale[r1];
        float* p0 = g_part + (size_t)r0 * H_DIM;
        float* p1 = g_part + (size_t)r1 * H_DIM;
        #pragma unroll
        for (int nj = 0; nj < 4; nj++) {
            int col = cbase + nj * 8;
            float2 v0 = make_float2(acc[mi][nj][0] * sc0, acc[mi][nj][1] * sc0);
            float2 v1 = make_float2(acc[mi][nj][2] * sc1, acc[mi][nj][3] * sc1);
            *(float2*)(p0 + col) = v0;
            *(float2*)(p1 + col) = v1;
        }
    }
}

// ---------------- kernel 6: combine the two expert contributions -------------
__global__ __launch_bounds__(256)
void k_combine(float* __restrict__ out)
{
    int t = blockIdx.x;
    int tid = threadIdx.x;
    int r0 = g_rowof[t * 2 + 0];
    int r1 = g_rowof[t * 2 + 1];
    float4 a = ((const float4*)(g_part + (size_t)r0 * H_DIM))[tid];
    float4 b = ((const float4*)(g_part + (size_t)r1 * H_DIM))[tid];
    float4 o;
    o.x = a.x + b.x;  o.y = a.y + b.y;
    o.z = a.z + b.z;  o.w = a.w + b.w;
    ((float4*)(out + (size_t)t * H_DIM))[tid] = o;
}

// ---------------- launch ----------------
extern "C" void kernel_launch(void* const* d_in, const int* in_sizes, int n_in,
                              void* d_out, int out_size)
{
    const float* hs  = (const float*)d_in[0];
    const float* lnw = (const float*)d_in[1];
    const float* rw  = (const float*)d_in[2];
    const float* wg  = (const float*)d_in[3];
    const float* wu  = (const float*)d_in[4];
    const float* wd  = (const float*)d_in[5];
    float* out = (float*)d_out;

    cudaFuncSetAttribute(k_gemm1_mma, cudaFuncAttributeMaxDynamicSharedMemorySize, SMEM_TOT);
    cudaFuncSetAttribute(k_gemm2_mma, cudaFuncAttributeMaxDynamicSharedMemorySize, SMEM_TOT);

    void *p_cnt = nullptr, *p_tok = nullptr;
    cudaGetSymbolAddress(&p_cnt, g_cnt);
    cudaGetSymbolAddress(&p_tok, g_tok);

    cudaMemsetAsync(p_cnt, 0, N_EXP * sizeof(int));
    cudaMemsetAsync(p_tok, 0xFF, MP_MAX * sizeof(int));

    // fork: weight prep on side stream, concurrent with activation chain
    cudaStream_t s2;
    cudaStreamCreateWithFlags(&s2, cudaStreamNonBlocking);
    cudaEvent_t eFork, eJoin;
    cudaEventCreateWithFlags(&eFork, cudaEventDisableTiming);
    cudaEventCreateWithFlags(&eJoin, cudaEventDisableTiming);

    cudaEventRecord(eFork, 0);
    cudaStreamWaitEvent(s2, eFork, 0);

    dim3 tb(32, 8);
    dim3 tg(F_DIM / 32, F_DIM / 64, 24);
    k_tsplit_all<<<tg, tb, 0, s2>>>(wg, wu, wd);     // launch 1 (side stream)
    cudaEventRecord(eJoin, s2);

    k_rms_router<<<T_TOK, 256>>>(hs, lnw, rw);        // launch 2 (main)
    k_offscatter<<<1, 256>>>();                       // launch 3 (main)

    cudaStreamWaitEvent(0, eJoin, 0);                 // join before GEMMs

    // launch 4 (ncu capture slot): GEMM1
    dim3 g1(F_DIM / 64, MP_MAX / 128);   // (44, 72)
    k_gemm1_mma<<<g1, 256, SMEM_TOT>>>();

    dim3 g2(H_DIM / 128, MP_MAX / 128);  // (8, 72)
    k_gemm2_mma<<<g2, 256, SMEM_TOT>>>();

    k_combine<<<T_TOK, 256>>>(out);
}

// round 13
// speedup vs baseline: 1.0689x; 1.0195x over previous
#include <cuda_runtime.h>
#include <cuda_bf16.h>
#include <math.h>
#include <stdint.h>

#define T_TOK 4096
#define H_DIM 1024
#define F_DIM 2816
#define N_EXP 8
#define EPS_V 1e-5f
#define MP_MAX 9216

// swizzled smem: 64B rows (32 bf16), seg' = seg ^ ((row>>1)&3)
#define TILE_B 8192                  // 128 rows * 64B
#define STG   (4 * TILE_B)           // Ah, Al, Bh, Bl per stage = 32768
#define SMEM_TOT (3 * STG)           // 98304 -> 2 CTAs/SM
#define PITCH_E 72                   // epilogue staging pitch (bf16 elems)

// ---------------- PTX helpers (sm_80-family, valid on plain sm_103) ---------
__device__ __forceinline__ uint32_t s2u(const void* p) {
    uint32_t a;
    asm("{ .reg .u64 t; cvta.to.shared.u64 t, %1; cvt.u32.u64 %0, t; }" : "=r"(a) : "l"(p));
    return a;
}
__device__ __forceinline__ void ldsm4(uint32_t* r, uint32_t a) {
    asm volatile("ldmatrix.sync.aligned.m8n8.x4.shared.b16 {%0,%1,%2,%3}, [%4];"
        : "=r"(r[0]), "=r"(r[1]), "=r"(r[2]), "=r"(r[3]) : "r"(a));
}
__device__ __forceinline__ void mma16816(float* d, const uint32_t* a, uint32_t b0, uint32_t b1) {
    asm volatile("mma.sync.aligned.m16n8k16.row.col.f32.bf16.bf16.f32 "
        "{%0,%1,%2,%3}, {%4,%5,%6,%7}, {%8,%9}, {%0,%1,%2,%3};"
        : "+f"(d[0]), "+f"(d[1]), "+f"(d[2]), "+f"(d[3])
        : "r"(a[0]), "r"(a[1]), "r"(a[2]), "r"(a[3]), "r"(b0), "r"(b1));
}
__device__ __forceinline__ void cp16(uint32_t s, const void* g) {
    asm volatile("{ .reg .u64 gg; cvta.to.global.u64 gg, %1; "
                 "cp.async.cg.shared.global [%0], [gg], 16; }"
                 :: "r"(s), "l"(g) : "memory");
}
#define CP_COMMIT() asm volatile("cp.async.commit_group;" ::: "memory")
#define CP_WAIT1()  asm volatile("cp.async.wait_group 1;" ::: "memory")
#define CP_WAIT0()  asm volatile("cp.async.wait_group 0;" ::: "memory")

// ---------------- scratch (device globals) ----------------
__device__ __nv_bfloat16 g_x_hi[T_TOK * H_DIM];
__device__ __nv_bfloat16 g_x_lo[T_TOK * H_DIM];
__device__ __nv_bfloat16 g_h_hi[(size_t)MP_MAX * F_DIM];
__device__ __nv_bfloat16 g_h_lo[(size_t)MP_MAX * F_DIM];
__device__ __nv_bfloat16 g_wg_hi[(size_t)N_EXP * F_DIM * H_DIM];
__device__ __nv_bfloat16 g_wg_lo[(size_t)N_EXP * F_DIM * H_DIM];
__device__ __nv_bfloat16 g_wu_hi[(size_t)N_EXP * F_DIM * H_DIM];
__device__ __nv_bfloat16 g_wu_lo[(size_t)N_EXP * F_DIM * H_DIM];
__device__ __nv_bfloat16 g_wd_hi[(size_t)N_EXP * H_DIM * F_DIM];
__device__ __nv_bfloat16 g_wd_lo[(size_t)N_EXP * H_DIM * F_DIM];
__device__ float g_part[(size_t)MP_MAX * H_DIM];     // per-assignment scaled output
__device__ int   g_tok[MP_MAX];
__device__ float g_scale[MP_MAX];
__device__ int   g_rowof[T_TOK * 2];                 // token -> assignment rows
__device__ int   g_te[T_TOK * 2];
__device__ float g_tp[T_TOK * 2];
__device__ int   g_cnt[N_EXP];
__device__ int   g_offp[N_EXP + 1];

// ---------------- kernel 1: rmsnorm + router + bf16 split ----------------
__global__ __launch_bounds__(256)
void k_rms_router(const float* __restrict__ hs,
                  const float* __restrict__ lnw,
                  const float* __restrict__ rw)
{
    int t = blockIdx.x;
    int tid = threadIdx.x;
    int lane = tid & 31, wid = tid >> 5;

    __shared__ float s_x[H_DIM];
    __shared__ float swr[8];
    __shared__ float s_inv;
    __shared__ float sl[8][N_EXP];

    const float4 v = ((const float4*)(hs + (size_t)t * H_DIM))[tid];
    float ss = v.x*v.x + v.y*v.y + v.z*v.z + v.w*v.w;
    #pragma unroll
    for (int o = 16; o; o >>= 1) ss += __shfl_xor_sync(0xffffffffu, ss, o);
    if (lane == 0) swr[wid] = ss;
    __syncthreads();
    if (tid == 0) {
        float s = 0.f;
        #pragma unroll
        for (int i = 0; i < 8; i++) s += swr[i];
        s_inv = rsqrtf(s / (float)H_DIM + EPS_V);
    }
    __syncthreads();
    float inv = s_inv;

    const float4 w = ((const float4*)lnw)[tid];
    float xv[4];
    xv[0] = v.x * inv * w.x;  xv[1] = v.y * inv * w.y;
    xv[2] = v.z * inv * w.z;  xv[3] = v.w * inv * w.w;

    __nv_bfloat16 hi[4], lo[4];
    #pragma unroll
    for (int j = 0; j < 4; j++) {
        s_x[tid * 4 + j] = xv[j];
        hi[j] = __float2bfloat16(xv[j]);
        lo[j] = __float2bfloat16(xv[j] - __bfloat162float(hi[j]));
    }
    ((uint2*)(g_x_hi + (size_t)t * H_DIM))[tid] = *(uint2*)hi;
    ((uint2*)(g_x_lo + (size_t)t * H_DIM))[tid] = *(uint2*)lo;
    __syncthreads();

    {
        const int c = lane & 3, r = lane >> 2;
        const float2* rw2 = (const float2*)rw;
        float2 p = make_float2(0.f, 0.f);
        int ibase = wid * 128 + r;
        #pragma unroll
        for (int k = 0; k < 16; k++) {
            int i = ibase + k * 8;
            float2 w2 = rw2[i * 4 + c];
            float xs = s_x[i];
            p.x += xs * w2.x;
            p.y += xs * w2.y;
        }
        #pragma unroll
        for (int o = 16; o >= 4; o >>= 1) {
            p.x += __shfl_xor_sync(0xffffffffu, p.x, o);
            p.y += __shfl_xor_sync(0xffffffffu, p.y, o);
        }
        if (lane < 4) {
            sl[wid][2 * c]     = p.x;
            sl[wid][2 * c + 1] = p.y;
        }
    }
    __syncthreads();

    if (tid == 0) {
        float l[N_EXP];
        #pragma unroll
        for (int e = 0; e < N_EXP; e++) {
            float s = 0.f;
            #pragma unroll
            for (int w2 = 0; w2 < 8; w2++) s += sl[w2][e];
            l[e] = s;
        }
        float m = l[0];
        #pragma unroll
        for (int e = 1; e < N_EXP; e++) m = fmaxf(m, l[e]);
        float den = 0.f, pr[N_EXP];
        #pragma unroll
        for (int e = 0; e < N_EXP; e++) { pr[e] = expf(l[e] - m); den += pr[e]; }
        float rden = 1.f / den;
        #pragma unroll
        for (int e = 0; e < N_EXP; e++) pr[e] *= rden;

        int i1 = 0;
        #pragma unroll
        for (int e = 1; e < N_EXP; e++) if (pr[e] > pr[i1]) i1 = e;
        int i2 = (i1 == 0) ? 1 : 0;
        #pragma unroll
        for (int e = 0; e < N_EXP; e++) if (e != i1 && pr[e] > pr[i2]) i2 = e;

        g_te[t * 2 + 0] = i1;  g_tp[t * 2 + 0] = pr[i1];
        g_te[t * 2 + 1] = i2;  g_tp[t * 2 + 1] = pr[i2];
        atomicAdd(&g_cnt[i1], 1);
        atomicAdd(&g_cnt[i2], 1);
    }
}

// ---------------- kernel 2: ALL weight transposes + bf16 splits --------------
__global__ __launch_bounds__(256)
void k_tsplit_all(const float* __restrict__ wg,
                  const float* __restrict__ wu,
                  const float* __restrict__ wd)
{
    int z = blockIdx.z;
    const float* src;
    __nv_bfloat16 *dhi, *dlo;
    int R, C, e;
    if (z < 8)       { src = wg; dhi = g_wg_hi; dlo = g_wg_lo; R = H_DIM; C = F_DIM; e = z; }
    else if (z < 16) { src = wu; dhi = g_wu_hi; dlo = g_wu_lo; R = H_DIM; C = F_DIM; e = z - 8; }
    else             { src = wd; dhi = g_wd_hi; dlo = g_wd_lo; R = F_DIM; C = H_DIM; e = z - 16; }

    int c0 = blockIdx.x * 32, r0 = blockIdx.y * 64;
    if (c0 >= C || r0 >= R) return;

    __shared__ float t[64][33];
    const float* s = src + (size_t)e * R * C;
    size_t dbase = (size_t)e * R * C;
    int tx = threadIdx.x, ty = threadIdx.y;
    #pragma unroll
    for (int i = 0; i < 8; i++) {
        int r = ty + i * 8;
        t[r][tx] = s[(size_t)(r0 + r) * C + c0 + tx];
    }
    __syncthreads();
    #pragma unroll
    for (int i = 0; i < 4; i++) {
        int c = ty + i * 8;
        float v0 = t[2 * tx][c];
        float v1 = t[2 * tx + 1][c];
        __nv_bfloat16 h0 = __float2bfloat16(v0);
        __nv_bfloat16 h1 = __float2bfloat16(v1);
        __nv_bfloat16 l0 = __float2bfloat16(v0 - __bfloat162float(h0));
        __nv_bfloat16 l1 = __float2bfloat16(v1 - __bfloat162float(h1));
        uint32_t uh = (uint32_t)__bfloat16_as_ushort(h0) | ((uint32_t)__bfloat16_as_ushort(h1) << 16);
        uint32_t ul = (uint32_t)__bfloat16_as_ushort(l0) | ((uint32_t)__bfloat16_as_ushort(l1) << 16);
        size_t o = dbase + (size_t)(c0 + c) * R + r0 + 2 * tx;
        *(uint32_t*)(dhi + o) = uh;
        *(uint32_t*)(dlo + o) = ul;
    }
}

// ---------------- kernel 3: offsets + scatter (single block) -----------------
__global__ __launch_bounds__(256)
void k_offscatter()
{
    __shared__ int s_fill[N_EXP];
    int tid = threadIdx.x;
    if (tid == 0) {
        int acc = 0;
        #pragma unroll
        for (int e = 0; e < N_EXP; e++) {
            g_offp[e]  = acc;
            s_fill[e]  = acc;
            acc += (g_cnt[e] + 127) & ~127;
        }
        g_offp[N_EXP] = acc;
    }
    __syncthreads();
    for (int t = tid; t < T_TOK; t += 256) {
        #pragma unroll
        for (int k = 0; k < 2; k++) {
            int e = g_te[t * 2 + k];
            int r = atomicAdd(&s_fill[e], 1);
            g_tok[r]     = t;
            g_scale[r]   = g_tp[t * 2 + k];
            g_rowof[t * 2 + k] = r;
        }
    }
}

// ======================= GEMM1: gate/up + SiLU (mma.sync) ====================
// Frozen R8 mainloop; NEW staged coalesced epilogue (smem -> uint4 stores).
__global__ __launch_bounds__(256, 2)
void k_gemm1_mma()
{
    extern __shared__ char smem[];
    const uint32_t sb = s2u(smem);
    const int tid = threadIdx.x, lane = tid & 31, wid = tid >> 5;

    const int Mp = g_offp[N_EXP];
    const int m0 = blockIdx.y * 128;
    if (m0 >= Mp) return;
    const int n0 = blockIdx.x * 64;
    int e = 0;
    #pragma unroll
    for (int i = 1; i < N_EXP; i++) if (m0 >= g_offp[i]) e = i;

    __shared__ int s_tok[128];
    if (tid < 128) {
        int tok = g_tok[m0 + tid];
        s_tok[tid] = (tok >= 0) ? tok : 0;
    }
    __syncthreads();

    const int lr = tid >> 2;
    const int ls = tid & 3;
    const int NC = H_DIM / 32;

    auto load_chunk = [&](int c, int stg) {
        int kc = c * 32;
        uint32_t base = sb + stg * STG;
        uint32_t ah = base, al = base + TILE_B, bh = base + 2 * TILE_B, bl = base + 3 * TILE_B;
        #pragma unroll
        for (int i = 0; i < 2; i++) {
            int row = lr + 64 * i;
            uint32_t so = row * 64 + ((ls ^ ((row >> 1) & 3)) << 4);
            size_t go = (size_t)s_tok[row] * H_DIM + kc + ls * 8;
            cp16(ah + so, g_x_hi + go);
            cp16(al + so, g_x_lo + go);
        }
        #pragma unroll
        for (int i = 0; i < 2; i++) {
            int rn = lr + 64 * i;
            uint32_t so = rn * 64 + ((ls ^ ((rn >> 1) & 3)) << 4);
            int col = n0 + (rn >> 1);
            size_t go = ((size_t)e * F_DIM + col) * H_DIM + kc + ls * 8;
            const __nv_bfloat16* Wh = (rn & 1) ? g_wu_hi : g_wg_hi;
            const __nv_bfloat16* Wl = (rn & 1) ? g_wu_lo : g_wg_lo;
            cp16(bh + so, Wh + go);
            cp16(bl + so, Wl + go);
        }
    };

    load_chunk(0, 0); CP_COMMIT();
    load_chunk(1, 1); CP_COMMIT();

    const int warp_m = (wid & 1) * 64;
    const int warp_n = (wid >> 1) * 32;

    float acc[4][4][4];
    #pragma unroll
    for (int i = 0; i < 4; i++)
        #pragma unroll
        for (int j = 0; j < 4; j++)
            #pragma unroll
            for (int k = 0; k < 4; k++) acc[i][j][k] = 0.f;

    const int quad = lane >> 3, l7 = lane & 7;
    const int a_row = warp_m + (quad & 1) * 8 + l7;
    const int b_row = warp_n + (quad & 1) * 8 + l7;
    const int kq = quad >> 1;
    const int a_swz = (a_row >> 1) & 3;
    const int b_swz = (b_row >> 1) & 3;

    for (int c = 0; c < NC; c++) {
        if (c + 1 < NC) { CP_WAIT1(); } else { CP_WAIT0(); }
        __syncthreads();
        if (c + 2 < NC) { load_chunk(c + 2, (c + 2) % 3); CP_COMMIT(); }

        uint32_t base = sb + (c % 3) * STG;
        uint32_t ah = base, al = base + TILE_B, bh = base + 2 * TILE_B, bl = base + 3 * TILE_B;
        #pragma unroll
        for (int ks = 0; ks < 2; ks++) {
            const uint32_t a_seg = (uint32_t)(((ks * 2 + kq) ^ a_swz) << 4);
            const uint32_t b_seg = (uint32_t)(((ks * 2 + kq) ^ b_swz) << 4);
            uint32_t aH[4][4], aL[4][4], bH[2][4], bL[2][4];
            #pragma unroll
            for (int mi = 0; mi < 4; mi++) {
                uint32_t ro = (a_row + mi * 16) * 64 + a_seg;
                ldsm4(aH[mi], ah + ro);
                ldsm4(aL[mi], al + ro);
            }
            #pragma unroll
            for (int bj = 0; bj < 2; bj++) {
                uint32_t ro = (b_row + bj * 16) * 64 + b_seg;
                ldsm4(bH[bj], bh + ro);
                ldsm4(bL[bj], bl + ro);
            }
            #pragma unroll
            for (int mi = 0; mi < 4; mi++)
                #pragma unroll
                for (int nj = 0; nj < 4; nj++) {
                    const uint32_t* fh = bH[nj >> 1];
                    const uint32_t* fl = bL[nj >> 1];
                    int s = nj & 1;
                    mma16816(acc[mi][nj], aH[mi], fh[s], fh[s + 2]);
                    mma16816(acc[mi][nj], aH[mi], fl[s], fl[s + 2]);
                    mma16816(acc[mi][nj], aL[mi], fh[s], fh[s + 2]);
                }
        }
    }

    // ---- staged epilogue: silu(g)*u -> smem staging -> coalesced stores ----
    __syncthreads();   // all warps done reading pipeline smem
    __nv_bfloat16* s_hi = (__nv_bfloat16*)smem;                         // [128][PITCH_E]
    __nv_bfloat16* s_lo = (__nv_bfloat16*)(smem + 128 * PITCH_E * 2);
    const int r_l = warp_m + (lane >> 2);
    const int c_l = (warp_n >> 1) + (lane & 3);
    #pragma unroll
    for (int mi = 0; mi < 4; mi++) {
        int row0 = r_l + mi * 16;
        int row1 = row0 + 8;
        #pragma unroll
        for (int nj = 0; nj < 4; nj++) {
            int cc = c_l + nj * 4;
            float g0 = acc[mi][nj][0], u0 = acc[mi][nj][1];
            float g1 = acc[mi][nj][2], u1 = acc[mi][nj][3];
            float h0 = (g0 / (1.f + expf(-g0))) * u0;
            float h1 = (g1 / (1.f + expf(-g1))) * u1;
            __nv_bfloat16 h0h = __float2bfloat16(h0);
            __nv_bfloat16 h1h = __float2bfloat16(h1);
            s_hi[row0 * PITCH_E + cc] = h0h;
            s_hi[row1 * PITCH_E + cc] = h1h;
            s_lo[row0 * PITCH_E + cc] = __float2bfloat16(h0 - __bfloat162float(h0h));
            s_lo[row1 * PITCH_E + cc] = __float2bfloat16(h1 - __bfloat162float(h1h));
        }
    }
    __syncthreads();
    {
        const int row  = tid >> 1;           // 0..127
        const int half = tid & 1;            // 32-col half
        size_t gbase = (size_t)(m0 + row) * F_DIM + n0 + half * 32;
        const uint4* src_h = (const uint4*)(s_hi + row * PITCH_E + half * 32);
        const uint4* src_l = (const uint4*)(s_lo + row * PITCH_E + half * 32);
        uint4* dst_h = (uint4*)(g_h_hi + gbase);
        uint4* dst_l = (uint4*)(g_h_lo + gbase);
        #pragma unroll
        for (int i = 0; i < 4; i++) dst_h[i] = src_h[i];
        #pragma unroll
        for (int i = 0; i < 4; i++) dst_l[i] = src_l[i];
    }
}

// ======================= GEMM2: down proj -> g_part (STG, no atomics) ========
__global__ __launch_bounds__(256, 2)
void k_gemm2_mma()
{
    extern __shared__ char smem[];
    const uint32_t sb = s2u(smem);
    const int tid = threadIdx.x, lane = tid & 31, wid = tid >> 5;

    const int Mp = g_offp[N_EXP];
    const int m0 = blockIdx.y * 128;
    if (m0 >= Mp) return;
    const int n0 = blockIdx.x * 128;
    int e = 0;
    #pragma unroll
    for (int i = 1; i < N_EXP; i++) if (m0 >= g_offp[i]) e = i;

    const int lr = tid >> 2;
    const int ls = tid & 3;
    const int NC = F_DIM / 32;

    auto load_chunk = [&](int c, int stg) {
        int kc = c * 32;
        uint32_t base = sb + stg * STG;
        uint32_t ah = base, al = base + TILE_B, bh = base + 2 * TILE_B, bl = base + 3 * TILE_B;
        #pragma unroll
        for (int i = 0; i < 2; i++) {
            int row = lr + 64 * i;
            uint32_t so = row * 64 + ((ls ^ ((row >> 1) & 3)) << 4);
            size_t go = (size_t)(m0 + row) * F_DIM + kc + ls * 8;
            cp16(ah + so, g_h_hi + go);
            cp16(al + so, g_h_lo + go);
        }
        #pragma unroll
        for (int i = 0; i < 2; i++) {
            int rn = lr + 64 * i;
            uint32_t so = rn * 64 + ((ls ^ ((rn >> 1) & 3)) << 4);
            size_t go = ((size_t)e * H_DIM + n0 + rn) * F_DIM + kc + ls * 8;
            cp16(bh + so, g_wd_hi + go);
            cp16(bl + so, g_wd_lo + go);
        }
    };

    load_chunk(0, 0); CP_COMMIT();
    load_chunk(1, 1); CP_COMMIT();

    const int warp_m = (wid & 1) * 64;
    const int warp_n = (wid >> 1) * 32;

    float acc[4][4][4];
    #pragma unroll
    for (int i = 0; i < 4; i++)
        #pragma unroll
        for (int j = 0; j < 4; j++)
            #pragma unroll
            for (int k = 0; k < 4; k++) acc[i][j][k] = 0.f;

    const int quad = lane >> 3, l7 = lane & 7;
    const int a_row = warp_m + (quad & 1) * 8 + l7;
    const int b_row = warp_n + (quad & 1) * 8 + l7;
    const int kq = quad >> 1;
    const int a_swz = (a_row >> 1) & 3;
    const int b_swz = (b_row >> 1) & 3;

    for (int c = 0; c < NC; c++) {
        if (c + 1 < NC) { CP_WAIT1(); } else { CP_WAIT0(); }
        __syncthreads();
        if (c + 2 < NC) { load_chunk(c + 2, (c + 2) % 3); CP_COMMIT(); }

        uint32_t base = sb + (c % 3) * STG;
        uint32_t ah = base, al = base + TILE_B, bh = base + 2 * TILE_B, bl = base + 3 * TILE_B;
        #pragma unroll
        for (int ks = 0; ks < 2; ks++) {
            const uint32_t a_seg = (uint32_t)(((ks * 2 + kq) ^ a_swz) << 4);
            const uint32_t b_seg = (uint32_t)(((ks * 2 + kq) ^ b_swz) << 4);
            uint32_t aH[4][4], aL[4][4], bH[2][4], bL[2][4];
            #pragma unroll
            for (int mi = 0; mi < 4; mi++) {
                uint32_t ro = (a_row + mi * 16) * 64 + a_seg;
                ldsm4(aH[mi], ah + ro);
                ldsm4(aL[mi], al + ro);
            }
            #pragma unroll
            for (int bj = 0; bj < 2; bj++) {
                uint32_t ro = (b_row + bj * 16) * 64 + b_seg;
                ldsm4(bH[bj], bh + ro);
                ldsm4(bL[bj], bl + ro);
            }
            #pragma unroll
            for (int mi = 0; mi < 4; mi++)
                #pragma unroll
                for (int nj = 0; nj < 4; nj++) {
                    const uint32_t* fh = bH[nj >> 1];
                    const uint32_t* fl = bL[nj >> 1];
                    int s = nj & 1;
                    mma16816(acc[mi][nj], aH[mi], fh[s], fh[s + 2]);
                    mma16816(acc[mi][nj], aH[mi], fl[s], fl[s + 2]);
                    mma16816(acc[mi][nj], aL[mi], fh[s], fh[s + 2]);
                }
        }
    }

    // epilogue: scale and STORE to per-assignment buffer (exclusive rows)
    const int rbase = m0 + warp_m + (lane >> 2);
    const int cbase = n0 + warp_n + (lane & 3) * 2;
    #pragma unroll
    for (int mi = 0; mi < 4; mi++) {
        int r0 = rbase + mi * 16;
        int r1 = r0 + 8;
        float sc0 = g_scale[r0];
        float sc1 = g_scale[r1];
        float* p0 = g_part + (size_t)r0 * H_DIM;
        float* p1 = g_part + (size_t)r1 * H_DIM;
        #pragma unroll
        for (int nj = 0; nj < 4; nj++) {
            int col = cbase + nj * 8;
            float2 v0 = make_float2(acc[mi][nj][0] * sc0, acc[mi][nj][1] * sc0);
            float2 v1 = make_float2(acc[mi][nj][2] * sc1, acc[mi][nj][3] * sc1);
            *(float2*)(p0 + col) = v0;
            *(float2*)(p1 + col) = v1;
        }
    }
}

// ---------------- kernel 6: combine the two expert contributions -------------
__global__ __launch_bounds__(256)
void k_combine(float* __restrict__ out)
{
    int t = blockIdx.x;
    int tid = threadIdx.x;
    int r0 = g_rowof[t * 2 + 0];
    int r1 = g_rowof[t * 2 + 1];
    float4 a = ((const float4*)(g_part + (size_t)r0 * H_DIM))[tid];
    float4 b = ((const float4*)(g_part + (size_t)r1 * H_DIM))[tid];
    float4 o;
    o.x = a.x + b.x;  o.y = a.y + b.y;
    o.z = a.z + b.z;  o.w = a.w + b.w;
    ((float4*)(out + (size_t)t * H_DIM))[tid] = o;
}

// ---------------- launch ----------------
extern "C" void kernel_launch(void* const* d_in, const int* in_sizes, int n_in,
                              void* d_out, int out_size)
{
    const float* hs  = (const float*)d_in[0];
    const float* lnw = (const float*)d_in[1];
    const float* rw  = (const float*)d_in[2];
    const float* wg  = (const float*)d_in[3];
    const float* wu  = (const float*)d_in[4];
    const float* wd  = (const float*)d_in[5];
    float* out = (float*)d_out;

    cudaFuncSetAttribute(k_gemm1_mma, cudaFuncAttributeMaxDynamicSharedMemorySize, SMEM_TOT);
    cudaFuncSetAttribute(k_gemm2_mma, cudaFuncAttributeMaxDynamicSharedMemorySize, SMEM_TOT);

    void *p_cnt = nullptr, *p_tok = nullptr;
    cudaGetSymbolAddress(&p_cnt, g_cnt);
    cudaGetSymbolAddress(&p_tok, g_tok);

    cudaMemsetAsync(p_cnt, 0, N_EXP * sizeof(int));
    cudaMemsetAsync(p_tok, 0xFF, MP_MAX * sizeof(int));

    // fork: weight prep on side stream, concurrent with activation chain
    cudaStream_t s2;
    cudaStreamCreateWithFlags(&s2, cudaStreamNonBlocking);
    cudaEvent_t eFork, eJoin;
    cudaEventCreateWithFlags(&eFork, cudaEventDisableTiming);
    cudaEventCreateWithFlags(&eJoin, cudaEventDisableTiming);

    cudaEventRecord(eFork, 0);
    cudaStreamWaitEvent(s2, eFork, 0);

    dim3 tb(32, 8);
    dim3 tg(F_DIM / 32, F_DIM / 64, 24);
    k_tsplit_all<<<tg, tb, 0, s2>>>(wg, wu, wd);     // launch 1 (side stream)
    cudaEventRecord(eJoin, s2);

    k_rms_router<<<T_TOK, 256>>>(hs, lnw, rw);        // launch 2 (main)
    k_offscatter<<<1, 256>>>();                       // launch 3 (main)

    cudaStreamWaitEvent(0, eJoin, 0);                 // join before GEMMs

    // launch 4 (ncu capture slot): GEMM1
    dim3 g1(F_DIM / 64, MP_MAX / 128);   // (44, 72)
    k_gemm1_mma<<<g1, 256, SMEM_TOT>>>();

    dim3 g2(H_DIM / 128, MP_MAX / 128);  // (8, 72)
    k_gemm2_mma<<<g2, 256, SMEM_TOT>>>();

    k_combine<<<T_TOK, 256>>>(out);
}

// round 14
// speedup vs baseline: 1.4844x; 1.3888x over previous
#include <cuda_runtime.h>
#include <cuda_fp16.h>
#include <math.h>
#include <stdint.h>

#define T_TOK 4096
#define H_DIM 1024
#define F_DIM 2816
#define N_EXP 8
#define EPS_V 1e-5f
#define MP_MAX 9216

// swizzled smem: 64B rows (32 fp16), seg' = seg ^ ((row>>1)&3)
#define TILE_B 8192                  // 128 rows * 64B
#define STG   (3 * TILE_B)           // Ah, Al, Bh per stage = 24576
#define SMEM_TOT (3 * STG)           // 73728 -> 2 CTAs/SM
#define PITCH_E 72                   // epilogue staging pitch (fp16 elems)

// ---------------- PTX helpers (sm_80-family, valid on plain sm_103) ---------
__device__ __forceinline__ uint32_t s2u(const void* p) {
    uint32_t a;
    asm("{ .reg .u64 t; cvta.to.shared.u64 t, %1; cvt.u32.u64 %0, t; }" : "=r"(a) : "l"(p));
    return a;
}
__device__ __forceinline__ void ldsm4(uint32_t* r, uint32_t a) {
    asm volatile("ldmatrix.sync.aligned.m8n8.x4.shared.b16 {%0,%1,%2,%3}, [%4];"
        : "=r"(r[0]), "=r"(r[1]), "=r"(r[2]), "=r"(r[3]) : "r"(a));
}
__device__ __forceinline__ void mma16816h(float* d, const uint32_t* a, uint32_t b0, uint32_t b1) {
    asm volatile("mma.sync.aligned.m16n8k16.row.col.f32.f16.f16.f32 "
        "{%0,%1,%2,%3}, {%4,%5,%6,%7}, {%8,%9}, {%0,%1,%2,%3};"
        : "+f"(d[0]), "+f"(d[1]), "+f"(d[2]), "+f"(d[3])
        : "r"(a[0]), "r"(a[1]), "r"(a[2]), "r"(a[3]), "r"(b0), "r"(b1));
}
__device__ __forceinline__ void cp16(uint32_t s, const void* g) {
    asm volatile("{ .reg .u64 gg; cvta.to.global.u64 gg, %1; "
                 "cp.async.cg.shared.global [%0], [gg], 16; }"
                 :: "r"(s), "l"(g) : "memory");
}
#define CP_COMMIT() asm volatile("cp.async.commit_group;" ::: "memory")
#define CP_WAIT1()  asm volatile("cp.async.wait_group 1;" ::: "memory")
#define CP_WAIT0()  asm volatile("cp.async.wait_group 0;" ::: "memory")

// ---------------- scratch (device globals) ----------------
__device__ __half g_x_hi[T_TOK * H_DIM];
__device__ __half g_x_lo[T_TOK * H_DIM];
__device__ __half g_h_hi[(size_t)MP_MAX * F_DIM];
__device__ __half g_h_lo[(size_t)MP_MAX * F_DIM];
__device__ __half g_wg[(size_t)N_EXP * F_DIM * H_DIM];
__device__ __half g_wu[(size_t)N_EXP * F_DIM * H_DIM];
__device__ __half g_wd[(size_t)N_EXP * H_DIM * F_DIM];
__device__ float g_part[(size_t)MP_MAX * H_DIM];     // per-assignment scaled output
__device__ int   g_tok[MP_MAX];
__device__ float g_scale[MP_MAX];
__device__ int   g_rowof[T_TOK * 2];                 // token -> assignment rows
__device__ int   g_te[T_TOK * 2];
__device__ float g_tp[T_TOK * 2];
__device__ int   g_cnt[N_EXP];
__device__ int   g_offp[N_EXP + 1];

// ---------------- kernel 1: rmsnorm + router + fp16 split ----------------
__global__ __launch_bounds__(256)
void k_rms_router(const float* __restrict__ hs,
                  const float* __restrict__ lnw,
                  const float* __restrict__ rw)
{
    int t = blockIdx.x;
    int tid = threadIdx.x;
    int lane = tid & 31, wid = tid >> 5;

    __shared__ float s_x[H_DIM];
    __shared__ float swr[8];
    __shared__ float s_inv;
    __shared__ float sl[8][N_EXP];

    const float4 v = ((const float4*)(hs + (size_t)t * H_DIM))[tid];
    float ss = v.x*v.x + v.y*v.y + v.z*v.z + v.w*v.w;
    #pragma unroll
    for (int o = 16; o; o >>= 1) ss += __shfl_xor_sync(0xffffffffu, ss, o);
    if (lane == 0) swr[wid] = ss;
    __syncthreads();
    if (tid == 0) {
        float s = 0.f;
        #pragma unroll
        for (int i = 0; i < 8; i++) s += swr[i];
        s_inv = rsqrtf(s / (float)H_DIM + EPS_V);
    }
    __syncthreads();
    float inv = s_inv;

    const float4 w = ((const float4*)lnw)[tid];
    float xv[4];
    xv[0] = v.x * inv * w.x;  xv[1] = v.y * inv * w.y;
    xv[2] = v.z * inv * w.z;  xv[3] = v.w * inv * w.w;

    __half hi[4], lo[4];
    #pragma unroll
    for (int j = 0; j < 4; j++) {
        s_x[tid * 4 + j] = xv[j];
        hi[j] = __float2half(xv[j]);
        lo[j] = __float2half(xv[j] - __half2float(hi[j]));
    }
    ((uint2*)(g_x_hi + (size_t)t * H_DIM))[tid] = *(uint2*)hi;
    ((uint2*)(g_x_lo + (size_t)t * H_DIM))[tid] = *(uint2*)lo;
    __syncthreads();

    {
        const int c = lane & 3, r = lane >> 2;
        const float2* rw2 = (const float2*)rw;
        float2 p = make_float2(0.f, 0.f);
        int ibase = wid * 128 + r;
        #pragma unroll
        for (int k = 0; k < 16; k++) {
            int i = ibase + k * 8;
            float2 w2 = rw2[i * 4 + c];
            float xs = s_x[i];
            p.x += xs * w2.x;
            p.y += xs * w2.y;
        }
        #pragma unroll
        for (int o = 16; o >= 4; o >>= 1) {
            p.x += __shfl_xor_sync(0xffffffffu, p.x, o);
            p.y += __shfl_xor_sync(0xffffffffu, p.y, o);
        }
        if (lane < 4) {
            sl[wid][2 * c]     = p.x;
            sl[wid][2 * c + 1] = p.y;
        }
    }
    __syncthreads();

    if (tid == 0) {
        float l[N_EXP];
        #pragma unroll
        for (int e = 0; e < N_EXP; e++) {
            float s = 0.f;
            #pragma unroll
            for (int w2 = 0; w2 < 8; w2++) s += sl[w2][e];
            l[e] = s;
        }
        float m = l[0];
        #pragma unroll
        for (int e = 1; e < N_EXP; e++) m = fmaxf(m, l[e]);
        float den = 0.f, pr[N_EXP];
        #pragma unroll
        for (int e = 0; e < N_EXP; e++) { pr[e] = expf(l[e] - m); den += pr[e]; }
        float rden = 1.f / den;
        #pragma unroll
        for (int e = 0; e < N_EXP; e++) pr[e] *= rden;

        int i1 = 0;
        #pragma unroll
        for (int e = 1; e < N_EXP; e++) if (pr[e] > pr[i1]) i1 = e;
        int i2 = (i1 == 0) ? 1 : 0;
        #pragma unroll
        for (int e = 0; e < N_EXP; e++) if (e != i1 && pr[e] > pr[i2]) i2 = e;

        g_te[t * 2 + 0] = i1;  g_tp[t * 2 + 0] = pr[i1];
        g_te[t * 2 + 1] = i2;  g_tp[t * 2 + 1] = pr[i2];
        atomicAdd(&g_cnt[i1], 1);
        atomicAdd(&g_cnt[i2], 1);
    }
}

// ---------------- kernel 2: ALL weight transposes (single fp16) --------------
__global__ __launch_bounds__(256)
void k_tsplit_all(const float* __restrict__ wg,
                  const float* __restrict__ wu,
                  const float* __restrict__ wd)
{
    int z = blockIdx.z;
    const float* src;
    __half* dst;
    int R, C, e;
    if (z < 8)       { src = wg; dst = g_wg; R = H_DIM; C = F_DIM; e = z; }
    else if (z < 16) { src = wu; dst = g_wu; R = H_DIM; C = F_DIM; e = z - 8; }
    else             { src = wd; dst = g_wd; R = F_DIM; C = H_DIM; e = z - 16; }

    int c0 = blockIdx.x * 32, r0 = blockIdx.y * 64;
    if (c0 >= C || r0 >= R) return;

    __shared__ float t[64][33];
    const float* s = src + (size_t)e * R * C;
    size_t dbase = (size_t)e * R * C;
    int tx = threadIdx.x, ty = threadIdx.y;
    #pragma unroll
    for (int i = 0; i < 8; i++) {
        int r = ty + i * 8;
        t[r][tx] = s[(size_t)(r0 + r) * C + c0 + tx];
    }
    __syncthreads();
    #pragma unroll
    for (int i = 0; i < 4; i++) {
        int c = ty + i * 8;
        __half h0 = __float2half(t[2 * tx][c]);
        __half h1 = __float2half(t[2 * tx + 1][c]);
        uint32_t uh = (uint32_t)__half_as_ushort(h0) | ((uint32_t)__half_as_ushort(h1) << 16);
        size_t o = dbase + (size_t)(c0 + c) * R + r0 + 2 * tx;
        *(uint32_t*)(dst + o) = uh;
    }
}

// ---------------- kernel 3: offsets + scatter (single block) -----------------
__global__ __launch_bounds__(256)
void k_offscatter()
{
    __shared__ int s_fill[N_EXP];
    int tid = threadIdx.x;
    if (tid == 0) {
        int acc = 0;
        #pragma unroll
        for (int e = 0; e < N_EXP; e++) {
            g_offp[e]  = acc;
            s_fill[e]  = acc;
            acc += (g_cnt[e] + 127) & ~127;
        }
        g_offp[N_EXP] = acc;
    }
    __syncthreads();
    for (int t = tid; t < T_TOK; t += 256) {
        #pragma unroll
        for (int k = 0; k < 2; k++) {
            int e = g_te[t * 2 + k];
            int r = atomicAdd(&s_fill[e], 1);
            g_tok[r]     = t;
            g_scale[r]   = g_tp[t * 2 + k];
            g_rowof[t * 2 + k] = r;
        }
    }
}

// ======================= GEMM1: gate/up + SiLU (fp16 2-term) =================
__global__ __launch_bounds__(256, 2)
void k_gemm1_mma()
{
    extern __shared__ char smem[];
    const uint32_t sb = s2u(smem);
    const int tid = threadIdx.x, lane = tid & 31, wid = tid >> 5;

    const int Mp = g_offp[N_EXP];
    const int m0 = blockIdx.y * 128;
    if (m0 >= Mp) return;
    const int n0 = blockIdx.x * 64;
    int e = 0;
    #pragma unroll
    for (int i = 1; i < N_EXP; i++) if (m0 >= g_offp[i]) e = i;

    __shared__ int s_tok[128];
    if (tid < 128) {
        int tok = g_tok[m0 + tid];
        s_tok[tid] = (tok >= 0) ? tok : 0;
    }
    __syncthreads();

    const int lr = tid >> 2;
    const int ls = tid & 3;
    const int NC = H_DIM / 32;

    auto load_chunk = [&](int c, int stg) {
        int kc = c * 32;
        uint32_t base = sb + stg * STG;
        uint32_t ah = base, al = base + TILE_B, bh = base + 2 * TILE_B;
        #pragma unroll
        for (int i = 0; i < 2; i++) {
            int row = lr + 64 * i;
            uint32_t so = row * 64 + ((ls ^ ((row >> 1) & 3)) << 4);
            size_t go = (size_t)s_tok[row] * H_DIM + kc + ls * 8;
            cp16(ah + so, g_x_hi + go);
            cp16(al + so, g_x_lo + go);
        }
        #pragma unroll
        for (int i = 0; i < 2; i++) {
            int rn = lr + 64 * i;
            uint32_t so = rn * 64 + ((ls ^ ((rn >> 1) & 3)) << 4);
            int col = n0 + (rn >> 1);
            size_t go = ((size_t)e * F_DIM + col) * H_DIM + kc + ls * 8;
            const __half* W = (rn & 1) ? g_wu : g_wg;
            cp16(bh + so, W + go);
        }
    };

    load_chunk(0, 0); CP_COMMIT();
    load_chunk(1, 1); CP_COMMIT();

    const int warp_m = (wid & 1) * 64;
    const int warp_n = (wid >> 1) * 32;

    float acc[4][4][4];
    #pragma unroll
    for (int i = 0; i < 4; i++)
        #pragma unroll
        for (int j = 0; j < 4; j++)
            #pragma unroll
            for (int k = 0; k < 4; k++) acc[i][j][k] = 0.f;

    const int quad = lane >> 3, l7 = lane & 7;
    const int a_row = warp_m + (quad & 1) * 8 + l7;
    const int b_row = warp_n + (quad & 1) * 8 + l7;
    const int kq = quad >> 1;
    const int a_swz = (a_row >> 1) & 3;
    const int b_swz = (b_row >> 1) & 3;

    for (int c = 0; c < NC; c++) {
        if (c + 1 < NC) { CP_WAIT1(); } else { CP_WAIT0(); }
        __syncthreads();
        if (c + 2 < NC) { load_chunk(c + 2, (c + 2) % 3); CP_COMMIT(); }

        uint32_t base = sb + (c % 3) * STG;
        uint32_t ah = base, al = base + TILE_B, bh = base + 2 * TILE_B;
        #pragma unroll
        for (int ks = 0; ks < 2; ks++) {
            const uint32_t a_seg = (uint32_t)(((ks * 2 + kq) ^ a_swz) << 4);
            const uint32_t b_seg = (uint32_t)(((ks * 2 + kq) ^ b_swz) << 4);
            uint32_t aH[4][4], aL[4][4], bH[2][4];
            #pragma unroll
            for (int mi = 0; mi < 4; mi++) {
                uint32_t ro = (a_row + mi * 16) * 64 + a_seg;
                ldsm4(aH[mi], ah + ro);
                ldsm4(aL[mi], al + ro);
            }
            #pragma unroll
            for (int bj = 0; bj < 2; bj++) {
                uint32_t ro = (b_row + bj * 16) * 64 + b_seg;
                ldsm4(bH[bj], bh + ro);
            }
            #pragma unroll
            for (int mi = 0; mi < 4; mi++)
                #pragma unroll
                for (int nj = 0; nj < 4; nj++) {
                    const uint32_t* f = bH[nj >> 1];
                    int s = nj & 1;
                    mma16816h(acc[mi][nj], aH[mi], f[s], f[s + 2]);
                    mma16816h(acc[mi][nj], aL[mi], f[s], f[s + 2]);
                }
        }
    }

    // ---- staged epilogue: silu(g)*u -> smem staging -> coalesced stores ----
    __syncthreads();
    __half* s_hi = (__half*)smem;                         // [128][PITCH_E]
    __half* s_lo = (__half*)(smem + 128 * PITCH_E * 2);
    const int r_l = warp_m + (lane >> 2);
    const int c_l = (warp_n >> 1) + (lane & 3);
    #pragma unroll
    for (int mi = 0; mi < 4; mi++) {
        int row0 = r_l + mi * 16;
        int row1 = row0 + 8;
        #pragma unroll
        for (int nj = 0; nj < 4; nj++) {
            int cc = c_l + nj * 4;
            float g0 = acc[mi][nj][0], u0 = acc[mi][nj][1];
            float g1 = acc[mi][nj][2], u1 = acc[mi][nj][3];
            float h0 = (g0 / (1.f + expf(-g0))) * u0;
            float h1 = (g1 / (1.f + expf(-g1))) * u1;
            __half h0h = __float2half(h0);
            __half h1h = __float2half(h1);
            s_hi[row0 * PITCH_E + cc] = h0h;
            s_hi[row1 * PITCH_E + cc] = h1h;
            s_lo[row0 * PITCH_E + cc] = __float2half(h0 - __half2float(h0h));
            s_lo[row1 * PITCH_E + cc] = __float2half(h1 - __half2float(h1h));
        }
    }
    __syncthreads();
    {
        const int row  = tid >> 1;
        const int half = tid & 1;
        size_t gbase = (size_t)(m0 + row) * F_DIM + n0 + half * 32;
        const uint4* src_h = (const uint4*)(s_hi + row * PITCH_E + half * 32);
        const uint4* src_l = (const uint4*)(s_lo + row * PITCH_E + half * 32);
        uint4* dst_h = (uint4*)(g_h_hi + gbase);
        uint4* dst_l = (uint4*)(g_h_lo + gbase);
        #pragma unroll
        for (int i = 0; i < 4; i++) dst_h[i] = src_h[i];
        #pragma unroll
        for (int i = 0; i < 4; i++) dst_l[i] = src_l[i];
    }
}

// ======================= GEMM2: down proj -> g_part (fp16 2-term) ============
__global__ __launch_bounds__(256, 2)
void k_gemm2_mma()
{
    extern __shared__ char smem[];
    const uint32_t sb = s2u(smem);
    const int tid = threadIdx.x, lane = tid & 31, wid = tid >> 5;

    const int Mp = g_offp[N_EXP];
    const int m0 = blockIdx.y * 128;
    if (m0 >= Mp) return;
    const int n0 = blockIdx.x * 128;
    int e = 0;
    #pragma unroll
    for (int i = 1; i < N_EXP; i++) if (m0 >= g_offp[i]) e = i;

    const int lr = tid >> 2;
    const int ls = tid & 3;
    const int NC = F_DIM / 32;

    auto load_chunk = [&](int c, int stg) {
        int kc = c * 32;
        uint32_t base = sb + stg * STG;
        uint32_t ah = base, al = base + TILE_B, bh = base + 2 * TILE_B;
        #pragma unroll
        for (int i = 0; i < 2; i++) {
            int row = lr + 64 * i;
            uint32_t so = row * 64 + ((ls ^ ((row >> 1) & 3)) << 4);
            size_t go = (size_t)(m0 + row) * F_DIM + kc + ls * 8;
            cp16(ah + so, g_h_hi + go);
            cp16(al + so, g_h_lo + go);
        }
        #pragma unroll
        for (int i = 0; i < 2; i++) {
            int rn = lr + 64 * i;
            uint32_t so = rn * 64 + ((ls ^ ((rn >> 1) & 3)) << 4);
            size_t go = ((size_t)e * H_DIM + n0 + rn) * F_DIM + kc + ls * 8;
            cp16(bh + so, g_wd + go);
        }
    };

    load_chunk(0, 0); CP_COMMIT();
    load_chunk(1, 1); CP_COMMIT();

    const int warp_m = (wid & 1) * 64;
    const int warp_n = (wid >> 1) * 32;

    float acc[4][4][4];
    #pragma unroll
    for (int i = 0; i < 4; i++)
        #pragma unroll
        for (int j = 0; j < 4; j++)
            #pragma unroll
            for (int k = 0; k < 4; k++) acc[i][j][k] = 0.f;

    const int quad = lane >> 3, l7 = lane & 7;
    const int a_row = warp_m + (quad & 1) * 8 + l7;
    const int b_row = warp_n + (quad & 1) * 8 + l7;
    const int kq = quad >> 1;
    const int a_swz = (a_row >> 1) & 3;
    const int b_swz = (b_row >> 1) & 3;

    for (int c = 0; c < NC; c++) {
        if (c + 1 < NC) { CP_WAIT1(); } else { CP_WAIT0(); }
        __syncthreads();
        if (c + 2 < NC) { load_chunk(c + 2, (c + 2) % 3); CP_COMMIT(); }

        uint32_t base = sb + (c % 3) * STG;
        uint32_t ah = base, al = base + TILE_B, bh = base + 2 * TILE_B;
        #pragma unroll
        for (int ks = 0; ks < 2; ks++) {
            const uint32_t a_seg = (uint32_t)(((ks * 2 + kq) ^ a_swz) << 4);
            const uint32_t b_seg = (uint32_t)(((ks * 2 + kq) ^ b_swz) << 4);
            uint32_t aH[4][4], aL[4][4], bH[2][4];
            #pragma unroll
            for (int mi = 0; mi < 4; mi++) {
                uint32_t ro = (a_row + mi * 16) * 64 + a_seg;
                ldsm4(aH[mi], ah + ro);
                ldsm4(aL[mi], al + ro);
            }
            #pragma unroll
            for (int bj = 0; bj < 2; bj++) {
                uint32_t ro = (b_row + bj * 16) * 64 + b_seg;
                ldsm4(bH[bj], bh + ro);
            }
            #pragma unroll
            for (int mi = 0; mi < 4; mi++)
                #pragma unroll
                for (int nj = 0; nj < 4; nj++) {
                    const uint32_t* f = bH[nj >> 1];
                    int s = nj & 1;
                    mma16816h(acc[mi][nj], aH[mi], f[s], f[s + 2]);
                    mma16816h(acc[mi][nj], aL[mi], f[s], f[s + 2]);
                }
        }
    }

    // epilogue: scale and STORE to per-assignment buffer (exclusive rows)
    const int rbase = m0 + warp_m + (lane >> 2);
    const int cbase = n0 + warp_n + (lane & 3) * 2;
    #pragma unroll
    for (int mi = 0; mi < 4; mi++) {
        int r0 = rbase + mi * 16;
        int r1 = r0 + 8;
        float sc0 = g_scale[r0];
        float sc1 = g_scale[r1];
        float* p0 = g_part + (size_t)r0 * H_DIM;
        float* p1 = g_part + (size_t)r1 * H_DIM;
        #pragma unroll
        for (int nj = 0; nj < 4; nj++) {
            int col = cbase + nj * 8;
            float2 v0 = make_float2(acc[mi][nj][0] * sc0, acc[mi][nj][1] * sc0);
            float2 v1 = make_float2(acc[mi][nj][2] * sc1, acc[mi][nj][3] * sc1);
            *(float2*)(p0 + col) = v0;
            *(float2*)(p1 + col) = v1;
        }
    }
}

// ---------------- kernel 6: combine the two expert contributions -------------
__global__ __launch_bounds__(256)
void k_combine(float* __restrict__ out)
{
    int t = blockIdx.x;
    int tid = threadIdx.x;
    int r0 = g_rowof[t * 2 + 0];
    int r1 = g_rowof[t * 2 + 1];
    float4 a = ((const float4*)(g_part + (size_t)r0 * H_DIM))[tid];
    float4 b = ((const float4*)(g_part + (size_t)r1 * H_DIM))[tid];
    float4 o;
    o.x = a.x + b.x;  o.y = a.y + b.y;
    o.z = a.z + b.z;  o.w = a.w + b.w;
    ((float4*)(out + (size_t)t * H_DIM))[tid] = o;
}

// ---------------- launch ----------------
extern "C" void kernel_launch(void* const* d_in, const int* in_sizes, int n_in,
                              void* d_out, int out_size)
{
    const float* hs  = (const float*)d_in[0];
    const float* lnw = (const float*)d_in[1];
    const float* rw  = (const float*)d_in[2];
    const float* wg  = (const float*)d_in[3];
    const float* wu  = (const float*)d_in[4];
    const float* wd  = (const float*)d_in[5];
    float* out = (float*)d_out;

    cudaFuncSetAttribute(k_gemm1_mma, cudaFuncAttributeMaxDynamicSharedMemorySize, SMEM_TOT);
    cudaFuncSetAttribute(k_gemm2_mma, cudaFuncAttributeMaxDynamicSharedMemorySize, SMEM_TOT);

    void *p_cnt = nullptr, *p_tok = nullptr;
    cudaGetSymbolAddress(&p_cnt, g_cnt);
    cudaGetSymbolAddress(&p_tok, g_tok);

    cudaMemsetAsync(p_cnt, 0, N_EXP * sizeof(int));
    cudaMemsetAsync(p_tok, 0xFF, MP_MAX * sizeof(int));

    // fork: weight prep on side stream, concurrent with activation chain
    cudaStream_t s2;
    cudaStreamCreateWithFlags(&s2, cudaStreamNonBlocking);
    cudaEvent_t eFork, eJoin;
    cudaEventCreateWithFlags(&eFork, cudaEventDisableTiming);
    cudaEventCreateWithFlags(&eJoin, cudaEventDisableTiming);

    cudaEventRecord(eFork, 0);
    cudaStreamWaitEvent(s2, eFork, 0);

    dim3 tb(32, 8);
    dim3 tg(F_DIM / 32, F_DIM / 64, 24);
    k_tsplit_all<<<tg, tb, 0, s2>>>(wg, wu, wd);     // launch 1 (side stream)
    cudaEventRecord(eJoin, s2);

    k_rms_router<<<T_TOK, 256>>>(hs, lnw, rw);        // launch 2 (main)
    k_offscatter<<<1, 256>>>();                       // launch 3 (main)

    cudaStreamWaitEvent(0, eJoin, 0);                 // join before GEMMs

    // launch 4 (ncu capture slot): GEMM1
    dim3 g1(F_DIM / 64, MP_MAX / 128);   // (44, 72)
    k_gemm1_mma<<<g1, 256, SMEM_TOT>>>();

    dim3 g2(H_DIM / 128, MP_MAX / 128);  // (8, 72)
    k_gemm2_mma<<<g2, 256, SMEM_TOT>>>();

    k_combine<<<T_TOK, 256>>>(out);
}

// round 15
// speedup vs baseline: 1.7673x; 1.1906x over previous
#include <cuda_runtime.h>
#include <cuda_fp16.h>
#include <math.h>
#include <stdint.h>

#define T_TOK 4096
#define H_DIM 1024
#define F_DIM 2816
#define N_EXP 8
#define EPS_V 1e-5f
#define MP_MAX 9216

// swizzled smem: 64B rows (32 fp16), seg' = seg ^ ((row>>1)&3)
#define TILE_B 8192                  // 128 rows * 64B
#define STG1  (3 * TILE_B)           // gemm1: Ah, Al, Bh = 24576
#define SMEM1 (3 * STG1)             // 73728
#define STG2  (2 * TILE_B)           // gemm2: Ah, Bh = 16384
#define SMEM2 (3 * STG2)             // 49152
#define PITCH_E 72                   // epilogue staging pitch (fp16 elems)

// ---------------- PTX helpers (sm_80-family, valid on plain sm_103) ---------
__device__ __forceinline__ uint32_t s2u(const void* p) {
    uint32_t a;
    asm("{ .reg .u64 t; cvta.to.shared.u64 t, %1; cvt.u32.u64 %0, t; }" : "=r"(a) : "l"(p));
    return a;
}
__device__ __forceinline__ void ldsm4(uint32_t* r, uint32_t a) {
    asm volatile("ldmatrix.sync.aligned.m8n8.x4.shared.b16 {%0,%1,%2,%3}, [%4];"
        : "=r"(r[0]), "=r"(r[1]), "=r"(r[2]), "=r"(r[3]) : "r"(a));
}
__device__ __forceinline__ void mma16816h(float* d, const uint32_t* a, uint32_t b0, uint32_t b1) {
    asm volatile("mma.sync.aligned.m16n8k16.row.col.f32.f16.f16.f32 "
        "{%0,%1,%2,%3}, {%4,%5,%6,%7}, {%8,%9}, {%0,%1,%2,%3};"
        : "+f"(d[0]), "+f"(d[1]), "+f"(d[2]), "+f"(d[3])
        : "r"(a[0]), "r"(a[1]), "r"(a[2]), "r"(a[3]), "r"(b0), "r"(b1));
}
__device__ __forceinline__ void cp16(uint32_t s, const void* g) {
    asm volatile("{ .reg .u64 gg; cvta.to.global.u64 gg, %1; "
                 "cp.async.cg.shared.global [%0], [gg], 16; }"
                 :: "r"(s), "l"(g) : "memory");
}
#define CP_COMMIT() asm volatile("cp.async.commit_group;" ::: "memory")
#define CP_WAIT1()  asm volatile("cp.async.wait_group 1;" ::: "memory")
#define CP_WAIT0()  asm volatile("cp.async.wait_group 0;" ::: "memory")

// ---------------- scratch (device globals) ----------------
__device__ __half g_x_hi[T_TOK * H_DIM];
__device__ __half g_x_lo[T_TOK * H_DIM];
__device__ __half g_h[(size_t)MP_MAX * F_DIM];
__device__ __half g_wg[(size_t)N_EXP * F_DIM * H_DIM];
__device__ __half g_wu[(size_t)N_EXP * F_DIM * H_DIM];
__device__ __half g_wd[(size_t)N_EXP * H_DIM * F_DIM];
__device__ float g_part[(size_t)MP_MAX * H_DIM];     // per-assignment scaled output
__device__ int   g_tok[MP_MAX];
__device__ float g_scale[MP_MAX];
__device__ int   g_rowof[T_TOK * 2];                 // token -> assignment rows
__device__ int   g_te[T_TOK * 2];
__device__ float g_tp[T_TOK * 2];
__device__ int   g_cnt[N_EXP];
__device__ int   g_offp[N_EXP + 1];

// ---------------- kernel 1: rmsnorm + router + fp16 split ----------------
__global__ __launch_bounds__(256)
void k_rms_router(const float* __restrict__ hs,
                  const float* __restrict__ lnw,
                  const float* __restrict__ rw)
{
    int t = blockIdx.x;
    int tid = threadIdx.x;
    int lane = tid & 31, wid = tid >> 5;

    __shared__ float s_x[H_DIM];
    __shared__ float swr[8];
    __shared__ float s_inv;
    __shared__ float sl[8][N_EXP];

    const float4 v = ((const float4*)(hs + (size_t)t * H_DIM))[tid];
    float ss = v.x*v.x + v.y*v.y + v.z*v.z + v.w*v.w;
    #pragma unroll
    for (int o = 16; o; o >>= 1) ss += __shfl_xor_sync(0xffffffffu, ss, o);
    if (lane == 0) swr[wid] = ss;
    __syncthreads();
    if (tid == 0) {
        float s = 0.f;
        #pragma unroll
        for (int i = 0; i < 8; i++) s += swr[i];
        s_inv = rsqrtf(s / (float)H_DIM + EPS_V);
    }
    __syncthreads();
    float inv = s_inv;

    const float4 w = ((const float4*)lnw)[tid];
    float xv[4];
    xv[0] = v.x * inv * w.x;  xv[1] = v.y * inv * w.y;
    xv[2] = v.z * inv * w.z;  xv[3] = v.w * inv * w.w;

    __half hi[4], lo[4];
    #pragma unroll
    for (int j = 0; j < 4; j++) {
        s_x[tid * 4 + j] = xv[j];
        hi[j] = __float2half(xv[j]);
        lo[j] = __float2half(xv[j] - __half2float(hi[j]));
    }
    ((uint2*)(g_x_hi + (size_t)t * H_DIM))[tid] = *(uint2*)hi;
    ((uint2*)(g_x_lo + (size_t)t * H_DIM))[tid] = *(uint2*)lo;
    __syncthreads();

    {
        const int c = lane & 3, r = lane >> 2;
        const float2* rw2 = (const float2*)rw;
        float2 p = make_float2(0.f, 0.f);
        int ibase = wid * 128 + r;
        #pragma unroll
        for (int k = 0; k < 16; k++) {
            int i = ibase + k * 8;
            float2 w2 = rw2[i * 4 + c];
            float xs = s_x[i];
            p.x += xs * w2.x;
            p.y += xs * w2.y;
        }
        #pragma unroll
        for (int o = 16; o >= 4; o >>= 1) {
            p.x += __shfl_xor_sync(0xffffffffu, p.x, o);
            p.y += __shfl_xor_sync(0xffffffffu, p.y, o);
        }
        if (lane < 4) {
            sl[wid][2 * c]     = p.x;
            sl[wid][2 * c + 1] = p.y;
        }
    }
    __syncthreads();

    if (tid == 0) {
        float l[N_EXP];
        #pragma unroll
        for (int e = 0; e < N_EXP; e++) {
            float s = 0.f;
            #pragma unroll
            for (int w2 = 0; w2 < 8; w2++) s += sl[w2][e];
            l[e] = s;
        }
        float m = l[0];
        #pragma unroll
        for (int e = 1; e < N_EXP; e++) m = fmaxf(m, l[e]);
        float den = 0.f, pr[N_EXP];
        #pragma unroll
        for (int e = 0; e < N_EXP; e++) { pr[e] = expf(l[e] - m); den += pr[e]; }
        float rden = 1.f / den;
        #pragma unroll
        for (int e = 0; e < N_EXP; e++) pr[e] *= rden;

        int i1 = 0;
        #pragma unroll
        for (int e = 1; e < N_EXP; e++) if (pr[e] > pr[i1]) i1 = e;
        int i2 = (i1 == 0) ? 1 : 0;
        #pragma unroll
        for (int e = 0; e < N_EXP; e++) if (e != i1 && pr[e] > pr[i2]) i2 = e;

        g_te[t * 2 + 0] = i1;  g_tp[t * 2 + 0] = pr[i1];
        g_te[t * 2 + 1] = i2;  g_tp[t * 2 + 1] = pr[i2];
        atomicAdd(&g_cnt[i1], 1);
        atomicAdd(&g_cnt[i2], 1);
    }
}

// ---------------- kernel 2: ALL weight transposes (single fp16) --------------
__global__ __launch_bounds__(256)
void k_tsplit_all(const float* __restrict__ wg,
                  const float* __restrict__ wu,
                  const float* __restrict__ wd)
{
    int z = blockIdx.z;
    const float* src;
    __half* dst;
    int R, C, e;
    if (z < 8)       { src = wg; dst = g_wg; R = H_DIM; C = F_DIM; e = z; }
    else if (z < 16) { src = wu; dst = g_wu; R = H_DIM; C = F_DIM; e = z - 8; }
    else             { src = wd; dst = g_wd; R = F_DIM; C = H_DIM; e = z - 16; }

    int c0 = blockIdx.x * 32, r0 = blockIdx.y * 64;
    if (c0 >= C || r0 >= R) return;

    __shared__ float t[64][33];
    const float* s = src + (size_t)e * R * C;
    size_t dbase = (size_t)e * R * C;
    int tx = threadIdx.x, ty = threadIdx.y;
    #pragma unroll
    for (int i = 0; i < 8; i++) {
        int r = ty + i * 8;
        t[r][tx] = s[(size_t)(r0 + r) * C + c0 + tx];
    }
    __syncthreads();
    #pragma unroll
    for (int i = 0; i < 4; i++) {
        int c = ty + i * 8;
        __half h0 = __float2half(t[2 * tx][c]);
        __half h1 = __float2half(t[2 * tx + 1][c]);
        uint32_t uh = (uint32_t)__half_as_ushort(h0) | ((uint32_t)__half_as_ushort(h1) << 16);
        size_t o = dbase + (size_t)(c0 + c) * R + r0 + 2 * tx;
        *(uint32_t*)(dst + o) = uh;
    }
}

// ---------------- kernel 3: offsets + scatter (single block) -----------------
__global__ __launch_bounds__(256)
void k_offscatter()
{
    __shared__ int s_fill[N_EXP];
    int tid = threadIdx.x;
    if (tid == 0) {
        int acc = 0;
        #pragma unroll
        for (int e = 0; e < N_EXP; e++) {
            g_offp[e]  = acc;
            s_fill[e]  = acc;
            acc += (g_cnt[e] + 127) & ~127;
        }
        g_offp[N_EXP] = acc;
    }
    __syncthreads();
    for (int t = tid; t < T_TOK; t += 256) {
        #pragma unroll
        for (int k = 0; k < 2; k++) {
            int e = g_te[t * 2 + k];
            int r = atomicAdd(&s_fill[e], 1);
            g_tok[r]     = t;
            g_scale[r]   = g_tp[t * 2 + k];
            g_rowof[t * 2 + k] = r;
        }
    }
}

// ======================= GEMM1: gate/up + SiLU (fp16 2-term) =================
__global__ __launch_bounds__(256, 2)
void k_gemm1_mma()
{
    extern __shared__ char smem[];
    const uint32_t sb = s2u(smem);
    const int tid = threadIdx.x, lane = tid & 31, wid = tid >> 5;

    const int Mp = g_offp[N_EXP];
    const int m0 = blockIdx.y * 128;
    if (m0 >= Mp) return;
    const int n0 = blockIdx.x * 64;
    int e = 0;
    #pragma unroll
    for (int i = 1; i < N_EXP; i++) if (m0 >= g_offp[i]) e = i;

    __shared__ int s_tok[128];
    if (tid < 128) {
        int tok = g_tok[m0 + tid];
        s_tok[tid] = (tok >= 0) ? tok : 0;
    }
    __syncthreads();

    const int lr = tid >> 2;
    const int ls = tid & 3;
    const int NC = H_DIM / 32;

    auto load_chunk = [&](int c, int stg) {
        int kc = c * 32;
        uint32_t base = sb + stg * STG1;
        uint32_t ah = base, al = base + TILE_B, bh = base + 2 * TILE_B;
        #pragma unroll
        for (int i = 0; i < 2; i++) {
            int row = lr + 64 * i;
            uint32_t so = row * 64 + ((ls ^ ((row >> 1) & 3)) << 4);
            size_t go = (size_t)s_tok[row] * H_DIM + kc + ls * 8;
            cp16(ah + so, g_x_hi + go);
            cp16(al + so, g_x_lo + go);
        }
        #pragma unroll
        for (int i = 0; i < 2; i++) {
            int rn = lr + 64 * i;
            uint32_t so = rn * 64 + ((ls ^ ((rn >> 1) & 3)) << 4);
            int col = n0 + (rn >> 1);
            size_t go = ((size_t)e * F_DIM + col) * H_DIM + kc + ls * 8;
            const __half* W = (rn & 1) ? g_wu : g_wg;
            cp16(bh + so, W + go);
        }
    };

    load_chunk(0, 0); CP_COMMIT();
    load_chunk(1, 1); CP_COMMIT();

    const int warp_m = (wid & 1) * 64;
    const int warp_n = (wid >> 1) * 32;

    float acc[4][4][4];
    #pragma unroll
    for (int i = 0; i < 4; i++)
        #pragma unroll
        for (int j = 0; j < 4; j++)
            #pragma unroll
            for (int k = 0; k < 4; k++) acc[i][j][k] = 0.f;

    const int quad = lane >> 3, l7 = lane & 7;
    const int a_row = warp_m + (quad & 1) * 8 + l7;
    const int b_row = warp_n + (quad & 1) * 8 + l7;
    const int kq = quad >> 1;
    const int a_swz = (a_row >> 1) & 3;
    const int b_swz = (b_row >> 1) & 3;

    for (int c = 0; c < NC; c++) {
        if (c + 1 < NC) { CP_WAIT1(); } else { CP_WAIT0(); }
        __syncthreads();
        if (c + 2 < NC) { load_chunk(c + 2, (c + 2) % 3); CP_COMMIT(); }

        uint32_t base = sb + (c % 3) * STG1;
        uint32_t ah = base, al = base + TILE_B, bh = base + 2 * TILE_B;
        #pragma unroll
        for (int ks = 0; ks < 2; ks++) {
            const uint32_t a_seg = (uint32_t)(((ks * 2 + kq) ^ a_swz) << 4);
            const uint32_t b_seg = (uint32_t)(((ks * 2 + kq) ^ b_swz) << 4);
            uint32_t aH[4][4], aL[4][4], bH[2][4];
            #pragma unroll
            for (int mi = 0; mi < 4; mi++) {
                uint32_t ro = (a_row + mi * 16) * 64 + a_seg;
                ldsm4(aH[mi], ah + ro);
                ldsm4(aL[mi], al + ro);
            }
            #pragma unroll
            for (int bj = 0; bj < 2; bj++) {
                uint32_t ro = (b_row + bj * 16) * 64 + b_seg;
                ldsm4(bH[bj], bh + ro);
            }
            #pragma unroll
            for (int mi = 0; mi < 4; mi++)
                #pragma unroll
                for (int nj = 0; nj < 4; nj++) {
                    const uint32_t* f = bH[nj >> 1];
                    int s = nj & 1;
                    mma16816h(acc[mi][nj], aH[mi], f[s], f[s + 2]);
                    mma16816h(acc[mi][nj], aL[mi], f[s], f[s + 2]);
                }
        }
    }

    // ---- staged epilogue: silu(g)*u -> smem staging -> coalesced stores ----
    __syncthreads();
    __half* s_h = (__half*)smem;                         // [128][PITCH_E]
    const int r_l = warp_m + (lane >> 2);
    const int c_l = (warp_n >> 1) + (lane & 3);
    #pragma unroll
    for (int mi = 0; mi < 4; mi++) {
        int row0 = r_l + mi * 16;
        int row1 = row0 + 8;
        #pragma unroll
        for (int nj = 0; nj < 4; nj++) {
            int cc = c_l + nj * 4;
            float g0 = acc[mi][nj][0], u0 = acc[mi][nj][1];
            float g1 = acc[mi][nj][2], u1 = acc[mi][nj][3];
            float h0 = (g0 / (1.f + expf(-g0))) * u0;
            float h1 = (g1 / (1.f + expf(-g1))) * u1;
            s_h[row0 * PITCH_E + cc] = __float2half(h0);
            s_h[row1 * PITCH_E + cc] = __float2half(h1);
        }
    }
    __syncthreads();
    {
        const int row  = tid >> 1;
        const int half = tid & 1;
        size_t gbase = (size_t)(m0 + row) * F_DIM + n0 + half * 32;
        const uint4* src_h = (const uint4*)(s_h + row * PITCH_E + half * 32);
        uint4* dst_h = (uint4*)(g_h + gbase);
        #pragma unroll
        for (int i = 0; i < 4; i++) dst_h[i] = src_h[i];
    }
}

// ======================= GEMM2: down proj -> g_part (fp16 1-term A) ==========
__global__ __launch_bounds__(256, 2)
void k_gemm2_mma()
{
    extern __shared__ char smem[];
    const uint32_t sb = s2u(smem);
    const int tid = threadIdx.x, lane = tid & 31, wid = tid >> 5;

    const int Mp = g_offp[N_EXP];
    const int m0 = blockIdx.y * 128;
    if (m0 >= Mp) return;
    const int n0 = blockIdx.x * 128;
    int e = 0;
    #pragma unroll
    for (int i = 1; i < N_EXP; i++) if (m0 >= g_offp[i]) e = i;

    const int lr = tid >> 2;
    const int ls = tid & 3;
    const int NC = F_DIM / 32;

    auto load_chunk = [&](int c, int stg) {
        int kc = c * 32;
        uint32_t base = sb + stg * STG2;
        uint32_t ah = base, bh = base + TILE_B;
        #pragma unroll
        for (int i = 0; i < 2; i++) {
            int row = lr + 64 * i;
            uint32_t so = row * 64 + ((ls ^ ((row >> 1) & 3)) << 4);
            size_t go = (size_t)(m0 + row) * F_DIM + kc + ls * 8;
            cp16(ah + so, g_h + go);
        }
        #pragma unroll
        for (int i = 0; i < 2; i++) {
            int rn = lr + 64 * i;
            uint32_t so = rn * 64 + ((ls ^ ((rn >> 1) & 3)) << 4);
            size_t go = ((size_t)e * H_DIM + n0 + rn) * F_DIM + kc + ls * 8;
            cp16(bh + so, g_wd + go);
        }
    };

    load_chunk(0, 0); CP_COMMIT();
    load_chunk(1, 1); CP_COMMIT();

    const int warp_m = (wid & 1) * 64;
    const int warp_n = (wid >> 1) * 32;

    float acc[4][4][4];
    #pragma unroll
    for (int i = 0; i < 4; i++)
        #pragma unroll
        for (int j = 0; j < 4; j++)
            #pragma unroll
            for (int k = 0; k < 4; k++) acc[i][j][k] = 0.f;

    const int quad = lane >> 3, l7 = lane & 7;
    const int a_row = warp_m + (quad & 1) * 8 + l7;
    const int b_row = warp_n + (quad & 1) * 8 + l7;
    const int kq = quad >> 1;
    const int a_swz = (a_row >> 1) & 3;
    const int b_swz = (b_row >> 1) & 3;

    for (int c = 0; c < NC; c++) {
        if (c + 1 < NC) { CP_WAIT1(); } else { CP_WAIT0(); }
        __syncthreads();
        if (c + 2 < NC) { load_chunk(c + 2, (c + 2) % 3); CP_COMMIT(); }

        uint32_t base = sb + (c % 3) * STG2;
        uint32_t ah = base, bh = base + TILE_B;
        #pragma unroll
        for (int ks = 0; ks < 2; ks++) {
            const uint32_t a_seg = (uint32_t)(((ks * 2 + kq) ^ a_swz) << 4);
            const uint32_t b_seg = (uint32_t)(((ks * 2 + kq) ^ b_swz) << 4);
            uint32_t aH[4][4], bH[2][4];
            #pragma unroll
            for (int mi = 0; mi < 4; mi++)
                ldsm4(aH[mi], ah + (a_row + mi * 16) * 64 + a_seg);
            #pragma unroll
            for (int bj = 0; bj < 2; bj++)
                ldsm4(bH[bj], bh + (b_row + bj * 16) * 64 + b_seg);
            #pragma unroll
            for (int mi = 0; mi < 4; mi++)
                #pragma unroll
                for (int nj = 0; nj < 4; nj++) {
                    const uint32_t* f = bH[nj >> 1];
                    int s = nj & 1;
                    mma16816h(acc[mi][nj], aH[mi], f[s], f[s + 2]);
                }
        }
    }

    // epilogue: scale and STORE to per-assignment buffer (exclusive rows)
    const int rbase = m0 + warp_m + (lane >> 2);
    const int cbase = n0 + warp_n + (lane & 3) * 2;
    #pragma unroll
    for (int mi = 0; mi < 4; mi++) {
        int r0 = rbase + mi * 16;
        int r1 = r0 + 8;
        float sc0 = g_scale[r0];
        float sc1 = g_scale[r1];
        float* p0 = g_part + (size_t)r0 * H_DIM;
        float* p1 = g_part + (size_t)r1 * H_DIM;
        #pragma unroll
        for (int nj = 0; nj < 4; nj++) {
            int col = cbase + nj * 8;
            float2 v0 = make_float2(acc[mi][nj][0] * sc0, acc[mi][nj][1] * sc0);
            float2 v1 = make_float2(acc[mi][nj][2] * sc1, acc[mi][nj][3] * sc1);
            *(float2*)(p0 + col) = v0;
            *(float2*)(p1 + col) = v1;
        }
    }
}

// ---------------- kernel 6: combine the two expert contributions -------------
__global__ __launch_bounds__(256)
void k_combine(float* __restrict__ out)
{
    int t = blockIdx.x;
    int tid = threadIdx.x;
    int r0 = g_rowof[t * 2 + 0];
    int r1 = g_rowof[t * 2 + 1];
    float4 a = ((const float4*)(g_part + (size_t)r0 * H_DIM))[tid];
    float4 b = ((const float4*)(g_part + (size_t)r1 * H_DIM))[tid];
    float4 o;
    o.x = a.x + b.x;  o.y = a.y + b.y;
    o.z = a.z + b.z;  o.w = a.w + b.w;
    ((float4*)(out + (size_t)t * H_DIM))[tid] = o;
}

// ---------------- launch ----------------
extern "C" void kernel_launch(void* const* d_in, const int* in_sizes, int n_in,
                              void* d_out, int out_size)
{
    const float* hs  = (const float*)d_in[0];
    const float* lnw = (const float*)d_in[1];
    const float* rw  = (const float*)d_in[2];
    const float* wg  = (const float*)d_in[3];
    const float* wu  = (const float*)d_in[4];
    const float* wd  = (const float*)d_in[5];
    float* out = (float*)d_out;

    cudaFuncSetAttribute(k_gemm1_mma, cudaFuncAttributeMaxDynamicSharedMemorySize, SMEM1);
    cudaFuncSetAttribute(k_gemm2_mma, cudaFuncAttributeMaxDynamicSharedMemorySize, SMEM2);

    void *p_cnt = nullptr, *p_tok = nullptr;
    cudaGetSymbolAddress(&p_cnt, g_cnt);
    cudaGetSymbolAddress(&p_tok, g_tok);

    cudaMemsetAsync(p_cnt, 0, N_EXP * sizeof(int));
    cudaMemsetAsync(p_tok, 0xFF, MP_MAX * sizeof(int));

    // fork: weight prep on side stream, concurrent with activation chain
    cudaStream_t s2;
    cudaStreamCreateWithFlags(&s2, cudaStreamNonBlocking);
    cudaEvent_t eFork, eJoin;
    cudaEventCreateWithFlags(&eFork, cudaEventDisableTiming);
    cudaEventCreateWithFlags(&eJoin, cudaEventDisableTiming);

    cudaEventRecord(eFork, 0);
    cudaStreamWaitEvent(s2, eFork, 0);

    dim3 tb(32, 8);
    dim3 tg(F_DIM / 32, F_DIM / 64, 24);
    k_tsplit_all<<<tg, tb, 0, s2>>>(wg, wu, wd);     // launch 1 (side stream)
    cudaEventRecord(eJoin, s2);

    k_rms_router<<<T_TOK, 256>>>(hs, lnw, rw);        // launch 2 (main)
    k_offscatter<<<1, 256>>>();                       // launch 3 (main)

    cudaStreamWaitEvent(0, eJoin, 0);                 // join before GEMMs

    // launch 4 (ncu capture slot): GEMM1
    dim3 g1(F_DIM / 64, MP_MAX / 128);   // (44, 72)
    k_gemm1_mma<<<g1, 256, SMEM1>>>();

    dim3 g2(H_DIM / 128, MP_MAX / 128);  // (8, 72)
    k_gemm2_mma<<<g2, 256, SMEM2>>>();

    k_combine<<<T_TOK, 256>>>(out);
}

// round 16
// speedup vs baseline: 2.4297x; 1.3748x over previous
#include <cuda_runtime.h>
#include <cuda_fp16.h>
#include <math.h>
#include <stdint.h>

#define T_TOK 4096
#define H_DIM 1024
#define F_DIM 2816
#define N_EXP 8
#define EPS_V 1e-5f
#define MP_MAX 9216

// swizzled smem: 64B rows (32 fp16), seg' = seg ^ ((row>>1)&3)
#define TILE_B 8192                  // 128 rows * 64B
#define STG2  (2 * TILE_B)           // A, B per stage = 16384
#define SMEM_G (3 * STG2)            // 49152 (both GEMMs)
#define PITCH_E 72                   // epilogue staging pitch (fp16 elems)

// ---------------- PTX helpers (sm_80-family, valid on plain sm_103) ---------
__device__ __forceinline__ uint32_t s2u(const void* p) {
    uint32_t a;
    asm("{ .reg .u64 t; cvta.to.shared.u64 t, %1; cvt.u32.u64 %0, t; }" : "=r"(a) : "l"(p));
    return a;
}
__device__ __forceinline__ void ldsm4(uint32_t* r, uint32_t a) {
    asm volatile("ldmatrix.sync.aligned.m8n8.x4.shared.b16 {%0,%1,%2,%3}, [%4];"
        : "=r"(r[0]), "=r"(r[1]), "=r"(r[2]), "=r"(r[3]) : "r"(a));
}
__device__ __forceinline__ void mma16816h(float* d, const uint32_t* a, uint32_t b0, uint32_t b1) {
    asm volatile("mma.sync.aligned.m16n8k16.row.col.f32.f16.f16.f32 "
        "{%0,%1,%2,%3}, {%4,%5,%6,%7}, {%8,%9}, {%0,%1,%2,%3};"
        : "+f"(d[0]), "+f"(d[1]), "+f"(d[2]), "+f"(d[3])
        : "r"(a[0]), "r"(a[1]), "r"(a[2]), "r"(a[3]), "r"(b0), "r"(b1));
}
__device__ __forceinline__ void cp16(uint32_t s, const void* g) {
    asm volatile("{ .reg .u64 gg; cvta.to.global.u64 gg, %1; "
                 "cp.async.cg.shared.global [%0], [gg], 16; }"
                 :: "r"(s), "l"(g) : "memory");
}
#define CP_COMMIT() asm volatile("cp.async.commit_group;" ::: "memory")
#define CP_WAIT1()  asm volatile("cp.async.wait_group 1;" ::: "memory")
#define CP_WAIT0()  asm volatile("cp.async.wait_group 0;" ::: "memory")

// ---------------- scratch (device globals) ----------------
__device__ __half g_x[T_TOK * H_DIM];
__device__ __half g_h[(size_t)MP_MAX * F_DIM];
__device__ __half g_wg[(size_t)N_EXP * F_DIM * H_DIM];
__device__ __half g_wu[(size_t)N_EXP * F_DIM * H_DIM];
__device__ __half g_wd[(size_t)N_EXP * H_DIM * F_DIM];
__device__ float g_part[(size_t)MP_MAX * H_DIM];     // per-assignment scaled output
__device__ int   g_tok[MP_MAX];
__device__ float g_scale[MP_MAX];
__device__ int   g_rowof[T_TOK * 2];                 // token -> assignment rows
__device__ int   g_te[T_TOK * 2];
__device__ float g_tp[T_TOK * 2];
__device__ int   g_cnt[N_EXP];
__device__ int   g_offp[N_EXP + 1];

// ---------------- kernel 1: rmsnorm + router + fp16 cast ----------------
__global__ __launch_bounds__(256)
void k_rms_router(const float* __restrict__ hs,
                  const float* __restrict__ lnw,
                  const float* __restrict__ rw)
{
    int t = blockIdx.x;
    int tid = threadIdx.x;
    int lane = tid & 31, wid = tid >> 5;

    __shared__ float s_x[H_DIM];
    __shared__ float swr[8];
    __shared__ float s_inv;
    __shared__ float sl[8][N_EXP];

    const float4 v = ((const float4*)(hs + (size_t)t * H_DIM))[tid];
    float ss = v.x*v.x + v.y*v.y + v.z*v.z + v.w*v.w;
    #pragma unroll
    for (int o = 16; o; o >>= 1) ss += __shfl_xor_sync(0xffffffffu, ss, o);
    if (lane == 0) swr[wid] = ss;
    __syncthreads();
    if (tid == 0) {
        float s = 0.f;
        #pragma unroll
        for (int i = 0; i < 8; i++) s += swr[i];
        s_inv = rsqrtf(s / (float)H_DIM + EPS_V);
    }
    __syncthreads();
    float inv = s_inv;

    const float4 w = ((const float4*)lnw)[tid];
    float xv[4];
    xv[0] = v.x * inv * w.x;  xv[1] = v.y * inv * w.y;
    xv[2] = v.z * inv * w.z;  xv[3] = v.w * inv * w.w;

    __half hi[4];
    #pragma unroll
    for (int j = 0; j < 4; j++) {
        s_x[tid * 4 + j] = xv[j];
        hi[j] = __float2half(xv[j]);
    }
    ((uint2*)(g_x + (size_t)t * H_DIM))[tid] = *(uint2*)hi;
    __syncthreads();

    {
        const int c = lane & 3, r = lane >> 2;
        const float2* rw2 = (const float2*)rw;
        float2 p = make_float2(0.f, 0.f);
        int ibase = wid * 128 + r;
        #pragma unroll
        for (int k = 0; k < 16; k++) {
            int i = ibase + k * 8;
            float2 w2 = rw2[i * 4 + c];
            float xs = s_x[i];
            p.x += xs * w2.x;
            p.y += xs * w2.y;
        }
        #pragma unroll
        for (int o = 16; o >= 4; o >>= 1) {
            p.x += __shfl_xor_sync(0xffffffffu, p.x, o);
            p.y += __shfl_xor_sync(0xffffffffu, p.y, o);
        }
        if (lane < 4) {
            sl[wid][2 * c]     = p.x;
            sl[wid][2 * c + 1] = p.y;
        }
    }
    __syncthreads();

    if (tid == 0) {
        float l[N_EXP];
        #pragma unroll
        for (int e = 0; e < N_EXP; e++) {
            float s = 0.f;
            #pragma unroll
            for (int w2 = 0; w2 < 8; w2++) s += sl[w2][e];
            l[e] = s;
        }
        float m = l[0];
        #pragma unroll
        for (int e = 1; e < N_EXP; e++) m = fmaxf(m, l[e]);
        float den = 0.f, pr[N_EXP];
        #pragma unroll
        for (int e = 0; e < N_EXP; e++) { pr[e] = expf(l[e] - m); den += pr[e]; }
        float rden = 1.f / den;
        #pragma unroll
        for (int e = 0; e < N_EXP; e++) pr[e] *= rden;

        int i1 = 0;
        #pragma unroll
        for (int e = 1; e < N_EXP; e++) if (pr[e] > pr[i1]) i1 = e;
        int i2 = (i1 == 0) ? 1 : 0;
        #pragma unroll
        for (int e = 0; e < N_EXP; e++) if (e != i1 && pr[e] > pr[i2]) i2 = e;

        g_te[t * 2 + 0] = i1;  g_tp[t * 2 + 0] = pr[i1];
        g_te[t * 2 + 1] = i2;  g_tp[t * 2 + 1] = pr[i2];
        atomicAdd(&g_cnt[i1], 1);
        atomicAdd(&g_cnt[i2], 1);
    }
}

// ---------------- kernel 2: ALL weight transposes (single fp16) --------------
__global__ __launch_bounds__(256)
void k_tsplit_all(const float* __restrict__ wg,
                  const float* __restrict__ wu,
                  const float* __restrict__ wd)
{
    int z = blockIdx.z;
    const float* src;
    __half* dst;
    int R, C, e;
    if (z < 8)       { src = wg; dst = g_wg; R = H_DIM; C = F_DIM; e = z; }
    else if (z < 16) { src = wu; dst = g_wu; R = H_DIM; C = F_DIM; e = z - 8; }
    else             { src = wd; dst = g_wd; R = F_DIM; C = H_DIM; e = z - 16; }

    int c0 = blockIdx.x * 32, r0 = blockIdx.y * 64;
    if (c0 >= C || r0 >= R) return;

    __shared__ float t[64][33];
    const float* s = src + (size_t)e * R * C;
    size_t dbase = (size_t)e * R * C;
    int tx = threadIdx.x, ty = threadIdx.y;
    #pragma unroll
    for (int i = 0; i < 8; i++) {
        int r = ty + i * 8;
        t[r][tx] = s[(size_t)(r0 + r) * C + c0 + tx];
    }
    __syncthreads();
    #pragma unroll
    for (int i = 0; i < 4; i++) {
        int c = ty + i * 8;
        __half h0 = __float2half(t[2 * tx][c]);
        __half h1 = __float2half(t[2 * tx + 1][c]);
        uint32_t uh = (uint32_t)__half_as_ushort(h0) | ((uint32_t)__half_as_ushort(h1) << 16);
        size_t o = dbase + (size_t)(c0 + c) * R + r0 + 2 * tx;
        *(uint32_t*)(dst + o) = uh;
    }
}

// ---------------- kernel 3: offsets + scatter (single block) -----------------
__global__ __launch_bounds__(256)
void k_offscatter()
{
    __shared__ int s_fill[N_EXP];
    int tid = threadIdx.x;
    if (tid == 0) {
        int acc = 0;
        #pragma unroll
        for (int e = 0; e < N_EXP; e++) {
            g_offp[e]  = acc;
            s_fill[e]  = acc;
            acc += (g_cnt[e] + 127) & ~127;
        }
        g_offp[N_EXP] = acc;
    }
    __syncthreads();
    for (int t = tid; t < T_TOK; t += 256) {
        #pragma unroll
        for (int k = 0; k < 2; k++) {
            int e = g_te[t * 2 + k];
            int r = atomicAdd(&s_fill[e], 1);
            g_tok[r]     = t;
            g_scale[r]   = g_tp[t * 2 + k];
            g_rowof[t * 2 + k] = r;
        }
    }
}

// ======================= GEMM1: gate/up + SiLU (fp16 single) =================
__global__ __launch_bounds__(256, 2)
void k_gemm1_mma()
{
    extern __shared__ char smem[];
    const uint32_t sb = s2u(smem);
    const int tid = threadIdx.x, lane = tid & 31, wid = tid >> 5;

    const int Mp = g_offp[N_EXP];
    const int m0 = blockIdx.y * 128;
    if (m0 >= Mp) return;
    const int n0 = blockIdx.x * 64;
    int e = 0;
    #pragma unroll
    for (int i = 1; i < N_EXP; i++) if (m0 >= g_offp[i]) e = i;

    __shared__ int s_tok[128];
    if (tid < 128) {
        int tok = g_tok[m0 + tid];
        s_tok[tid] = (tok >= 0) ? tok : 0;
    }
    __syncthreads();

    const int lr = tid >> 2;
    const int ls = tid & 3;
    const int NC = H_DIM / 32;

    auto load_chunk = [&](int c, int stg) {
        int kc = c * 32;
        uint32_t base = sb + stg * STG2;
        uint32_t ah = base, bh = base + TILE_B;
        #pragma unroll
        for (int i = 0; i < 2; i++) {
            int row = lr + 64 * i;
            uint32_t so = row * 64 + ((ls ^ ((row >> 1) & 3)) << 4);
            size_t go = (size_t)s_tok[row] * H_DIM + kc + ls * 8;
            cp16(ah + so, g_x + go);
        }
        #pragma unroll
        for (int i = 0; i < 2; i++) {
            int rn = lr + 64 * i;
            uint32_t so = rn * 64 + ((ls ^ ((rn >> 1) & 3)) << 4);
            int col = n0 + (rn >> 1);
            size_t go = ((size_t)e * F_DIM + col) * H_DIM + kc + ls * 8;
            const __half* W = (rn & 1) ? g_wu : g_wg;
            cp16(bh + so, W + go);
        }
    };

    load_chunk(0, 0); CP_COMMIT();
    load_chunk(1, 1); CP_COMMIT();

    const int warp_m = (wid & 1) * 64;
    const int warp_n = (wid >> 1) * 32;

    float acc[4][4][4];
    #pragma unroll
    for (int i = 0; i < 4; i++)
        #pragma unroll
        for (int j = 0; j < 4; j++)
            #pragma unroll
            for (int k = 0; k < 4; k++) acc[i][j][k] = 0.f;

    const int quad = lane >> 3, l7 = lane & 7;
    const int a_row = warp_m + (quad & 1) * 8 + l7;
    const int b_row = warp_n + (quad & 1) * 8 + l7;
    const int kq = quad >> 1;
    const int a_swz = (a_row >> 1) & 3;
    const int b_swz = (b_row >> 1) & 3;

    for (int c = 0; c < NC; c++) {
        if (c + 1 < NC) { CP_WAIT1(); } else { CP_WAIT0(); }
        __syncthreads();
        if (c + 2 < NC) { load_chunk(c + 2, (c + 2) % 3); CP_COMMIT(); }

        uint32_t base = sb + (c % 3) * STG2;
        uint32_t ah = base, bh = base + TILE_B;
        #pragma unroll
        for (int ks = 0; ks < 2; ks++) {
            const uint32_t a_seg = (uint32_t)(((ks * 2 + kq) ^ a_swz) << 4);
            const uint32_t b_seg = (uint32_t)(((ks * 2 + kq) ^ b_swz) << 4);
            uint32_t aH[4][4], bH[2][4];
            #pragma unroll
            for (int mi = 0; mi < 4; mi++)
                ldsm4(aH[mi], ah + (a_row + mi * 16) * 64 + a_seg);
            #pragma unroll
            for (int bj = 0; bj < 2; bj++)
                ldsm4(bH[bj], bh + (b_row + bj * 16) * 64 + b_seg);
            #pragma unroll
            for (int mi = 0; mi < 4; mi++)
                #pragma unroll
                for (int nj = 0; nj < 4; nj++) {
                    const uint32_t* f = bH[nj >> 1];
                    int s = nj & 1;
                    mma16816h(acc[mi][nj], aH[mi], f[s], f[s + 2]);
                }
        }
    }

    // ---- staged epilogue: silu(g)*u -> smem staging -> coalesced stores ----
    __syncthreads();
    __half* s_h = (__half*)smem;                         // [128][PITCH_E]
    const int r_l = warp_m + (lane >> 2);
    const int c_l = (warp_n >> 1) + (lane & 3);
    #pragma unroll
    for (int mi = 0; mi < 4; mi++) {
        int row0 = r_l + mi * 16;
        int row1 = row0 + 8;
        #pragma unroll
        for (int nj = 0; nj < 4; nj++) {
            int cc = c_l + nj * 4;
            float g0 = acc[mi][nj][0], u0 = acc[mi][nj][1];
            float g1 = acc[mi][nj][2], u1 = acc[mi][nj][3];
            float h0 = (g0 / (1.f + expf(-g0))) * u0;
            float h1 = (g1 / (1.f + expf(-g1))) * u1;
            s_h[row0 * PITCH_E + cc] = __float2half(h0);
            s_h[row1 * PITCH_E + cc] = __float2half(h1);
        }
    }
    __syncthreads();
    {
        const int row  = tid >> 1;
        const int half = tid & 1;
        size_t gbase = (size_t)(m0 + row) * F_DIM + n0 + half * 32;
        const uint4* src_h = (const uint4*)(s_h + row * PITCH_E + half * 32);
        uint4* dst_h = (uint4*)(g_h + gbase);
        #pragma unroll
        for (int i = 0; i < 4; i++) dst_h[i] = src_h[i];
    }
}

// ======================= GEMM2: down proj -> g_part (fp16 single) ============
__global__ __launch_bounds__(256, 2)
void k_gemm2_mma()
{
    extern __shared__ char smem[];
    const uint32_t sb = s2u(smem);
    const int tid = threadIdx.x, lane = tid & 31, wid = tid >> 5;

    const int Mp = g_offp[N_EXP];
    const int m0 = blockIdx.y * 128;
    if (m0 >= Mp) return;
    const int n0 = blockIdx.x * 128;
    int e = 0;
    #pragma unroll
    for (int i = 1; i < N_EXP; i++) if (m0 >= g_offp[i]) e = i;

    const int lr = tid >> 2;
    const int ls = tid & 3;
    const int NC = F_DIM / 32;

    auto load_chunk = [&](int c, int stg) {
        int kc = c * 32;
        uint32_t base = sb + stg * STG2;
        uint32_t ah = base, bh = base + TILE_B;
        #pragma unroll
        for (int i = 0; i < 2; i++) {
            int row = lr + 64 * i;
            uint32_t so = row * 64 + ((ls ^ ((row >> 1) & 3)) << 4);
            size_t go = (size_t)(m0 + row) * F_DIM + kc + ls * 8;
            cp16(ah + so, g_h + go);
        }
        #pragma unroll
        for (int i = 0; i < 2; i++) {
            int rn = lr + 64 * i;
            uint32_t so = rn * 64 + ((ls ^ ((rn >> 1) & 3)) << 4);
            size_t go = ((size_t)e * H_DIM + n0 + rn) * F_DIM + kc + ls * 8;
            cp16(bh + so, g_wd + go);
        }
    };

    load_chunk(0, 0); CP_COMMIT();
    load_chunk(1, 1); CP_COMMIT();

    const int warp_m = (wid & 1) * 64;
    const int warp_n = (wid >> 1) * 32;

    float acc[4][4][4];
    #pragma unroll
    for (int i = 0; i < 4; i++)
        #pragma unroll
        for (int j = 0; j < 4; j++)
            #pragma unroll
            for (int k = 0; k < 4; k++) acc[i][j][k] = 0.f;

    const int quad = lane >> 3, l7 = lane & 7;
    const int a_row = warp_m + (quad & 1) * 8 + l7;
    const int b_row = warp_n + (quad & 1) * 8 + l7;
    const int kq = quad >> 1;
    const int a_swz = (a_row >> 1) & 3;
    const int b_swz = (b_row >> 1) & 3;

    for (int c = 0; c < NC; c++) {
        if (c + 1 < NC) { CP_WAIT1(); } else { CP_WAIT0(); }
        __syncthreads();
        if (c + 2 < NC) { load_chunk(c + 2, (c + 2) % 3); CP_COMMIT(); }

        uint32_t base = sb + (c % 3) * STG2;
        uint32_t ah = base, bh = base + TILE_B;
        #pragma unroll
        for (int ks = 0; ks < 2; ks++) {
            const uint32_t a_seg = (uint32_t)(((ks * 2 + kq) ^ a_swz) << 4);
            const uint32_t b_seg = (uint32_t)(((ks * 2 + kq) ^ b_swz) << 4);
            uint32_t aH[4][4], bH[2][4];
            #pragma unroll
            for (int mi = 0; mi < 4; mi++)
                ldsm4(aH[mi], ah + (a_row + mi * 16) * 64 + a_seg);
            #pragma unroll
            for (int bj = 0; bj < 2; bj++)
                ldsm4(bH[bj], bh + (b_row + bj * 16) * 64 + b_seg);
            #pragma unroll
            for (int mi = 0; mi < 4; mi++)
                #pragma unroll
                for (int nj = 0; nj < 4; nj++) {
                    const uint32_t* f = bH[nj >> 1];
                    int s = nj & 1;
                    mma16816h(acc[mi][nj], aH[mi], f[s], f[s + 2]);
                }
        }
    }

    // epilogue: scale and STORE to per-assignment buffer (exclusive rows)
    const int rbase = m0 + warp_m + (lane >> 2);
    const int cbase = n0 + warp_n + (lane & 3) * 2;
    #pragma unroll
    for (int mi = 0; mi < 4; mi++) {
        int r0 = rbase + mi * 16;
        int r1 = r0 + 8;
        float sc0 = g_scale[r0];
        float sc1 = g_scale[r1];
        float* p0 = g_part + (size_t)r0 * H_DIM;
        float* p1 = g_part + (size_t)r1 * H_DIM;
        #pragma unroll
        for (int nj = 0; nj < 4; nj++) {
            int col = cbase + nj * 8;
            float2 v0 = make_float2(acc[mi][nj][0] * sc0, acc[mi][nj][1] * sc0);
            float2 v1 = make_float2(acc[mi][nj][2] * sc1, acc[mi][nj][3] * sc1);
            *(float2*)(p0 + col) = v0;
            *(float2*)(p1 + col) = v1;
        }
    }
}

// ---------------- kernel 6: combine the two expert contributions -------------
__global__ __launch_bounds__(256)
void k_combine(float* __restrict__ out)
{
    int t = blockIdx.x;
    int tid = threadIdx.x;
    int r0 = g_rowof[t * 2 + 0];
    int r1 = g_rowof[t * 2 + 1];
    float4 a = ((const float4*)(g_part + (size_t)r0 * H_DIM))[tid];
    float4 b = ((const float4*)(g_part + (size_t)r1 * H_DIM))[tid];
    float4 o;
    o.x = a.x + b.x;  o.y = a.y + b.y;
    o.z = a.z + b.z;  o.w = a.w + b.w;
    ((float4*)(out + (size_t)t * H_DIM))[tid] = o;
}

// ---------------- launch ----------------
extern "C" void kernel_launch(void* const* d_in, const int* in_sizes, int n_in,
                              void* d_out, int out_size)
{
    const float* hs  = (const float*)d_in[0];
    const float* lnw = (const float*)d_in[1];
    const float* rw  = (const float*)d_in[2];
    const float* wg  = (const float*)d_in[3];
    const float* wu  = (const float*)d_in[4];
    const float* wd  = (const float*)d_in[5];
    float* out = (float*)d_out;

    cudaFuncSetAttribute(k_gemm1_mma, cudaFuncAttributeMaxDynamicSharedMemorySize, SMEM_G);
    cudaFuncSetAttribute(k_gemm2_mma, cudaFuncAttributeMaxDynamicSharedMemorySize, SMEM_G);

    void *p_cnt = nullptr, *p_tok = nullptr;
    cudaGetSymbolAddress(&p_cnt, g_cnt);
    cudaGetSymbolAddress(&p_tok, g_tok);

    cudaMemsetAsync(p_cnt, 0, N_EXP * sizeof(int));
    cudaMemsetAsync(p_tok, 0xFF, MP_MAX * sizeof(int));

    // fork: weight prep on side stream, concurrent with activation chain
    cudaStream_t s2;
    cudaStreamCreateWithFlags(&s2, cudaStreamNonBlocking);
    cudaEvent_t eFork, eJoin;
    cudaEventCreateWithFlags(&eFork, cudaEventDisableTiming);
    cudaEventCreateWithFlags(&eJoin, cudaEventDisableTiming);

    cudaEventRecord(eFork, 0);
    cudaStreamWaitEvent(s2, eFork, 0);

    dim3 tb(32, 8);
    dim3 tg(F_DIM / 32, F_DIM / 64, 24);
    k_tsplit_all<<<tg, tb, 0, s2>>>(wg, wu, wd);     // launch 1 (side stream)
    cudaEventRecord(eJoin, s2);

    k_rms_router<<<T_TOK, 256>>>(hs, lnw, rw);        // launch 2 (main)
    k_offscatter<<<1, 256>>>();                       // launch 3 (main)

    cudaStreamWaitEvent(0, eJoin, 0);                 // join before GEMMs

    // launch 4 (ncu capture slot): GEMM1
    dim3 g1(F_DIM / 64, MP_MAX / 128);   // (44, 72)
    k_gemm1_mma<<<g1, 256, SMEM_G>>>();

    dim3 g2(H_DIM / 128, MP_MAX / 128);  // (8, 72)
    k_gemm2_mma<<<g2, 256, SMEM_G>>>();

    k_combine<<<T_TOK, 256>>>(out);
}

// round 17
// speedup vs baseline: 2.6639x; 1.0964x over previous
#include <cuda_runtime.h>
#include <cuda_fp16.h>
#include <math.h>
#include <stdint.h>

#define T_TOK 4096
#define H_DIM 1024
#define F_DIM 2816
#define N_EXP 8
#define EPS_V 1e-5f
#define MP_MAX 9216

// SW128 swizzled smem: 128B rows (64 fp16), seg' = seg ^ (row&7)
#define TILE_B 16384                 // 128 rows * 128B
#define STG   (2 * TILE_B)           // A, B per stage = 32768
#define SMEM_G (3 * STG)             // 98304 -> 2 CTAs/SM
#define PITCH_E 72                   // epilogue staging pitch (fp16 elems)

// ---------------- PTX helpers (sm_80-family, valid on plain sm_103) ---------
__device__ __forceinline__ uint32_t s2u(const void* p) {
    uint32_t a;
    asm("{ .reg .u64 t; cvta.to.shared.u64 t, %1; cvt.u32.u64 %0, t; }" : "=r"(a) : "l"(p));
    return a;
}
__device__ __forceinline__ void ldsm4(uint32_t* r, uint32_t a) {
    asm volatile("ldmatrix.sync.aligned.m8n8.x4.shared.b16 {%0,%1,%2,%3}, [%4];"
        : "=r"(r[0]), "=r"(r[1]), "=r"(r[2]), "=r"(r[3]) : "r"(a));
}
__device__ __forceinline__ void mma16816h(float* d, const uint32_t* a, uint32_t b0, uint32_t b1) {
    asm volatile("mma.sync.aligned.m16n8k16.row.col.f32.f16.f16.f32 "
        "{%0,%1,%2,%3}, {%4,%5,%6,%7}, {%8,%9}, {%0,%1,%2,%3};"
        : "+f"(d[0]), "+f"(d[1]), "+f"(d[2]), "+f"(d[3])
        : "r"(a[0]), "r"(a[1]), "r"(a[2]), "r"(a[3]), "r"(b0), "r"(b1));
}
__device__ __forceinline__ void cp16(uint32_t s, const void* g) {
    asm volatile("{ .reg .u64 gg; cvta.to.global.u64 gg, %1; "
                 "cp.async.cg.shared.global [%0], [gg], 16; }"
                 :: "r"(s), "l"(g) : "memory");
}
#define CP_COMMIT() asm volatile("cp.async.commit_group;" ::: "memory")
#define CP_WAIT1()  asm volatile("cp.async.wait_group 1;" ::: "memory")
#define CP_WAIT0()  asm volatile("cp.async.wait_group 0;" ::: "memory")

// ---------------- scratch (device globals) ----------------
__device__ __half g_x[T_TOK * H_DIM];
__device__ __half g_h[(size_t)MP_MAX * F_DIM];
__device__ __half g_wg[(size_t)N_EXP * F_DIM * H_DIM];
__device__ __half g_wu[(size_t)N_EXP * F_DIM * H_DIM];
__device__ __half g_wd[(size_t)N_EXP * H_DIM * F_DIM];
__device__ float g_part[(size_t)MP_MAX * H_DIM];
__device__ int   g_tok[MP_MAX];
__device__ float g_scale[MP_MAX];
__device__ int   g_rowof[T_TOK * 2];
__device__ int   g_te[T_TOK * 2];
__device__ float g_tp[T_TOK * 2];
__device__ int   g_cnt[N_EXP];
__device__ int   g_offp[N_EXP + 1];

// ---------------- kernel 1: rmsnorm + router + fp16 cast ----------------
__global__ __launch_bounds__(256)
void k_rms_router(const float* __restrict__ hs,
                  const float* __restrict__ lnw,
                  const float* __restrict__ rw)
{
    int t = blockIdx.x;
    int tid = threadIdx.x;
    int lane = tid & 31, wid = tid >> 5;

    __shared__ float s_x[H_DIM];
    __shared__ float swr[8];
    __shared__ float s_inv;
    __shared__ float sl[8][N_EXP];

    const float4 v = ((const float4*)(hs + (size_t)t * H_DIM))[tid];
    float ss = v.x*v.x + v.y*v.y + v.z*v.z + v.w*v.w;
    #pragma unroll
    for (int o = 16; o; o >>= 1) ss += __shfl_xor_sync(0xffffffffu, ss, o);
    if (lane == 0) swr[wid] = ss;
    __syncthreads();
    if (tid == 0) {
        float s = 0.f;
        #pragma unroll
        for (int i = 0; i < 8; i++) s += swr[i];
        s_inv = rsqrtf(s / (float)H_DIM + EPS_V);
    }
    __syncthreads();
    float inv = s_inv;

    const float4 w = ((const float4*)lnw)[tid];
    float xv[4];
    xv[0] = v.x * inv * w.x;  xv[1] = v.y * inv * w.y;
    xv[2] = v.z * inv * w.z;  xv[3] = v.w * inv * w.w;

    __half hi[4];
    #pragma unroll
    for (int j = 0; j < 4; j++) {
        s_x[tid * 4 + j] = xv[j];
        hi[j] = __float2half(xv[j]);
    }
    ((uint2*)(g_x + (size_t)t * H_DIM))[tid] = *(uint2*)hi;
    __syncthreads();

    {
        const int c = lane & 3, r = lane >> 2;
        const float2* rw2 = (const float2*)rw;
        float2 p = make_float2(0.f, 0.f);
        int ibase = wid * 128 + r;
        #pragma unroll
        for (int k = 0; k < 16; k++) {
            int i = ibase + k * 8;
            float2 w2 = rw2[i * 4 + c];
            float xs = s_x[i];
            p.x += xs * w2.x;
            p.y += xs * w2.y;
        }
        #pragma unroll
        for (int o = 16; o >= 4; o >>= 1) {
            p.x += __shfl_xor_sync(0xffffffffu, p.x, o);
            p.y += __shfl_xor_sync(0xffffffffu, p.y, o);
        }
        if (lane < 4) {
            sl[wid][2 * c]     = p.x;
            sl[wid][2 * c + 1] = p.y;
        }
    }
    __syncthreads();

    if (tid == 0) {
        float l[N_EXP];
        #pragma unroll
        for (int e = 0; e < N_EXP; e++) {
            float s = 0.f;
            #pragma unroll
            for (int w2 = 0; w2 < 8; w2++) s += sl[w2][e];
            l[e] = s;
        }
        float m = l[0];
        #pragma unroll
        for (int e = 1; e < N_EXP; e++) m = fmaxf(m, l[e]);
        float den = 0.f, pr[N_EXP];
        #pragma unroll
        for (int e = 0; e < N_EXP; e++) { pr[e] = expf(l[e] - m); den += pr[e]; }
        float rden = 1.f / den;
        #pragma unroll
        for (int e = 0; e < N_EXP; e++) pr[e] *= rden;

        int i1 = 0;
        #pragma unroll
        for (int e = 1; e < N_EXP; e++) if (pr[e] > pr[i1]) i1 = e;
        int i2 = (i1 == 0) ? 1 : 0;
        #pragma unroll
        for (int e = 0; e < N_EXP; e++) if (e != i1 && pr[e] > pr[i2]) i2 = e;

        g_te[t * 2 + 0] = i1;  g_tp[t * 2 + 0] = pr[i1];
        g_te[t * 2 + 1] = i2;  g_tp[t * 2 + 1] = pr[i2];
        atomicAdd(&g_cnt[i1], 1);
        atomicAdd(&g_cnt[i2], 1);
    }
}

// ---------------- kernel 2: ALL weight transposes (single fp16) --------------
__global__ __launch_bounds__(256)
void k_tsplit_all(const float* __restrict__ wg,
                  const float* __restrict__ wu,
                  const float* __restrict__ wd)
{
    int z = blockIdx.z;
    const float* src;
    __half* dst;
    int R, C, e;
    if (z < 8)       { src = wg; dst = g_wg; R = H_DIM; C = F_DIM; e = z; }
    else if (z < 16) { src = wu; dst = g_wu; R = H_DIM; C = F_DIM; e = z - 8; }
    else             { src = wd; dst = g_wd; R = F_DIM; C = H_DIM; e = z - 16; }

    int c0 = blockIdx.x * 32, r0 = blockIdx.y * 64;
    if (c0 >= C || r0 >= R) return;

    __shared__ float t[64][33];
    const float* s = src + (size_t)e * R * C;
    size_t dbase = (size_t)e * R * C;
    int tx = threadIdx.x, ty = threadIdx.y;
    #pragma unroll
    for (int i = 0; i < 8; i++) {
        int r = ty + i * 8;
        t[r][tx] = s[(size_t)(r0 + r) * C + c0 + tx];
    }
    __syncthreads();
    #pragma unroll
    for (int i = 0; i < 4; i++) {
        int c = ty + i * 8;
        __half h0 = __float2half(t[2 * tx][c]);
        __half h1 = __float2half(t[2 * tx + 1][c]);
        uint32_t uh = (uint32_t)__half_as_ushort(h0) | ((uint32_t)__half_as_ushort(h1) << 16);
        size_t o = dbase + (size_t)(c0 + c) * R + r0 + 2 * tx;
        *(uint32_t*)(dst + o) = uh;
    }
}

// ---------------- kernel 3: offsets + scatter (single block) -----------------
__global__ __launch_bounds__(256)
void k_offscatter()
{
    __shared__ int s_fill[N_EXP];
    int tid = threadIdx.x;
    if (tid == 0) {
        int acc = 0;
        #pragma unroll
        for (int e = 0; e < N_EXP; e++) {
            g_offp[e]  = acc;
            s_fill[e]  = acc;
            acc += (g_cnt[e] + 127) & ~127;
        }
        g_offp[N_EXP] = acc;
    }
    __syncthreads();
    for (int t = tid; t < T_TOK; t += 256) {
        #pragma unroll
        for (int k = 0; k < 2; k++) {
            int e = g_te[t * 2 + k];
            int r = atomicAdd(&s_fill[e], 1);
            g_tok[r]     = t;
            g_scale[r]   = g_tp[t * 2 + k];
            g_rowof[t * 2 + k] = r;
        }
    }
}

// ======================= GEMM1: gate/up + SiLU (fp16, BK=64) =================
__global__ __launch_bounds__(256, 2)
void k_gemm1_mma()
{
    extern __shared__ char smem[];
    const uint32_t sb = s2u(smem);
    const int tid = threadIdx.x, lane = tid & 31, wid = tid >> 5;

    const int Mp = g_offp[N_EXP];
    const int m0 = blockIdx.y * 128;
    if (m0 >= Mp) return;
    const int n0 = blockIdx.x * 64;
    int e = 0;
    #pragma unroll
    for (int i = 1; i < N_EXP; i++) if (m0 >= g_offp[i]) e = i;

    __shared__ int s_tok[128];
    if (tid < 128) {
        int tok = g_tok[m0 + tid];
        s_tok[tid] = (tok >= 0) ? tok : 0;
    }
    __syncthreads();

    const int lr = tid >> 3;                  // smem row 0..31 (+32k)
    const int ls = tid & 7;                   // 16B segment 0..7
    const int NC = H_DIM / 64;                // 16 chunks

    auto load_chunk = [&](int c, int stg) {
        int kc = c * 64;
        uint32_t base = sb + stg * STG;
        uint32_t ah = base, bh = base + TILE_B;
        #pragma unroll
        for (int i = 0; i < 4; i++) {
            int row = lr + 32 * i;
            uint32_t so = row * 128 + ((ls ^ (row & 7)) << 4);
            size_t go = (size_t)s_tok[row] * H_DIM + kc + ls * 8;
            cp16(ah + so, g_x + go);
        }
        #pragma unroll
        for (int i = 0; i < 4; i++) {
            int rn = lr + 32 * i;
            uint32_t so = rn * 128 + ((ls ^ (rn & 7)) << 4);
            int col = n0 + (rn >> 1);
            size_t go = ((size_t)e * F_DIM + col) * H_DIM + kc + ls * 8;
            const __half* W = (rn & 1) ? g_wu : g_wg;
            cp16(bh + so, W + go);
        }
    };

    load_chunk(0, 0); CP_COMMIT();
    load_chunk(1, 1); CP_COMMIT();

    const int warp_m = (wid & 1) * 64;
    const int warp_n = (wid >> 1) * 32;

    float acc[4][4][4];
    #pragma unroll
    for (int i = 0; i < 4; i++)
        #pragma unroll
        for (int j = 0; j < 4; j++)
            #pragma unroll
            for (int k = 0; k < 4; k++) acc[i][j][k] = 0.f;

    const int quad = lane >> 3, l7 = lane & 7;
    const int a_row = warp_m + (quad & 1) * 8 + l7;
    const int b_row = warp_n + (quad & 1) * 8 + l7;
    const int kq = quad >> 1;
    const int a_swz = a_row & 7;
    const int b_swz = b_row & 7;

    for (int c = 0; c < NC; c++) {
        if (c + 1 < NC) { CP_WAIT1(); } else { CP_WAIT0(); }
        __syncthreads();
        if (c + 2 < NC) { load_chunk(c + 2, (c + 2) % 3); CP_COMMIT(); }

        uint32_t base = sb + (c % 3) * STG;
        uint32_t ah = base, bh = base + TILE_B;
        #pragma unroll
        for (int ks = 0; ks < 4; ks++) {
            const uint32_t a_seg = (uint32_t)(((ks * 2 + kq) ^ a_swz) << 4);
            const uint32_t b_seg = (uint32_t)(((ks * 2 + kq) ^ b_swz) << 4);
            uint32_t aH[4][4], bH[2][4];
            #pragma unroll
            for (int mi = 0; mi < 4; mi++)
                ldsm4(aH[mi], ah + (a_row + mi * 16) * 128 + a_seg);
            #pragma unroll
            for (int bj = 0; bj < 2; bj++)
                ldsm4(bH[bj], bh + (b_row + bj * 16) * 128 + b_seg);
            #pragma unroll
            for (int mi = 0; mi < 4; mi++)
                #pragma unroll
                for (int nj = 0; nj < 4; nj++) {
                    const uint32_t* f = bH[nj >> 1];
                    int s = nj & 1;
                    mma16816h(acc[mi][nj], aH[mi], f[s], f[s + 2]);
                }
        }
    }

    // ---- staged epilogue: silu(g)*u -> smem staging -> coalesced stores ----
    __syncthreads();
    __half* s_h = (__half*)smem;                         // [128][PITCH_E]
    const int r_l = warp_m + (lane >> 2);
    const int c_l = (warp_n >> 1) + (lane & 3);
    #pragma unroll
    for (int mi = 0; mi < 4; mi++) {
        int row0 = r_l + mi * 16;
        int row1 = row0 + 8;
        #pragma unroll
        for (int nj = 0; nj < 4; nj++) {
            int cc = c_l + nj * 4;
            float g0 = acc[mi][nj][0], u0 = acc[mi][nj][1];
            float g1 = acc[mi][nj][2], u1 = acc[mi][nj][3];
            float h0 = (g0 / (1.f + expf(-g0))) * u0;
            float h1 = (g1 / (1.f + expf(-g1))) * u1;
            s_h[row0 * PITCH_E + cc] = __float2half(h0);
            s_h[row1 * PITCH_E + cc] = __float2half(h1);
        }
    }
    __syncthreads();
    {
        const int row  = tid >> 1;
        const int half = tid & 1;
        size_t gbase = (size_t)(m0 + row) * F_DIM + n0 + half * 32;
        const uint4* src_h = (const uint4*)(s_h + row * PITCH_E + half * 32);
        uint4* dst_h = (uint4*)(g_h + gbase);
        #pragma unroll
        for (int i = 0; i < 4; i++) dst_h[i] = src_h[i];
    }
}

// ======================= GEMM2: down proj -> g_part (fp16, BK=64) ============
__global__ __launch_bounds__(256, 2)
void k_gemm2_mma()
{
    extern __shared__ char smem[];
    const uint32_t sb = s2u(smem);
    const int tid = threadIdx.x, lane = tid & 31, wid = tid >> 5;

    const int Mp = g_offp[N_EXP];
    const int m0 = blockIdx.y * 128;
    if (m0 >= Mp) return;
    const int n0 = blockIdx.x * 128;
    int e = 0;
    #pragma unroll
    for (int i = 1; i < N_EXP; i++) if (m0 >= g_offp[i]) e = i;

    const int lr = tid >> 3;
    const int ls = tid & 7;
    const int NC = F_DIM / 64;                // 44 chunks

    auto load_chunk = [&](int c, int stg) {
        int kc = c * 64;
        uint32_t base = sb + stg * STG;
        uint32_t ah = base, bh = base + TILE_B;
        #pragma unroll
        for (int i = 0; i < 4; i++) {
            int row = lr + 32 * i;
            uint32_t so = row * 128 + ((ls ^ (row & 7)) << 4);
            size_t go = (size_t)(m0 + row) * F_DIM + kc + ls * 8;
            cp16(ah + so, g_h + go);
        }
        #pragma unroll
        for (int i = 0; i < 4; i++) {
            int rn = lr + 32 * i;
            uint32_t so = rn * 128 + ((ls ^ (rn & 7)) << 4);
            size_t go = ((size_t)e * H_DIM + n0 + rn) * F_DIM + kc + ls * 8;
            cp16(bh + so, g_wd + go);
        }
    };

    load_chunk(0, 0); CP_COMMIT();
    load_chunk(1, 1); CP_COMMIT();

    const int warp_m = (wid & 1) * 64;
    const int warp_n = (wid >> 1) * 32;

    float acc[4][4][4];
    #pragma unroll
    for (int i = 0; i < 4; i++)
        #pragma unroll
        for (int j = 0; j < 4; j++)
            #pragma unroll
            for (int k = 0; k < 4; k++) acc[i][j][k] = 0.f;

    const int quad = lane >> 3, l7 = lane & 7;
    const int a_row = warp_m + (quad & 1) * 8 + l7;
    const int b_row = warp_n + (quad & 1) * 8 + l7;
    const int kq = quad >> 1;
    const int a_swz = a_row & 7;
    const int b_swz = b_row & 7;

    for (int c = 0; c < NC; c++) {
        if (c + 1 < NC) { CP_WAIT1(); } else { CP_WAIT0(); }
        __syncthreads();
        if (c + 2 < NC) { load_chunk(c + 2, (c + 2) % 3); CP_COMMIT(); }

        uint32_t base = sb + (c % 3) * STG;
        uint32_t ah = base, bh = base + TILE_B;
        #pragma unroll
        for (int ks = 0; ks < 4; ks++) {
            const uint32_t a_seg = (uint32_t)(((ks * 2 + kq) ^ a_swz) << 4);
            const uint32_t b_seg = (uint32_t)(((ks * 2 + kq) ^ b_swz) << 4);
            uint32_t aH[4][4], bH[2][4];
            #pragma unroll
            for (int mi = 0; mi < 4; mi++)
                ldsm4(aH[mi], ah + (a_row + mi * 16) * 128 + a_seg);
            #pragma unroll
            for (int bj = 0; bj < 2; bj++)
                ldsm4(bH[bj], bh + (b_row + bj * 16) * 128 + b_seg);
            #pragma unroll
            for (int mi = 0; mi < 4; mi++)
                #pragma unroll
                for (int nj = 0; nj < 4; nj++) {
                    const uint32_t* f = bH[nj >> 1];
                    int s = nj & 1;
                    mma16816h(acc[mi][nj], aH[mi], f[s], f[s + 2]);
                }
        }
    }

    // epilogue: scale and STORE to per-assignment buffer (exclusive rows)
    const int rbase = m0 + warp_m + (lane >> 2);
    const int cbase = n0 + warp_n + (lane & 3) * 2;
    #pragma unroll
    for (int mi = 0; mi < 4; mi++) {
        int r0 = rbase + mi * 16;
        int r1 = r0 + 8;
        float sc0 = g_scale[r0];
        float sc1 = g_scale[r1];
        float* p0 = g_part + (size_t)r0 * H_DIM;
        float* p1 = g_part + (size_t)r1 * H_DIM;
        #pragma unroll
        for (int nj = 0; nj < 4; nj++) {
            int col = cbase + nj * 8;
            float2 v0 = make_float2(acc[mi][nj][0] * sc0, acc[mi][nj][1] * sc0);
            float2 v1 = make_float2(acc[mi][nj][2] * sc1, acc[mi][nj][3] * sc1);
            *(float2*)(p0 + col) = v0;
            *(float2*)(p1 + col) = v1;
        }
    }
}

// ---------------- kernel 6: combine the two expert contributions -------------
__global__ __launch_bounds__(256)
void k_combine(float* __restrict__ out)
{
    int t = blockIdx.x;
    int tid = threadIdx.x;
    int r0 = g_rowof[t * 2 + 0];
    int r1 = g_rowof[t * 2 + 1];
    float4 a = ((const float4*)(g_part + (size_t)r0 * H_DIM))[tid];
    float4 b = ((const float4*)(g_part + (size_t)r1 * H_DIM))[tid];
    float4 o;
    o.x = a.x + b.x;  o.y = a.y + b.y;
    o.z = a.z + b.z;  o.w = a.w + b.w;
    ((float4*)(out + (size_t)t * H_DIM))[tid] = o;
}

// ---------------- launch ----------------
extern "C" void kernel_launch(void* const* d_in, const int* in_sizes, int n_in,
                              void* d_out, int out_size)
{
    const float* hs  = (const float*)d_in[0];
    const float* lnw = (const float*)d_in[1];
    const float* rw  = (const float*)d_in[2];
    const float* wg  = (const float*)d_in[3];
    const float* wu  = (const float*)d_in[4];
    const float* wd  = (const float*)d_in[5];
    float* out = (float*)d_out;

    cudaFuncSetAttribute(k_gemm1_mma, cudaFuncAttributeMaxDynamicSharedMemorySize, SMEM_G);
    cudaFuncSetAttribute(k_gemm2_mma, cudaFuncAttributeMaxDynamicSharedMemorySize, SMEM_G);

    void *p_cnt = nullptr, *p_tok = nullptr;
    cudaGetSymbolAddress(&p_cnt, g_cnt);
    cudaGetSymbolAddress(&p_tok, g_tok);

    cudaMemsetAsync(p_cnt, 0, N_EXP * sizeof(int));
    cudaMemsetAsync(p_tok, 0xFF, MP_MAX * sizeof(int));

    // fork: weight prep on side stream, concurrent with activation chain
    cudaStream_t s2;
    cudaStreamCreateWithFlags(&s2, cudaStreamNonBlocking);
    cudaEvent_t eFork, eJoin;
    cudaEventCreateWithFlags(&eFork, cudaEventDisableTiming);
    cudaEventCreateWithFlags(&eJoin, cudaEventDisableTiming);

    cudaEventRecord(eFork, 0);
    cudaStreamWaitEvent(s2, eFork, 0);

    dim3 tb(32, 8);
    dim3 tg(F_DIM / 32, F_DIM / 64, 24);
    k_tsplit_all<<<tg, tb, 0, s2>>>(wg, wu, wd);     // launch 1 (side stream)
    cudaEventRecord(eJoin, s2);

    k_rms_router<<<T_TOK, 256>>>(hs, lnw, rw);        // launch 2 (main)
    k_offscatter<<<1, 256>>>();                       // launch 3 (main)

    cudaStreamWaitEvent(0, eJoin, 0);                 // join before GEMMs

    // launch 4 (ncu capture slot): GEMM1
    dim3 g1(F_DIM / 64, MP_MAX / 128);   // (44, 72)
    k_gemm1_mma<<<g1, 256, SMEM_G>>>();

    dim3 g2(H_DIM / 128, MP_MAX / 128);  // (8, 72)
    k_gemm2_mma<<<g2, 256, SMEM_G>>>();

    k_combine<<<T_TOK, 256>>>(out);
}